// round 1
// baseline (speedup 1.0000x reference)
#include <cuda_runtime.h>
#include <cuda_bf16.h>
#include <math.h>

// ---------------------------------------------------------------------------
// Problem constants
//   X   : [2, 4096, 1024] fp32
//   W_q : [1024, 1024], W_k/W_v : [256, 1024], W_o : [1024, 1024]
//   out : [2, 4096, 1024] fp32
// ---------------------------------------------------------------------------
#define BATCH 2
#define SEQ   4096
#define DMODEL 1024
#define NHEAD 4
#define DK    256
#define SCALE_F (1.0f / 16.0f)   // 1/sqrt(256)

#define MS (BATCH * SEQ)          // 8192 rows total

// ---------------------------------------------------------------------------
// Static device scratch (no allocation allowed in kernel_launch)
// ---------------------------------------------------------------------------
__device__ float g_q[(long long)MS * DMODEL];          // 32 MB  Q projection
__device__ float g_kc[(long long)MS * DK];             // 8 MB   compressed K
__device__ float g_vc[(long long)MS * DK];             // 8 MB   compressed V
__device__ float g_vct[(long long)BATCH * DK * SEQ];   // 8 MB   V^T per batch
__device__ float g_scores[(long long)BATCH * NHEAD * SEQ * SEQ]; // 512 MB
__device__ float g_merged[(long long)MS * DMODEL];     // 32 MB  head-merged ctx

// ---------------------------------------------------------------------------
// Generic NT SGEMM:  C[m,n] = alpha * sum_k A[m,k] * B[n,k]
// Row-major A (lda), row-major B (ldb, "transposed" operand), row-major C.
// Batched over blockIdx.z = b*H + h with independent (b,h) strides so the same
// kernel serves projections, QK^T (per-head strided Q) and PV (merged write).
// Requires: gridDim.y*128 rows, gridDim.x*128 cols, K % 16 == 0.
// ---------------------------------------------------------------------------
#define BM 128
#define BN 128
#define BK 16

__global__ void __launch_bounds__(256, 2)
sgemm_nt(const float* __restrict__ A, const float* __restrict__ B,
         float* __restrict__ C,
         int K, int lda, int ldb, int ldc, float alpha,
         long long aSB, long long aSH,
         long long bSB, long long bSH,
         long long cSB, long long cSH, int H)
{
    const int zb = blockIdx.z / H;
    const int zh = blockIdx.z - zb * H;
    A += zb * aSB + zh * aSH;
    B += zb * bSB + zh * bSH;
    C += zb * cSB + zh * cSH;

    __shared__ float As[2][BK][BM];
    __shared__ float Bs[2][BK][BN];

    const int tid = threadIdx.x;
    const int tx = tid & 15;   // 0..15 -> col group
    const int ty = tid >> 4;   // 0..15 -> row group

    const int rowBase = blockIdx.y * BM;
    const int colBase = blockIdx.x * BN;

    const float* Aptr = A + (long long)rowBase * lda;
    const float* Bptr = B + (long long)colBase * ldb;

    float acc[8][8];
#pragma unroll
    for (int i = 0; i < 8; i++)
#pragma unroll
        for (int j = 0; j < 8; j++) acc[i][j] = 0.0f;

    const int nTiles = K / BK;

    // prologue: tile 0 -> buffer 0
#pragma unroll
    for (int i = 0; i < 2; i++) {
        int idx = tid + i * 256;          // 0..511
        int r   = idx >> 2;               // 0..127
        int c4  = (idx & 3) << 2;         // 0,4,8,12
        float4 va = *reinterpret_cast<const float4*>(Aptr + (long long)r * lda + c4);
        As[0][c4 + 0][r] = va.x; As[0][c4 + 1][r] = va.y;
        As[0][c4 + 2][r] = va.z; As[0][c4 + 3][r] = va.w;
        float4 vb = *reinterpret_cast<const float4*>(Bptr + (long long)r * ldb + c4);
        Bs[0][c4 + 0][r] = vb.x; Bs[0][c4 + 1][r] = vb.y;
        Bs[0][c4 + 2][r] = vb.z; Bs[0][c4 + 3][r] = vb.w;
    }
    __syncthreads();

    for (int t = 0; t < nTiles; t++) {
        const int cur = t & 1;
        const int nxt = cur ^ 1;

        if (t + 1 < nTiles) {
            const int koff = (t + 1) * BK;
#pragma unroll
            for (int i = 0; i < 2; i++) {
                int idx = tid + i * 256;
                int r   = idx >> 2;
                int c4  = (idx & 3) << 2;
                float4 va = *reinterpret_cast<const float4*>(Aptr + (long long)r * lda + koff + c4);
                As[nxt][c4 + 0][r] = va.x; As[nxt][c4 + 1][r] = va.y;
                As[nxt][c4 + 2][r] = va.z; As[nxt][c4 + 3][r] = va.w;
                float4 vb = *reinterpret_cast<const float4*>(Bptr + (long long)r * ldb + koff + c4);
                Bs[nxt][c4 + 0][r] = vb.x; Bs[nxt][c4 + 1][r] = vb.y;
                Bs[nxt][c4 + 2][r] = vb.z; Bs[nxt][c4 + 3][r] = vb.w;
            }
        }

#pragma unroll
        for (int k = 0; k < BK; k++) {
            float4 a0 = *reinterpret_cast<const float4*>(&As[cur][k][ty * 8]);
            float4 a1 = *reinterpret_cast<const float4*>(&As[cur][k][ty * 8 + 4]);
            float4 b0 = *reinterpret_cast<const float4*>(&Bs[cur][k][tx * 8]);
            float4 b1 = *reinterpret_cast<const float4*>(&Bs[cur][k][tx * 8 + 4]);
            float a[8] = {a0.x, a0.y, a0.z, a0.w, a1.x, a1.y, a1.z, a1.w};
            float b[8] = {b0.x, b0.y, b0.z, b0.w, b1.x, b1.y, b1.z, b1.w};
#pragma unroll
            for (int i = 0; i < 8; i++)
#pragma unroll
                for (int j = 0; j < 8; j++)
                    acc[i][j] = fmaf(a[i], b[j], acc[i][j]);
        }
        __syncthreads();
    }

    float* Cptr = C + (long long)(rowBase + ty * 8) * ldc + colBase + tx * 8;
#pragma unroll
    for (int i = 0; i < 8; i++) {
        float4 o0 = make_float4(acc[i][0] * alpha, acc[i][1] * alpha,
                                acc[i][2] * alpha, acc[i][3] * alpha);
        float4 o1 = make_float4(acc[i][4] * alpha, acc[i][5] * alpha,
                                acc[i][6] * alpha, acc[i][7] * alpha);
        *reinterpret_cast<float4*>(Cptr + (long long)i * ldc)     = o0;
        *reinterpret_cast<float4*>(Cptr + (long long)i * ldc + 4) = o1;
    }
}

// ---------------------------------------------------------------------------
// Row softmax over rows of length 4096. One 256-thread block per row;
// 16 values live in registers (single read, single write).
// ---------------------------------------------------------------------------
__global__ void __launch_bounds__(256)
softmax_rows(float* __restrict__ S)
{
    float* row = S + (long long)blockIdx.x * SEQ;
    const int tid = threadIdx.x;

    float v[16];
    float m = -INFINITY;
#pragma unroll
    for (int i = 0; i < 16; i++) {
        v[i] = row[tid + i * 256];
        m = fmaxf(m, v[i]);
    }

    __shared__ float red[256];
    red[tid] = m;
    __syncthreads();
#pragma unroll
    for (int s = 128; s > 0; s >>= 1) {
        if (tid < s) red[tid] = fmaxf(red[tid], red[tid + s]);
        __syncthreads();
    }
    m = red[0];
    __syncthreads();

    float sum = 0.0f;
#pragma unroll
    for (int i = 0; i < 16; i++) {
        v[i] = __expf(v[i] - m);
        sum += v[i];
    }
    red[tid] = sum;
    __syncthreads();
#pragma unroll
    for (int s = 128; s > 0; s >>= 1) {
        if (tid < s) red[tid] += red[tid + s];
        __syncthreads();
    }
    const float inv = 1.0f / red[0];
#pragma unroll
    for (int i = 0; i < 16; i++)
        row[tid + i * 256] = v[i] * inv;
}

// ---------------------------------------------------------------------------
// Transpose Vc [b][4096][256] -> VcT [b][256][4096]
// ---------------------------------------------------------------------------
__global__ void transpose_vc(const float* __restrict__ Vc, float* __restrict__ VcT)
{
    __shared__ float tile[32][33];
    const int b = blockIdx.z;
    const int s0 = blockIdx.y * 32;
    const int d0 = blockIdx.x * 32;
    const float* src = Vc + (long long)b * SEQ * DK;
    float* dst = VcT + (long long)b * DK * SEQ;

    const int x = threadIdx.x;   // 0..31
    const int y = threadIdx.y;   // 0..7
#pragma unroll
    for (int i = 0; i < 32; i += 8)
        tile[y + i][x] = src[(long long)(s0 + y + i) * DK + d0 + x];
    __syncthreads();
#pragma unroll
    for (int i = 0; i < 32; i += 8)
        dst[(long long)(d0 + y + i) * SEQ + s0 + x] = tile[x][y + i];
}

// ---------------------------------------------------------------------------
// Launch
// ---------------------------------------------------------------------------
static float* sym_addr(const void* symbol)
{
    void* p = nullptr;
    cudaGetSymbolAddress(&p, symbol);
    return (float*)p;
}

extern "C" void kernel_launch(void* const* d_in, const int* in_sizes, int n_in,
                              void* d_out, int out_size)
{
    const float* X  = (const float*)d_in[0];
    const float* Wq = (const float*)d_in[1];
    const float* Wk = (const float*)d_in[2];
    const float* Wv = (const float*)d_in[3];
    const float* Wo = (const float*)d_in[4];
    float* out = (float*)d_out;

    float* q      = sym_addr(g_q);
    float* kc     = sym_addr(g_kc);
    float* vc     = sym_addr(g_vc);
    float* vct    = sym_addr(g_vct);
    float* scores = sym_addr(g_scores);
    float* merged = sym_addr(g_merged);

    // ---- projections -----------------------------------------------------
    // Q = X @ Wq^T : [8192,1024]
    sgemm_nt<<<dim3(DMODEL / BN, MS / BM, 1), 256>>>(
        X, Wq, q, DMODEL, DMODEL, DMODEL, DMODEL, 1.0f,
        0, 0, 0, 0, 0, 0, 1);
    // Kc = X @ Wk^T : [8192,256]
    sgemm_nt<<<dim3(DK / BN, MS / BM, 1), 256>>>(
        X, Wk, kc, DMODEL, DMODEL, DMODEL, DK, 1.0f,
        0, 0, 0, 0, 0, 0, 1);
    // Vc = X @ Wv^T : [8192,256]
    sgemm_nt<<<dim3(DK / BN, MS / BM, 1), 256>>>(
        X, Wv, vc, DMODEL, DMODEL, DMODEL, DK, 1.0f,
        0, 0, 0, 0, 0, 0, 1);

    // ---- Vc transpose ----------------------------------------------------
    transpose_vc<<<dim3(DK / 32, SEQ / 32, BATCH), dim3(32, 8)>>>(vc, vct);

    // ---- scores[b,h] = SCALE * Q[b,h] @ Kc[b]^T : [4096,4096] x8 ----------
    sgemm_nt<<<dim3(SEQ / BN, SEQ / BM, BATCH * NHEAD), 256>>>(
        q, kc, scores, DK, DMODEL, DK, SEQ, SCALE_F,
        (long long)SEQ * DMODEL, DK,                 // A: batch rows, head col offset
        (long long)SEQ * DK, 0,                      // B: Kc per batch, shared by heads
        (long long)NHEAD * SEQ * SEQ, (long long)SEQ * SEQ,  // C: per (b,h) score matrix
        NHEAD);

    // ---- softmax over rows -------------------------------------------------
    softmax_rows<<<BATCH * NHEAD * SEQ, 256>>>(scores);

    // ---- merged[b,s,h*256+d] = attn[b,h] @ Vc[b] : [4096,256] x8 -----------
    sgemm_nt<<<dim3(DK / BN, SEQ / BM, BATCH * NHEAD), 256>>>(
        scores, vct, merged, SEQ, SEQ, SEQ, DMODEL, 1.0f,
        (long long)NHEAD * SEQ * SEQ, (long long)SEQ * SEQ,  // A: attn per (b,h)
        (long long)DK * SEQ, 0,                              // B: VcT per batch
        (long long)SEQ * DMODEL, DK,                         // C: merged, head col offset
        NHEAD);

    // ---- Y = merged @ Wo^T : [8192,1024] -----------------------------------
    sgemm_nt<<<dim3(DMODEL / BN, MS / BM, 1), 256>>>(
        merged, Wo, out, DMODEL, DMODEL, DMODEL, DMODEL, 1.0f,
        0, 0, 0, 0, 0, 0, 1);
}

// round 3
// speedup vs baseline: 2.5207x; 2.5207x over previous
#include <cuda_runtime.h>
#include <cuda_bf16.h>
#include <cstdint>
#include <math.h>

// ---------------------------------------------------------------------------
// MLA: X[2,4096,1024], Wq[1024,1024], Wk/Wv[256,1024], Wo[1024,1024] -> out
// All GEMMs: bf16 mma.sync (m16n8k16) with hi/lo fp32-emulation split,
// 3 accumulating phases per K-chunk: Ah*Bh + Ah*Bl + Al*Bh.
// (tcgen05 is unavailable: harness compiles via generic compute_103 PTX.)
// ---------------------------------------------------------------------------
#define BATCH 2
#define SEQ   4096
#define DMODEL 1024
#define NHEAD 4
#define DK    256
#define MS (BATCH * SEQ)
#define SCALE_F (1.0f / 16.0f)

// GEMM tiling
#define BM 128
#define BN 128
#define BKE 64              // K elements (bf16) per chunk -> 128B rows
#define STAGES 3
#define TILE_B 16384        // 128 rows * 128 bytes
#define STAGE_B (4 * TILE_B)  // Ah, Al, Bh, Bl
#define GEMM_SMEM (STAGES * STAGE_B)

// ---------------------------------------------------------------------------
// Device scratch (allocation-free rule -> __device__ globals)
// ---------------------------------------------------------------------------
__device__ __align__(256) __nv_bfloat16 g_Xh[(size_t)MS * DMODEL];
__device__ __align__(256) __nv_bfloat16 g_Xl[(size_t)MS * DMODEL];
__device__ __align__(256) __nv_bfloat16 g_Wqh[(size_t)DMODEL * DMODEL];
__device__ __align__(256) __nv_bfloat16 g_Wql[(size_t)DMODEL * DMODEL];
__device__ __align__(256) __nv_bfloat16 g_Wkh[(size_t)DK * DMODEL];
__device__ __align__(256) __nv_bfloat16 g_Wkl[(size_t)DK * DMODEL];
__device__ __align__(256) __nv_bfloat16 g_Wvh[(size_t)DK * DMODEL];
__device__ __align__(256) __nv_bfloat16 g_Wvl[(size_t)DK * DMODEL];
__device__ __align__(256) __nv_bfloat16 g_Woh[(size_t)DMODEL * DMODEL];
__device__ __align__(256) __nv_bfloat16 g_Wol[(size_t)DMODEL * DMODEL];
__device__ __align__(256) __nv_bfloat16 g_Qh[(size_t)MS * DMODEL];
__device__ __align__(256) __nv_bfloat16 g_Ql[(size_t)MS * DMODEL];
__device__ __align__(256) __nv_bfloat16 g_Kh[(size_t)MS * DK];
__device__ __align__(256) __nv_bfloat16 g_Kl[(size_t)MS * DK];
__device__ __align__(256) __nv_bfloat16 g_Vth[(size_t)BATCH * DK * SEQ];
__device__ __align__(256) __nv_bfloat16 g_Vtl[(size_t)BATCH * DK * SEQ];
__device__ __align__(256) float         g_S[(size_t)BATCH * NHEAD * SEQ * SEQ];
__device__ __align__(256) __nv_bfloat16 g_Ph[(size_t)BATCH * NHEAD * SEQ * SEQ];
__device__ __align__(256) __nv_bfloat16 g_Pl[(size_t)BATCH * NHEAD * SEQ * SEQ];
__device__ __align__(256) __nv_bfloat16 g_Mh[(size_t)MS * DMODEL];
__device__ __align__(256) __nv_bfloat16 g_Ml[(size_t)MS * DMODEL];

// ---------------------------------------------------------------------------
// PTX helpers (generic-PTX-safe: cp.async / ldmatrix / mma.sync only)
// ---------------------------------------------------------------------------
__device__ __forceinline__ uint32_t smem_u32(const void* p) {
    uint32_t a;
    asm("{ .reg .u64 t; cvta.to.shared.u64 t, %1; cvt.u32.u64 %0, t; }"
        : "=r"(a) : "l"(p));
    return a;
}
__device__ __forceinline__ void cp16(uint32_t s, const void* g) {
    asm volatile("cp.async.cg.shared.global [%0], [%1], 16;" :: "r"(s), "l"(g));
}
#define CP_COMMIT() asm volatile("cp.async.commit_group;" ::: "memory")
#define CP_WAIT2()  asm volatile("cp.async.wait_group 2;" ::: "memory")

__device__ __forceinline__ void ldsm4(uint32_t* r, uint32_t addr) {
    asm volatile("ldmatrix.sync.aligned.m8n8.x4.shared.b16 {%0,%1,%2,%3}, [%4];"
                 : "=r"(r[0]), "=r"(r[1]), "=r"(r[2]), "=r"(r[3]) : "r"(addr));
}
__device__ __forceinline__ void mma16816(float* c, const uint32_t* a,
                                         uint32_t b0, uint32_t b1) {
    asm volatile(
        "mma.sync.aligned.m16n8k16.row.col.f32.bf16.bf16.f32 "
        "{%0,%1,%2,%3}, {%4,%5,%6,%7}, {%8,%9}, {%0,%1,%2,%3};\n"
        : "+f"(c[0]), "+f"(c[1]), "+f"(c[2]), "+f"(c[3])
        : "r"(a[0]), "r"(a[1]), "r"(a[2]), "r"(a[3]), "r"(b0), "r"(b1));
}

// Fragment address inside a 128x(64 bf16) SW128-swizzled tile.
// rowBase: 16-row block start; ks: k16 step (0..3); lane layout matches
// ldmatrix.x4 producing a0..a3 / b0-pairs in canonical order.
__device__ __forceinline__ uint32_t frag_addr(uint32_t tbase, int rowBase,
                                              int ks, int lane) {
    int row = rowBase + (lane & 15);
    int chunk = ks * 2 + (lane >> 4);
    int sw = chunk ^ (row & 7);
    return tbase + row * 128 + sw * 16;
}

// ---------------------------------------------------------------------------
// Generic NT GEMM: C = alpha * (A*B^T), A = Ah+Al, B = Bh+Bl (bf16 splits).
// Tile 128x128, K % 64 == 0. mode 0: fp32 out. mode 1: hi/lo bf16 split out.
// Batched over blockIdx.z = b*H + h with independent strides.
// ---------------------------------------------------------------------------
__global__ void __launch_bounds__(256, 1)
gemm_bf16x3(const __nv_bfloat16* __restrict__ Ah, const __nv_bfloat16* __restrict__ Al,
            const __nv_bfloat16* __restrict__ Bh, const __nv_bfloat16* __restrict__ Bl,
            float* __restrict__ Cf, __nv_bfloat16* __restrict__ Ch,
            __nv_bfloat16* __restrict__ Cl,
            int K, int lda, int ldb, int ldc, float alpha, int mode,
            long long aSB, long long aSH, long long bSB, long long bSH,
            long long cSB, long long cSH, int H)
{
    extern __shared__ char smem[];
    const uint32_t sbase = smem_u32(smem);
    const int tid = threadIdx.x;
    const int wid = tid >> 5;
    const int lid = tid & 31;

    const int zb = blockIdx.z / H;
    const int zh = blockIdx.z - zb * H;
    const int rowBase = blockIdx.y * BM;
    const int colBase = blockIdx.x * BN;

    const __nv_bfloat16* Ah_ = Ah + zb * aSB + zh * aSH + (long long)rowBase * lda;
    const __nv_bfloat16* Al_ = Al + zb * aSB + zh * aSH + (long long)rowBase * lda;
    const __nv_bfloat16* Bh_ = Bh + zb * bSB + zh * bSH + (long long)colBase * ldb;
    const __nv_bfloat16* Bl_ = Bl + zb * bSB + zh * bSH + (long long)colBase * ldb;
    const long long cOff = zb * cSB + zh * cSH;

    const int warpM = (wid >> 2) * 64;   // 2 warp rows
    const int warpN = (wid & 3) * 32;    // 4 warp cols

    float acc[4][4][4];
#pragma unroll
    for (int i = 0; i < 4; i++)
#pragma unroll
        for (int j = 0; j < 4; j++)
#pragma unroll
            for (int v = 0; v < 4; v++) acc[i][j][v] = 0.0f;

    const int nK = K >> 6;

    // ---- stage loader: Ah, Al, Bh, Bl tiles (each 128 rows x 128B, SW128) --
    auto load_stage = [&](int t, int buf) {
        const int k0 = t << 6;
        const uint32_t sS = sbase + buf * STAGE_B;
        const __nv_bfloat16* src[4] = {Ah_, Al_, Bh_, Bl_};
        const int lds[4] = {lda, lda, ldb, ldb};
#pragma unroll
        for (int tl = 0; tl < 4; tl++) {
            const __nv_bfloat16* P = src[tl];
            const int ld = lds[tl];
            const uint32_t tb = sS + tl * TILE_B;
#pragma unroll
            for (int j = 0; j < 4; j++) {
                int idx = tid + j * 256;          // 0..1023
                int row = idx >> 3;
                int c = idx & 7;
                int sw = c ^ (row & 7);
                cp16(tb + row * 128 + sw * 16,
                     P + (long long)row * ld + k0 + c * 8);
            }
        }
    };

    // ---- prologue ----------------------------------------------------------
#pragma unroll
    for (int s = 0; s < STAGES; s++) {
        if (s < nK) load_stage(s, s);
        CP_COMMIT();
    }

    // ---- main loop ----------------------------------------------------------
    for (int t = 0; t < nK; t++) {
        const int buf = t % STAGES;
        CP_WAIT2();
        __syncthreads();

        const uint32_t sS = sbase + buf * STAGE_B;
        const uint32_t sAh = sS;
        const uint32_t sAl = sS + TILE_B;
        const uint32_t sBh = sS + 2 * TILE_B;
        const uint32_t sBl = sS + 3 * TILE_B;

#pragma unroll
        for (int ks = 0; ks < 4; ks++) {
            uint32_t ah[4][4], al[4][4], bh[2][4], bl[2][4];
#pragma unroll
            for (int i = 0; i < 4; i++)
                ldsm4(ah[i], frag_addr(sAh, warpM + i * 16, ks, lid));
#pragma unroll
            for (int j = 0; j < 2; j++)
                ldsm4(bh[j], frag_addr(sBh, warpN + j * 16, ks, lid));
#pragma unroll
            for (int j = 0; j < 2; j++)
                ldsm4(bl[j], frag_addr(sBl, warpN + j * 16, ks, lid));
#pragma unroll
            for (int i = 0; i < 4; i++)
                ldsm4(al[i], frag_addr(sAl, warpM + i * 16, ks, lid));

#pragma unroll
            for (int i = 0; i < 4; i++) {
#pragma unroll
                for (int j = 0; j < 4; j++) {
                    uint32_t bh0 = bh[j >> 1][j & 1], bh1 = bh[j >> 1][(j & 1) + 2];
                    uint32_t bl0 = bl[j >> 1][j & 1], bl1 = bl[j >> 1][(j & 1) + 2];
                    mma16816(acc[i][j], ah[i], bh0, bh1);   // hi*hi
                    mma16816(acc[i][j], ah[i], bl0, bl1);   // hi*lo
                    mma16816(acc[i][j], al[i], bh0, bh1);   // lo*hi
                }
            }
        }
        __syncthreads();

        const int nt = t + STAGES;
        if (nt < nK) load_stage(nt, buf);
        CP_COMMIT();
    }

    // ---- epilogue -----------------------------------------------------------
    const int g = lid >> 2;
    const int tq = lid & 3;
#pragma unroll
    for (int i = 0; i < 4; i++) {
        const long long r0 = rowBase + warpM + i * 16 + g;
        const long long r1 = r0 + 8;
#pragma unroll
        for (int j = 0; j < 4; j++) {
            const int col = colBase + warpN + j * 8 + tq * 2;
            if (mode == 0) {
                float2 v01 = make_float2(acc[i][j][0] * alpha, acc[i][j][1] * alpha);
                float2 v23 = make_float2(acc[i][j][2] * alpha, acc[i][j][3] * alpha);
                *reinterpret_cast<float2*>(Cf + cOff + r0 * ldc + col) = v01;
                *reinterpret_cast<float2*>(Cf + cOff + r1 * ldc + col) = v23;
            } else {
                float x0 = acc[i][j][0], x1 = acc[i][j][1];
                float x2 = acc[i][j][2], x3 = acc[i][j][3];
                __nv_bfloat16 h0 = __float2bfloat16(x0);
                __nv_bfloat16 h1 = __float2bfloat16(x1);
                __nv_bfloat16 h2 = __float2bfloat16(x2);
                __nv_bfloat16 h3 = __float2bfloat16(x3);
                __nv_bfloat162 hh01; hh01.x = h0; hh01.y = h1;
                __nv_bfloat162 hh23; hh23.x = h2; hh23.y = h3;
                __nv_bfloat162 ll01, ll23;
                ll01.x = __float2bfloat16(x0 - __bfloat162float(h0));
                ll01.y = __float2bfloat16(x1 - __bfloat162float(h1));
                ll23.x = __float2bfloat16(x2 - __bfloat162float(h2));
                ll23.y = __float2bfloat16(x3 - __bfloat162float(h3));
                *reinterpret_cast<__nv_bfloat162*>(Ch + cOff + r0 * ldc + col) = hh01;
                *reinterpret_cast<__nv_bfloat162*>(Ch + cOff + r1 * ldc + col) = hh23;
                *reinterpret_cast<__nv_bfloat162*>(Cl + cOff + r0 * ldc + col) = ll01;
                *reinterpret_cast<__nv_bfloat162*>(Cl + cOff + r1 * ldc + col) = ll23;
            }
        }
    }
}

// ---------------------------------------------------------------------------
// fp32 -> (hi, lo) bf16 split (elementwise, float4 vectorized)
// ---------------------------------------------------------------------------
__global__ void __launch_bounds__(256)
split_f32(const float* __restrict__ x, __nv_bfloat16* __restrict__ h,
          __nv_bfloat16* __restrict__ l, long long n4)
{
    long long i = (long long)blockIdx.x * blockDim.x + threadIdx.x;
    if (i >= n4) return;
    float4 v = reinterpret_cast<const float4*>(x)[i];
    __nv_bfloat16 h0 = __float2bfloat16(v.x), h1 = __float2bfloat16(v.y);
    __nv_bfloat16 h2 = __float2bfloat16(v.z), h3 = __float2bfloat16(v.w);
    __nv_bfloat162 a, b;
    a.x = h0; a.y = h1; b.x = h2; b.y = h3;
    reinterpret_cast<__nv_bfloat162*>(h)[2 * i] = a;
    reinterpret_cast<__nv_bfloat162*>(h)[2 * i + 1] = b;
    a.x = __float2bfloat16(v.x - __bfloat162float(h0));
    a.y = __float2bfloat16(v.y - __bfloat162float(h1));
    b.x = __float2bfloat16(v.z - __bfloat162float(h2));
    b.y = __float2bfloat16(v.w - __bfloat162float(h3));
    reinterpret_cast<__nv_bfloat162*>(l)[2 * i] = a;
    reinterpret_cast<__nv_bfloat162*>(l)[2 * i + 1] = b;
}

// ---------------------------------------------------------------------------
// Row softmax (len 4096) fused with hi/lo bf16 split of the probabilities.
// ---------------------------------------------------------------------------
__global__ void __launch_bounds__(256)
softmax_split(const float* __restrict__ S, __nv_bfloat16* __restrict__ Ph,
              __nv_bfloat16* __restrict__ Pl)
{
    const float* row = S + (long long)blockIdx.x * SEQ;
    __nv_bfloat16* ph = Ph + (long long)blockIdx.x * SEQ;
    __nv_bfloat16* pl = Pl + (long long)blockIdx.x * SEQ;
    const int tid = threadIdx.x;

    float v[16];
    float m = -INFINITY;
#pragma unroll
    for (int i = 0; i < 16; i++) {
        v[i] = row[tid + i * 256];
        m = fmaxf(m, v[i]);
    }
    __shared__ float red[256];
    red[tid] = m;
    __syncthreads();
#pragma unroll
    for (int s = 128; s > 0; s >>= 1) {
        if (tid < s) red[tid] = fmaxf(red[tid], red[tid + s]);
        __syncthreads();
    }
    m = red[0];
    __syncthreads();
    float sum = 0.0f;
#pragma unroll
    for (int i = 0; i < 16; i++) {
        v[i] = __expf(v[i] - m);
        sum += v[i];
    }
    red[tid] = sum;
    __syncthreads();
#pragma unroll
    for (int s = 128; s > 0; s >>= 1) {
        if (tid < s) red[tid] += red[tid + s];
        __syncthreads();
    }
    const float inv = 1.0f / red[0];
#pragma unroll
    for (int i = 0; i < 16; i++) {
        float p = v[i] * inv;
        __nv_bfloat16 h = __float2bfloat16(p);
        ph[tid + i * 256] = h;
        pl[tid + i * 256] = __float2bfloat16(p - __bfloat162float(h));
    }
}

// ---------------------------------------------------------------------------
// Launch
// ---------------------------------------------------------------------------
static void* sym_addr(const void* symbol)
{
    void* p = nullptr;
    cudaGetSymbolAddress(&p, symbol);
    return p;
}

extern "C" void kernel_launch(void* const* d_in, const int* in_sizes, int n_in,
                              void* d_out, int out_size)
{
    const float* X  = (const float*)d_in[0];
    const float* Wq = (const float*)d_in[1];
    const float* Wk = (const float*)d_in[2];
    const float* Wv = (const float*)d_in[3];
    const float* Wo = (const float*)d_in[4];
    float* out = (float*)d_out;

    __nv_bfloat16* Xh  = (__nv_bfloat16*)sym_addr(g_Xh);
    __nv_bfloat16* Xl  = (__nv_bfloat16*)sym_addr(g_Xl);
    __nv_bfloat16* Wqh = (__nv_bfloat16*)sym_addr(g_Wqh);
    __nv_bfloat16* Wql = (__nv_bfloat16*)sym_addr(g_Wql);
    __nv_bfloat16* Wkh = (__nv_bfloat16*)sym_addr(g_Wkh);
    __nv_bfloat16* Wkl = (__nv_bfloat16*)sym_addr(g_Wkl);
    __nv_bfloat16* Wvh = (__nv_bfloat16*)sym_addr(g_Wvh);
    __nv_bfloat16* Wvl = (__nv_bfloat16*)sym_addr(g_Wvl);
    __nv_bfloat16* Woh = (__nv_bfloat16*)sym_addr(g_Woh);
    __nv_bfloat16* Wol = (__nv_bfloat16*)sym_addr(g_Wol);
    __nv_bfloat16* Qh  = (__nv_bfloat16*)sym_addr(g_Qh);
    __nv_bfloat16* Ql  = (__nv_bfloat16*)sym_addr(g_Ql);
    __nv_bfloat16* Kh  = (__nv_bfloat16*)sym_addr(g_Kh);
    __nv_bfloat16* Kl  = (__nv_bfloat16*)sym_addr(g_Kl);
    __nv_bfloat16* Vth = (__nv_bfloat16*)sym_addr(g_Vth);
    __nv_bfloat16* Vtl = (__nv_bfloat16*)sym_addr(g_Vtl);
    float*         S   = (float*)sym_addr(g_S);
    __nv_bfloat16* Ph  = (__nv_bfloat16*)sym_addr(g_Ph);
    __nv_bfloat16* Pl  = (__nv_bfloat16*)sym_addr(g_Pl);
    __nv_bfloat16* Mh  = (__nv_bfloat16*)sym_addr(g_Mh);
    __nv_bfloat16* Ml  = (__nv_bfloat16*)sym_addr(g_Ml);

    cudaFuncSetAttribute(gemm_bf16x3, cudaFuncAttributeMaxDynamicSharedMemorySize,
                         GEMM_SMEM);

    // ---- input splits ------------------------------------------------------
    {
        long long n4;
        n4 = (long long)MS * DMODEL / 4;
        split_f32<<<(unsigned)((n4 + 255) / 256), 256>>>(X, Xh, Xl, n4);
        n4 = (long long)DMODEL * DMODEL / 4;
        split_f32<<<(unsigned)((n4 + 255) / 256), 256>>>(Wq, Wqh, Wql, n4);
        split_f32<<<(unsigned)((n4 + 255) / 256), 256>>>(Wo, Woh, Wol, n4);
        n4 = (long long)DK * DMODEL / 4;
        split_f32<<<(unsigned)((n4 + 255) / 256), 256>>>(Wk, Wkh, Wkl, n4);
        split_f32<<<(unsigned)((n4 + 255) / 256), 256>>>(Wv, Wvh, Wvl, n4);
    }

    // ---- Q = X @ Wq^T -> split [8192 x 1024] --------------------------------
    gemm_bf16x3<<<dim3(DMODEL / BN, MS / BM, 1), 256, GEMM_SMEM>>>(
        Xh, Xl, Wqh, Wql, nullptr, Qh, Ql,
        DMODEL, DMODEL, DMODEL, DMODEL, 1.0f, 1,
        0, 0, 0, 0, 0, 0, 1);

    // ---- Kc = X @ Wk^T -> split [8192 x 256] --------------------------------
    gemm_bf16x3<<<dim3(DK / BN, MS / BM, 1), 256, GEMM_SMEM>>>(
        Xh, Xl, Wkh, Wkl, nullptr, Kh, Kl,
        DMODEL, DMODEL, DMODEL, DK, 1.0f, 1,
        0, 0, 0, 0, 0, 0, 1);

    // ---- VcT[b] = Wv @ X[b]^T -> split [256 x 4096] per batch ---------------
    gemm_bf16x3<<<dim3(SEQ / BN, DK / BM, BATCH), 256, GEMM_SMEM>>>(
        Wvh, Wvl, Xh, Xl, nullptr, Vth, Vtl,
        DMODEL, DMODEL, DMODEL, SEQ, 1.0f, 1,
        0, 0, (long long)SEQ * DMODEL, 0, (long long)DK * SEQ, 0, 1);

    // ---- S[b,h] = SCALE * Q[b,h] @ Kc[b]^T -> fp32 [4096 x 4096] x8 ---------
    gemm_bf16x3<<<dim3(SEQ / BN, SEQ / BM, BATCH * NHEAD), 256, GEMM_SMEM>>>(
        Qh, Ql, Kh, Kl, S, nullptr, nullptr,
        DK, DMODEL, DK, SEQ, SCALE_F, 0,
        (long long)SEQ * DMODEL, DK,
        (long long)SEQ * DK, 0,
        (long long)NHEAD * SEQ * SEQ, (long long)SEQ * SEQ, NHEAD);

    // ---- softmax + split -----------------------------------------------------
    softmax_split<<<BATCH * NHEAD * SEQ, 256>>>(S, Ph, Pl);

    // ---- merged[b,s,h*256+d] = P[b,h] @ VcT[b]^T -> split --------------------
    gemm_bf16x3<<<dim3(DK / BN, SEQ / BM, BATCH * NHEAD), 256, GEMM_SMEM>>>(
        Ph, Pl, Vth, Vtl, nullptr, Mh, Ml,
        SEQ, SEQ, SEQ, DMODEL, 1.0f, 1,
        (long long)NHEAD * SEQ * SEQ, (long long)SEQ * SEQ,
        (long long)DK * SEQ, 0,
        (long long)SEQ * DMODEL, DK, NHEAD);

    // ---- out = merged @ Wo^T -> fp32 [8192 x 1024] ---------------------------
    gemm_bf16x3<<<dim3(DMODEL / BN, MS / BM, 1), 256, GEMM_SMEM>>>(
        Mh, Ml, Woh, Wol, out, nullptr, nullptr,
        DMODEL, DMODEL, DMODEL, DMODEL, 1.0f, 0,
        0, 0, 0, 0, 0, 0, 1);
}

// round 4
// speedup vs baseline: 2.8983x; 1.1498x over previous
#include <cuda_runtime.h>
#include <cuda_bf16.h>
#include <cuda_fp16.h>
#include <cstdint>
#include <math.h>

#define BATCH 2
#define SEQ   4096
#define DMODEL 1024
#define NHEAD 4
#define DK    256
#define MS (BATCH * SEQ)
#define SCALE_F (1.0f / 16.0f)

#define BM 128
#define BN 128
#define STAGES 3
#define TILE_B 16384
#define STAGE4_B (4 * TILE_B)
#define GEMM_SMEM (STAGES * STAGE4_B)
#define STAGE3_B (3 * TILE_B)
#define PV_SMEM (STAGES * STAGE3_B)

__device__ __align__(256) __nv_bfloat16 g_Xh[(size_t)MS * DMODEL];
__device__ __align__(256) __nv_bfloat16 g_Xl[(size_t)MS * DMODEL];
__device__ __align__(256) __nv_bfloat16 g_Wqh[(size_t)DMODEL * DMODEL];
__device__ __align__(256) __nv_bfloat16 g_Wql[(size_t)DMODEL * DMODEL];
__device__ __align__(256) __nv_bfloat16 g_Wkh[(size_t)DK * DMODEL];
__device__ __align__(256) __nv_bfloat16 g_Wkl[(size_t)DK * DMODEL];
__device__ __align__(256) __nv_bfloat16 g_Wvh[(size_t)DK * DMODEL];
__device__ __align__(256) __nv_bfloat16 g_Wvl[(size_t)DK * DMODEL];
__device__ __align__(256) __nv_bfloat16 g_Woh[(size_t)DMODEL * DMODEL];
__device__ __align__(256) __nv_bfloat16 g_Wol[(size_t)DMODEL * DMODEL];
__device__ __align__(256) __nv_bfloat16 g_Qh[(size_t)MS * DMODEL];
__device__ __align__(256) __nv_bfloat16 g_Ql[(size_t)MS * DMODEL];
__device__ __align__(256) __nv_bfloat16 g_Kh[(size_t)MS * DK];
__device__ __align__(256) __nv_bfloat16 g_Kl[(size_t)MS * DK];
__device__ __align__(256) __half        g_Vth[(size_t)BATCH * DK * SEQ];
__device__ __align__(256) __half        g_Vtl[(size_t)BATCH * DK * SEQ];
__device__ __align__(256) float         g_S[(size_t)BATCH * NHEAD * SEQ * SEQ];
__device__ __align__(256) __half        g_P[(size_t)BATCH * NHEAD * SEQ * SEQ];
__device__ __align__(256) __nv_bfloat16 g_Mh[(size_t)MS * DMODEL];
__device__ __align__(256) __nv_bfloat16 g_Ml[(size_t)MS * DMODEL];

__device__ __forceinline__ uint32_t smem_u32(const void* p) {
    uint32_t a;
    asm("{ .reg .u64 t; cvta.to.shared.u64 t, %1; cvt.u32.u64 %0, t; }"
        : "=r"(a) : "l"(p));
    return a;
}
__device__ __forceinline__ void cp16(uint32_t s, const void* g) {
    asm volatile("cp.async.cg.shared.global [%0], [%1], 16;" :: "r"(s), "l"(g));
}
#define CP_COMMIT() asm volatile("cp.async.commit_group;" ::: "memory")
#define CP_WAIT2()  asm volatile("cp.async.wait_group 2;" ::: "memory")

__device__ __forceinline__ void ldsm4(uint32_t* r, uint32_t addr) {
    asm volatile("ldmatrix.sync.aligned.m8n8.x4.shared.b16 {%0,%1,%2,%3}, [%4];"
                 : "=r"(r[0]), "=r"(r[1]), "=r"(r[2]), "=r"(r[3]) : "r"(addr));
}
__device__ __forceinline__ void mma_bf16(float* c, const uint32_t* a,
                                         uint32_t b0, uint32_t b1) {
    asm volatile(
        "mma.sync.aligned.m16n8k16.row.col.f32.bf16.bf16.f32 "
        "{%0,%1,%2,%3}, {%4,%5,%6,%7}, {%8,%9}, {%0,%1,%2,%3};\n"
        : "+f"(c[0]), "+f"(c[1]), "+f"(c[2]), "+f"(c[3])
        : "r"(a[0]), "r"(a[1]), "r"(a[2]), "r"(a[3]), "r"(b0), "r"(b1));
}
__device__ __forceinline__ void mma_f16(float* c, const uint32_t* a,
                                        uint32_t b0, uint32_t b1) {
    asm volatile(
        "mma.sync.aligned.m16n8k16.row.col.f32.f16.f16.f32 "
        "{%0,%1,%2,%3}, {%4,%5,%6,%7}, {%8,%9}, {%0,%1,%2,%3};\n"
        : "+f"(c[0]), "+f"(c[1]), "+f"(c[2]), "+f"(c[3])
        : "r"(a[0]), "r"(a[1]), "r"(a[2]), "r"(a[3]), "r"(b0), "r"(b1));
}
__device__ __forceinline__ uint32_t frag_addr(uint32_t tbase, int rowBase,
                                              int ks, int lane) {
    int row = rowBase + (lane & 15);
    int chunk = ks * 2 + (lane >> 4);
    int sw = chunk ^ (row & 7);
    return tbase + row * 128 + sw * 16;
}

__global__ void __launch_bounds__(256, 1)
gemm_bf16x3(const __nv_bfloat16* __restrict__ Ah, const __nv_bfloat16* __restrict__ Al,
            const __nv_bfloat16* __restrict__ Bh, const __nv_bfloat16* __restrict__ Bl,
            float* __restrict__ Cf, __nv_bfloat16* __restrict__ Ch,
            __nv_bfloat16* __restrict__ Cl,
            __half* __restrict__ Hh, __half* __restrict__ Hl,
            int K, int lda, int ldb, int ldc, float alpha, int mode,
            long long aSB, long long aSH, long long bSB, long long bSH,
            long long cSB, long long cSH, int H)
{
    extern __shared__ char smem[];
    const uint32_t sbase = smem_u32(smem);
    const int tid = threadIdx.x;
    const int wid = tid >> 5;
    const int lid = tid & 31;

    const int zb = blockIdx.z / H;
    const int zh = blockIdx.z - zb * H;
    const int rowBase = blockIdx.y * BM;
    const int colBase = blockIdx.x * BN;

    const __nv_bfloat16* Ah_ = Ah + zb * aSB + zh * aSH + (long long)rowBase * lda;
    const __nv_bfloat16* Al_ = Al + zb * aSB + zh * aSH + (long long)rowBase * lda;
    const __nv_bfloat16* Bh_ = Bh + zb * bSB + zh * bSH + (long long)colBase * ldb;
    const __nv_bfloat16* Bl_ = Bl + zb * bSB + zh * bSH + (long long)colBase * ldb;
    const long long cOff = zb * cSB + zh * cSH;

    const int warpM = (wid >> 2) * 64;
    const int warpN = (wid & 3) * 32;

    float acc[4][4][4];
#pragma unroll
    for (int i = 0; i < 4; i++)
#pragma unroll
        for (int j = 0; j < 4; j++)
#pragma unroll
            for (int v = 0; v < 4; v++) acc[i][j][v] = 0.0f;

    const int nK = K >> 6;

    auto load_stage = [&](int t, int buf) {
        const int k0 = t << 6;
        const uint32_t sS = sbase + buf * STAGE4_B;
        const __nv_bfloat16* src[4] = {Ah_, Al_, Bh_, Bl_};
        const int lds[4] = {lda, lda, ldb, ldb};
#pragma unroll
        for (int tl = 0; tl < 4; tl++) {
            const __nv_bfloat16* P = src[tl];
            const int ld = lds[tl];
            const uint32_t tb = sS + tl * TILE_B;
#pragma unroll
            for (int j = 0; j < 4; j++) {
                int idx = tid + j * 256;
                int row = idx >> 3;
                int c = idx & 7;
                int sw = c ^ (row & 7);
                cp16(tb + row * 128 + sw * 16,
                     P + (long long)row * ld + k0 + c * 8);
            }
        }
    };

#pragma unroll
    for (int s = 0; s < STAGES; s++) {
        if (s < nK) load_stage(s, s);
        CP_COMMIT();
    }

    for (int t = 0; t < nK; t++) {
        const int buf = t % STAGES;
        CP_WAIT2();
        __syncthreads();

        const uint32_t sS = sbase + buf * STAGE4_B;
        const uint32_t sAh = sS;
        const uint32_t sAl = sS + TILE_B;
        const uint32_t sBh = sS + 2 * TILE_B;
        const uint32_t sBl = sS + 3 * TILE_B;

#pragma unroll
        for (int ks = 0; ks < 4; ks++) {
            uint32_t ah[4][4], al[4][4], bh[2][4], bl[2][4];
#pragma unroll
            for (int i = 0; i < 4; i++)
                ldsm4(ah[i], frag_addr(sAh, warpM + i * 16, ks, lid));
#pragma unroll
            for (int j = 0; j < 2; j++)
                ldsm4(bh[j], frag_addr(sBh, warpN + j * 16, ks, lid));
#pragma unroll
            for (int j = 0; j < 2; j++)
                ldsm4(bl[j], frag_addr(sBl, warpN + j * 16, ks, lid));
#pragma unroll
            for (int i = 0; i < 4; i++)
                ldsm4(al[i], frag_addr(sAl, warpM + i * 16, ks, lid));

#pragma unroll
            for (int i = 0; i < 4; i++) {
#pragma unroll
                for (int j = 0; j < 4; j++) {
                    uint32_t bh0 = bh[j >> 1][j & 1], bh1 = bh[j >> 1][(j & 1) + 2];
                    uint32_t bl0 = bl[j >> 1][j & 1], bl1 = bl[j >> 1][(j & 1) + 2];
                    mma_bf16(acc[i][j], ah[i], bh0, bh1);
                    mma_bf16(acc[i][j], ah[i], bl0, bl1);
                    mma_bf16(acc[i][j], al[i], bh0, bh1);
                }
            }
        }
        __syncthreads();

        const int nt = t + STAGES;
        if (nt < nK) load_stage(nt, buf);
        CP_COMMIT();
    }

    const int g = lid >> 2;
    const int tq = lid & 3;
#pragma unroll
    for (int i = 0; i < 4; i++) {
        const long long r0 = rowBase + warpM + i * 16 + g;
        const long long r1 = r0 + 8;
#pragma unroll
        for (int j = 0; j < 4; j++) {
            const int col = colBase + warpN + j * 8 + tq * 2;
            float x0 = acc[i][j][0], x1 = acc[i][j][1];
            float x2 = acc[i][j][2], x3 = acc[i][j][3];
            if (mode == 0) {
                *reinterpret_cast<float2*>(Cf + cOff + r0 * ldc + col) =
                    make_float2(x0 * alpha, x1 * alpha);
                *reinterpret_cast<float2*>(Cf + cOff + r1 * ldc + col) =
                    make_float2(x2 * alpha, x3 * alpha);
            } else if (mode == 1) {
                __nv_bfloat16 h0 = __float2bfloat16(x0);
                __nv_bfloat16 h1 = __float2bfloat16(x1);
                __nv_bfloat16 h2 = __float2bfloat16(x2);
                __nv_bfloat16 h3 = __float2bfloat16(x3);
                __nv_bfloat162 hh01; hh01.x = h0; hh01.y = h1;
                __nv_bfloat162 hh23; hh23.x = h2; hh23.y = h3;
                __nv_bfloat162 ll01, ll23;
                ll01.x = __float2bfloat16(x0 - __bfloat162float(h0));
                ll01.y = __float2bfloat16(x1 - __bfloat162float(h1));
                ll23.x = __float2bfloat16(x2 - __bfloat162float(h2));
                ll23.y = __float2bfloat16(x3 - __bfloat162float(h3));
                *reinterpret_cast<__nv_bfloat162*>(Ch + cOff + r0 * ldc + col) = hh01;
                *reinterpret_cast<__nv_bfloat162*>(Ch + cOff + r1 * ldc + col) = hh23;
                *reinterpret_cast<__nv_bfloat162*>(Cl + cOff + r0 * ldc + col) = ll01;
                *reinterpret_cast<__nv_bfloat162*>(Cl + cOff + r1 * ldc + col) = ll23;
            } else {
                __half h0 = __float2half(x0);
                __half h1 = __float2half(x1);
                __half h2 = __float2half(x2);
                __half h3 = __float2half(x3);
                __half2 hh01; hh01.x = h0; hh01.y = h1;
                __half2 hh23; hh23.x = h2; hh23.y = h3;
                __half2 ll01, ll23;
                ll01.x = __float2half(x0 - __half2float(h0));
                ll01.y = __float2half(x1 - __half2float(h1));
                ll23.x = __float2half(x2 - __half2float(h2));
                ll23.y = __float2half(x3 - __half2float(h3));
                *reinterpret_cast<__half2*>(Hh + cOff + r0 * ldc + col) = hh01;
                *reinterpret_cast<__half2*>(Hh + cOff + r1 * ldc + col) = hh23;
                *reinterpret_cast<__half2*>(Hl + cOff + r0 * ldc + col) = ll01;
                *reinterpret_cast<__half2*>(Hl + cOff + r1 * ldc + col) = ll23;
            }
        }
    }
}

__global__ void __launch_bounds__(256, 1)
gemm_pv(const __half* __restrict__ P, const __half* __restrict__ Bh,
        const __half* __restrict__ Bl,
        __nv_bfloat16* __restrict__ Ch, __nv_bfloat16* __restrict__ Cl,
        int K, int lda, int ldb, int ldc,
        long long aSB, long long aSH, long long bSB, long long bSH,
        long long cSB, long long cSH, int H)
{
    extern __shared__ char smem[];
    const uint32_t sbase = smem_u32(smem);
    const int tid = threadIdx.x;
    const int wid = tid >> 5;
    const int lid = tid & 31;

    const int zb = blockIdx.z / H;
    const int zh = blockIdx.z - zb * H;
    const int rowBase = blockIdx.y * BM;
    const int colBase = blockIdx.x * BN;

    const __half* A_ = P + zb * aSB + zh * aSH + (long long)rowBase * lda;
    const __half* Bh_ = Bh + zb * bSB + zh * bSH + (long long)colBase * ldb;
    const __half* Bl_ = Bl + zb * bSB + zh * bSH + (long long)colBase * ldb;
    const long long cOff = zb * cSB + zh * cSH;

    const int warpM = (wid >> 2) * 64;
    const int warpN = (wid & 3) * 32;

    float acc[4][4][4];
#pragma unroll
    for (int i = 0; i < 4; i++)
#pragma unroll
        for (int j = 0; j < 4; j++)
#pragma unroll
            for (int v = 0; v < 4; v++) acc[i][j][v] = 0.0f;

    const int nK = K >> 6;

    auto load_stage = [&](int t, int buf) {
        const int k0 = t << 6;
        const uint32_t sS = sbase + buf * STAGE3_B;
        const __half* src[3] = {A_, Bh_, Bl_};
        const int lds[3] = {lda, ldb, ldb};
#pragma unroll
        for (int tl = 0; tl < 3; tl++) {
            const __half* Q = src[tl];
            const int ld = lds[tl];
            const uint32_t tb = sS + tl * TILE_B;
#pragma unroll
            for (int j = 0; j < 4; j++) {
                int idx = tid + j * 256;
                int row = idx >> 3;
                int c = idx & 7;
                int sw = c ^ (row & 7);
                cp16(tb + row * 128 + sw * 16,
                     Q + (long long)row * ld + k0 + c * 8);
            }
        }
    };

#pragma unroll
    for (int s = 0; s < STAGES; s++) {
        if (s < nK) load_stage(s, s);
        CP_COMMIT();
    }

    for (int t = 0; t < nK; t++) {
        const int buf = t % STAGES;
        CP_WAIT2();
        __syncthreads();

        const uint32_t sS = sbase + buf * STAGE3_B;
        const uint32_t sA = sS;
        const uint32_t sBh = sS + TILE_B;
        const uint32_t sBl = sS + 2 * TILE_B;

#pragma unroll
        for (int ks = 0; ks < 4; ks++) {
            uint32_t a[4][4], bh[2][4], bl[2][4];
#pragma unroll
            for (int i = 0; i < 4; i++)
                ldsm4(a[i], frag_addr(sA, warpM + i * 16, ks, lid));
#pragma unroll
            for (int j = 0; j < 2; j++)
                ldsm4(bh[j], frag_addr(sBh, warpN + j * 16, ks, lid));
#pragma unroll
            for (int j = 0; j < 2; j++)
                ldsm4(bl[j], frag_addr(sBl, warpN + j * 16, ks, lid));

#pragma unroll
            for (int i = 0; i < 4; i++) {
#pragma unroll
                for (int j = 0; j < 4; j++) {
                    uint32_t bh0 = bh[j >> 1][j & 1], bh1 = bh[j >> 1][(j & 1) + 2];
                    uint32_t bl0 = bl[j >> 1][j & 1], bl1 = bl[j >> 1][(j & 1) + 2];
                    mma_f16(acc[i][j], a[i], bh0, bh1);
                    mma_f16(acc[i][j], a[i], bl0, bl1);
                }
            }
        }
        __syncthreads();

        const int nt = t + STAGES;
        if (nt < nK) load_stage(nt, buf);
        CP_COMMIT();
    }

    const int g = lid >> 2;
    const int tq = lid & 3;
#pragma unroll
    for (int i = 0; i < 4; i++) {
        const long long r0 = rowBase + warpM + i * 16 + g;
        const long long r1 = r0 + 8;
#pragma unroll
        for (int j = 0; j < 4; j++) {
            const int col = colBase + warpN + j * 8 + tq * 2;
            float x0 = acc[i][j][0], x1 = acc[i][j][1];
            float x2 = acc[i][j][2], x3 = acc[i][j][3];
            __nv_bfloat16 h0 = __float2bfloat16(x0);
            __nv_bfloat16 h1 = __float2bfloat16(x1);
            __nv_bfloat16 h2 = __float2bfloat16(x2);
            __nv_bfloat16 h3 = __float2bfloat16(x3);
            __nv_bfloat162 hh01; hh01.x = h0; hh01.y = h1;
            __nv_bfloat162 hh23; hh23.x = h2; hh23.y = h3;
            __nv_bfloat162 ll01, ll23;
            ll01.x = __float2bfloat16(x0 - __bfloat162float(h0));
            ll01.y = __float2bfloat16(x1 - __bfloat162float(h1));
            ll23.x = __float2bfloat16(x2 - __bfloat162float(h2));
            ll23.y = __float2bfloat16(x3 - __bfloat162float(h3));
            *reinterpret_cast<__nv_bfloat162*>(Ch + cOff + r0 * ldc + col) = hh01;
            *reinterpret_cast<__nv_bfloat162*>(Ch + cOff + r1 * ldc + col) = hh23;
            *reinterpret_cast<__nv_bfloat162*>(Cl + cOff + r0 * ldc + col) = ll01;
            *reinterpret_cast<__nv_bfloat162*>(Cl + cOff + r1 * ldc + col) = ll23;
        }
    }
}

__global__ void __launch_bounds__(256)
split_f32(const float* __restrict__ x, __nv_bfloat16* __restrict__ h,
          __nv_bfloat16* __restrict__ l, long long n4)
{
    long long i = (long long)blockIdx.x * blockDim.x + threadIdx.x;
    if (i >= n4) return;
    float4 v = reinterpret_cast<const float4*>(x)[i];
    __nv_bfloat16 h0 = __float2bfloat16(v.x), h1 = __float2bfloat16(v.y);
    __nv_bfloat16 h2 = __float2bfloat16(v.z), h3 = __float2bfloat16(v.w);
    __nv_bfloat162 a, b;
    a.x = h0; a.y = h1; b.x = h2; b.y = h3;
    reinterpret_cast<__nv_bfloat162*>(h)[2 * i] = a;
    reinterpret_cast<__nv_bfloat162*>(h)[2 * i + 1] = b;
    a.x = __float2bfloat16(v.x - __bfloat162float(h0));
    a.y = __float2bfloat16(v.y - __bfloat162float(h1));
    b.x = __float2bfloat16(v.z - __bfloat162float(h2));
    b.y = __float2bfloat16(v.w - __bfloat162float(h3));
    reinterpret_cast<__nv_bfloat162*>(l)[2 * i] = a;
    reinterpret_cast<__nv_bfloat162*>(l)[2 * i + 1] = b;
}

__global__ void __launch_bounds__(256)
softmax_f16(const float* __restrict__ S, __half* __restrict__ P)
{
    const float* row = S + (long long)blockIdx.x * SEQ;
    __half* p = P + (long long)blockIdx.x * SEQ;
    const int tid = threadIdx.x;

    float v[16];
    float m = -INFINITY;
#pragma unroll
    for (int i = 0; i < 16; i++) {
        v[i] = row[tid + i * 256];
        m = fmaxf(m, v[i]);
    }
    __shared__ float red[256];
    red[tid] = m;
    __syncthreads();
#pragma unroll
    for (int s = 128; s > 0; s >>= 1) {
        if (tid < s) red[tid] = fmaxf(red[tid], red[tid + s]);
        __syncthreads();
    }
    m = red[0];
    __syncthreads();
    float sum = 0.0f;
#pragma unroll
    for (int i = 0; i < 16; i++) {
        v[i] = __expf(v[i] - m);
        sum += v[i];
    }
    red[tid] = sum;
    __syncthreads();
#pragma unroll
    for (int s = 128; s > 0; s >>= 1) {
        if (tid < s) red[tid] += red[tid + s];
        __syncthreads();
    }
    const float inv = 1.0f / red[0];
#pragma unroll
    for (int i = 0; i < 16; i++)
        p[tid + i * 256] = __float2half(v[i] * inv);
}

static void* sym_addr(const void* symbol)
{
    void* p = nullptr;
    cudaGetSymbolAddress(&p, symbol);
    return p;
}

extern "C" void kernel_launch(void* const* d_in, const int* in_sizes, int n_in,
                              void* d_out, int out_size)
{
    const float* X  = (const float*)d_in[0];
    const float* Wq = (const float*)d_in[1];
    const float* Wk = (const float*)d_in[2];
    const float* Wv = (const float*)d_in[3];
    const float* Wo = (const float*)d_in[4];
    float* out = (float*)d_out;

    __nv_bfloat16* Xh  = (__nv_bfloat16*)sym_addr(g_Xh);
    __nv_bfloat16* Xl  = (__nv_bfloat16*)sym_addr(g_Xl);
    __nv_bfloat16* Wqh = (__nv_bfloat16*)sym_addr(g_Wqh);
    __nv_bfloat16* Wql = (__nv_bfloat16*)sym_addr(g_Wql);
    __nv_bfloat16* Wkh = (__nv_bfloat16*)sym_addr(g_Wkh);
    __nv_bfloat16* Wkl = (__nv_bfloat16*)sym_addr(g_Wkl);
    __nv_bfloat16* Wvh = (__nv_bfloat16*)sym_addr(g_Wvh);
    __nv_bfloat16* Wvl = (__nv_bfloat16*)sym_addr(g_Wvl);
    __nv_bfloat16* Woh = (__nv_bfloat16*)sym_addr(g_Woh);
    __nv_bfloat16* Wol = (__nv_bfloat16*)sym_addr(g_Wol);
    __nv_bfloat16* Qh  = (__nv_bfloat16*)sym_addr(g_Qh);
    __nv_bfloat16* Ql  = (__nv_bfloat16*)sym_addr(g_Ql);
    __nv_bfloat16* Kh  = (__nv_bfloat16*)sym_addr(g_Kh);
    __nv_bfloat16* Kl  = (__nv_bfloat16*)sym_addr(g_Kl);
    __half*        Vth = (__half*)sym_addr(g_Vth);
    __half*        Vtl = (__half*)sym_addr(g_Vtl);
    float*         S   = (float*)sym_addr(g_S);
    __half*        P   = (__half*)sym_addr(g_P);
    __nv_bfloat16* Mh  = (__nv_bfloat16*)sym_addr(g_Mh);
    __nv_bfloat16* Ml  = (__nv_bfloat16*)sym_addr(g_Ml);

    cudaFuncSetAttribute(gemm_bf16x3, cudaFuncAttributeMaxDynamicSharedMemorySize,
                         GEMM_SMEM);
    cudaFuncSetAttribute(gemm_pv, cudaFuncAttributeMaxDynamicSharedMemorySize,
                         PV_SMEM);

    {
        long long n4;
        n4 = (long long)MS * DMODEL / 4;
        split_f32<<<(unsigned)((n4 + 255) / 256), 256>>>(X, Xh, Xl, n4);
        n4 = (long long)DMODEL * DMODEL / 4;
        split_f32<<<(unsigned)((n4 + 255) / 256), 256>>>(Wq, Wqh, Wql, n4);
        split_f32<<<(unsigned)((n4 + 255) / 256), 256>>>(Wo, Woh, Wol, n4);
        n4 = (long long)DK * DMODEL / 4;
        split_f32<<<(unsigned)((n4 + 255) / 256), 256>>>(Wk, Wkh, Wkl, n4);
        split_f32<<<(unsigned)((n4 + 255) / 256), 256>>>(Wv, Wvh, Wvl, n4);
    }

    gemm_bf16x3<<<dim3(DMODEL / BN, MS / BM, 1), 256, GEMM_SMEM>>>(
        Xh, Xl, Wqh, Wql, nullptr, Qh, Ql, nullptr, nullptr,
        DMODEL, DMODEL, DMODEL, DMODEL, 1.0f, 1,
        0, 0, 0, 0, 0, 0, 1);

    gemm_bf16x3<<<dim3(DK / BN, MS / BM, 1), 256, GEMM_SMEM>>>(
        Xh, Xl, Wkh, Wkl, nullptr, Kh, Kl, nullptr, nullptr,
        DMODEL, DMODEL, DMODEL, DK, 1.0f, 1,
        0, 0, 0, 0, 0, 0, 1);

    gemm_bf16x3<<<dim3(SEQ / BN, DK / BM, BATCH), 256, GEMM_SMEM>>>(
        Wvh, Wvl, Xh, Xl, nullptr, nullptr, nullptr, Vth, Vtl,
        DMODEL, DMODEL, DMODEL, SEQ, 1.0f, 2,
        0, 0, (long long)SEQ * DMODEL, 0, (long long)DK * SEQ, 0, 1);

    gemm_bf16x3<<<dim3(SEQ / BN, SEQ / BM, BATCH * NHEAD), 256, GEMM_SMEM>>>(
        Qh, Ql, Kh, Kl, S, nullptr, nullptr, nullptr, nullptr,
        DK, DMODEL, DK, SEQ, SCALE_F, 0,
        (long long)SEQ * DMODEL, DK,
        (long long)SEQ * DK, 0,
        (long long)NHEAD * SEQ * SEQ, (long long)SEQ * SEQ, NHEAD);

    softmax_f16<<<BATCH * NHEAD * SEQ, 256>>>(S, P);

    gemm_pv<<<dim3(DK / BN, SEQ / BM, BATCH * NHEAD), 256, PV_SMEM>>>(
        P, Vth, Vtl, Mh, Ml,
        SEQ, SEQ, SEQ, DMODEL,
        (long long)NHEAD * SEQ * SEQ, (long long)SEQ * SEQ,
        (long long)DK * SEQ, 0,
        (long long)SEQ * DMODEL, DK, NHEAD);

    gemm_bf16x3<<<dim3(DMODEL / BN, MS / BM, 1), 256, GEMM_SMEM>>>(
        Mh, Ml, Woh, Wol, out, nullptr, nullptr, nullptr, nullptr,
        DMODEL, DMODEL, DMODEL, DMODEL, 1.0f, 0,
        0, 0, 0, 0, 0, 0, 1);
}

// round 5
// speedup vs baseline: 3.2682x; 1.1276x over previous
#include <cuda_runtime.h>
#include <cuda_bf16.h>
#include <cuda_fp16.h>
#include <cstdint>
#include <math.h>

#define BATCH 2
#define SEQ   4096
#define DMODEL 1024
#define NHEAD 4
#define DK    256
#define MS (BATCH * SEQ)
#define SCALE_F (1.0f / 16.0f)

#define BM 128
#define BN 128
#define STAGES 3
#define TILE_B 16384
#define STAGE4_B (4 * TILE_B)
#define GEMM_SMEM (STAGES * STAGE4_B)
#define STAGE2_B (2 * TILE_B)
#define PV_SMEM (STAGES * STAGE2_B)

__device__ __align__(256) __nv_bfloat16 g_Xh[(size_t)MS * DMODEL];
__device__ __align__(256) __nv_bfloat16 g_Xl[(size_t)MS * DMODEL];
__device__ __align__(256) __nv_bfloat16 g_Wqh[(size_t)DMODEL * DMODEL];
__device__ __align__(256) __nv_bfloat16 g_Wql[(size_t)DMODEL * DMODEL];
__device__ __align__(256) __nv_bfloat16 g_Wkh[(size_t)DK * DMODEL];
__device__ __align__(256) __nv_bfloat16 g_Wkl[(size_t)DK * DMODEL];
__device__ __align__(256) __nv_bfloat16 g_Wvh[(size_t)DK * DMODEL];
__device__ __align__(256) __nv_bfloat16 g_Wvl[(size_t)DK * DMODEL];
__device__ __align__(256) __nv_bfloat16 g_Woh[(size_t)DMODEL * DMODEL];
__device__ __align__(256) __nv_bfloat16 g_Wol[(size_t)DMODEL * DMODEL];
__device__ __align__(256) __nv_bfloat16 g_Qh[(size_t)MS * DMODEL];
__device__ __align__(256) __nv_bfloat16 g_Ql[(size_t)MS * DMODEL];
__device__ __align__(256) __nv_bfloat16 g_Kh[(size_t)MS * DK];
__device__ __align__(256) __nv_bfloat16 g_Kl[(size_t)MS * DK];
__device__ __align__(256) __half        g_Vt[(size_t)BATCH * DK * SEQ];
__device__ __align__(256) float         g_S[(size_t)BATCH * NHEAD * SEQ * SEQ];
__device__ __align__(256) __half        g_P[(size_t)BATCH * NHEAD * SEQ * SEQ];
__device__ __align__(256) __nv_bfloat16 g_Mh[(size_t)MS * DMODEL];
__device__ __align__(256) __nv_bfloat16 g_Ml[(size_t)MS * DMODEL];

__device__ __forceinline__ uint32_t smem_u32(const void* p) {
    uint32_t a;
    asm("{ .reg .u64 t; cvta.to.shared.u64 t, %1; cvt.u32.u64 %0, t; }"
        : "=r"(a) : "l"(p));
    return a;
}
__device__ __forceinline__ void cp16(uint32_t s, const void* g) {
    asm volatile("cp.async.cg.shared.global [%0], [%1], 16;" :: "r"(s), "l"(g));
}
#define CP_COMMIT() asm volatile("cp.async.commit_group;" ::: "memory")
#define CP_WAIT2()  asm volatile("cp.async.wait_group 2;" ::: "memory")

__device__ __forceinline__ void ldsm4(uint32_t* r, uint32_t addr) {
    asm volatile("ldmatrix.sync.aligned.m8n8.x4.shared.b16 {%0,%1,%2,%3}, [%4];"
                 : "=r"(r[0]), "=r"(r[1]), "=r"(r[2]), "=r"(r[3]) : "r"(addr));
}
__device__ __forceinline__ void mma_bf16(float* c, const uint32_t* a,
                                         uint32_t b0, uint32_t b1) {
    asm volatile(
        "mma.sync.aligned.m16n8k16.row.col.f32.bf16.bf16.f32 "
        "{%0,%1,%2,%3}, {%4,%5,%6,%7}, {%8,%9}, {%0,%1,%2,%3};\n"
        : "+f"(c[0]), "+f"(c[1]), "+f"(c[2]), "+f"(c[3])
        : "r"(a[0]), "r"(a[1]), "r"(a[2]), "r"(a[3]), "r"(b0), "r"(b1));
}
__device__ __forceinline__ void mma_f16(float* c, const uint32_t* a,
                                        uint32_t b0, uint32_t b1) {
    asm volatile(
        "mma.sync.aligned.m16n8k16.row.col.f32.f16.f16.f32 "
        "{%0,%1,%2,%3}, {%4,%5,%6,%7}, {%8,%9}, {%0,%1,%2,%3};\n"
        : "+f"(c[0]), "+f"(c[1]), "+f"(c[2]), "+f"(c[3])
        : "r"(a[0]), "r"(a[1]), "r"(a[2]), "r"(a[3]), "r"(b0), "r"(b1));
}
__device__ __forceinline__ uint32_t frag_addr(uint32_t tbase, int rowBase,
                                              int ks, int lane) {
    int row = rowBase + (lane & 15);
    int chunk = ks * 2 + (lane >> 4);
    int sw = chunk ^ (row & 7);
    return tbase + row * 128 + sw * 16;
}

// ---------------------------------------------------------------------------
// bf16 3-phase split GEMM: C = alpha*(A*B^T), A=Ah+Al, B=Bh+Bl.
// mode 0: fp32 out. mode 1: bf16 hi/lo out. mode 2: fp16 single out (Hh).
// ---------------------------------------------------------------------------
__global__ void __launch_bounds__(256, 1)
gemm_bf16x3(const __nv_bfloat16* __restrict__ Ah, const __nv_bfloat16* __restrict__ Al,
            const __nv_bfloat16* __restrict__ Bh, const __nv_bfloat16* __restrict__ Bl,
            float* __restrict__ Cf, __nv_bfloat16* __restrict__ Ch,
            __nv_bfloat16* __restrict__ Cl, __half* __restrict__ Hh,
            int K, int lda, int ldb, int ldc, float alpha, int mode,
            long long aSB, long long aSH, long long bSB, long long bSH,
            long long cSB, long long cSH, int H)
{
    extern __shared__ char smem[];
    const uint32_t sbase = smem_u32(smem);
    const int tid = threadIdx.x;
    const int wid = tid >> 5;
    const int lid = tid & 31;

    const int zb = blockIdx.z / H;
    const int zh = blockIdx.z - zb * H;
    const int rowBase = blockIdx.y * BM;
    const int colBase = blockIdx.x * BN;

    const __nv_bfloat16* Ah_ = Ah + zb * aSB + zh * aSH + (long long)rowBase * lda;
    const __nv_bfloat16* Al_ = Al + zb * aSB + zh * aSH + (long long)rowBase * lda;
    const __nv_bfloat16* Bh_ = Bh + zb * bSB + zh * bSH + (long long)colBase * ldb;
    const __nv_bfloat16* Bl_ = Bl + zb * bSB + zh * bSH + (long long)colBase * ldb;
    const long long cOff = zb * cSB + zh * cSH;

    const int warpM = (wid >> 2) * 64;
    const int warpN = (wid & 3) * 32;

    float acc[4][4][4];
#pragma unroll
    for (int i = 0; i < 4; i++)
#pragma unroll
        for (int j = 0; j < 4; j++)
#pragma unroll
            for (int v = 0; v < 4; v++) acc[i][j][v] = 0.0f;

    const int nK = K >> 6;

    auto load_stage = [&](int t, int buf) {
        const int k0 = t << 6;
        const uint32_t sS = sbase + buf * STAGE4_B;
        const __nv_bfloat16* src[4] = {Ah_, Al_, Bh_, Bl_};
        const int lds[4] = {lda, lda, ldb, ldb};
#pragma unroll
        for (int tl = 0; tl < 4; tl++) {
            const __nv_bfloat16* P = src[tl];
            const int ld = lds[tl];
            const uint32_t tb = sS + tl * TILE_B;
#pragma unroll
            for (int j = 0; j < 4; j++) {
                int idx = tid + j * 256;
                int row = idx >> 3;
                int c = idx & 7;
                int sw = c ^ (row & 7);
                cp16(tb + row * 128 + sw * 16,
                     P + (long long)row * ld + k0 + c * 8);
            }
        }
    };

#pragma unroll
    for (int s = 0; s < STAGES; s++) {
        if (s < nK) load_stage(s, s);
        CP_COMMIT();
    }

    for (int t = 0; t < nK; t++) {
        const int buf = t % STAGES;
        CP_WAIT2();
        __syncthreads();

        const uint32_t sS = sbase + buf * STAGE4_B;
        const uint32_t sAh = sS;
        const uint32_t sAl = sS + TILE_B;
        const uint32_t sBh = sS + 2 * TILE_B;
        const uint32_t sBl = sS + 3 * TILE_B;

#pragma unroll
        for (int ks = 0; ks < 4; ks++) {
            uint32_t ah[4][4], al[4][4], bh[2][4], bl[2][4];
#pragma unroll
            for (int i = 0; i < 4; i++)
                ldsm4(ah[i], frag_addr(sAh, warpM + i * 16, ks, lid));
#pragma unroll
            for (int j = 0; j < 2; j++)
                ldsm4(bh[j], frag_addr(sBh, warpN + j * 16, ks, lid));
#pragma unroll
            for (int j = 0; j < 2; j++)
                ldsm4(bl[j], frag_addr(sBl, warpN + j * 16, ks, lid));
#pragma unroll
            for (int i = 0; i < 4; i++)
                ldsm4(al[i], frag_addr(sAl, warpM + i * 16, ks, lid));

#pragma unroll
            for (int i = 0; i < 4; i++) {
#pragma unroll
                for (int j = 0; j < 4; j++) {
                    uint32_t bh0 = bh[j >> 1][j & 1], bh1 = bh[j >> 1][(j & 1) + 2];
                    uint32_t bl0 = bl[j >> 1][j & 1], bl1 = bl[j >> 1][(j & 1) + 2];
                    mma_bf16(acc[i][j], ah[i], bh0, bh1);
                    mma_bf16(acc[i][j], ah[i], bl0, bl1);
                    mma_bf16(acc[i][j], al[i], bh0, bh1);
                }
            }
        }
        __syncthreads();

        const int nt = t + STAGES;
        if (nt < nK) load_stage(nt, buf);
        CP_COMMIT();
    }

    const int g = lid >> 2;
    const int tq = lid & 3;
#pragma unroll
    for (int i = 0; i < 4; i++) {
        const long long r0 = rowBase + warpM + i * 16 + g;
        const long long r1 = r0 + 8;
#pragma unroll
        for (int j = 0; j < 4; j++) {
            const int col = colBase + warpN + j * 8 + tq * 2;
            float x0 = acc[i][j][0], x1 = acc[i][j][1];
            float x2 = acc[i][j][2], x3 = acc[i][j][3];
            if (mode == 0) {
                *reinterpret_cast<float2*>(Cf + cOff + r0 * ldc + col) =
                    make_float2(x0 * alpha, x1 * alpha);
                *reinterpret_cast<float2*>(Cf + cOff + r1 * ldc + col) =
                    make_float2(x2 * alpha, x3 * alpha);
            } else if (mode == 1) {
                __nv_bfloat16 h0 = __float2bfloat16(x0);
                __nv_bfloat16 h1 = __float2bfloat16(x1);
                __nv_bfloat16 h2 = __float2bfloat16(x2);
                __nv_bfloat16 h3 = __float2bfloat16(x3);
                __nv_bfloat162 hh01; hh01.x = h0; hh01.y = h1;
                __nv_bfloat162 hh23; hh23.x = h2; hh23.y = h3;
                __nv_bfloat162 ll01, ll23;
                ll01.x = __float2bfloat16(x0 - __bfloat162float(h0));
                ll01.y = __float2bfloat16(x1 - __bfloat162float(h1));
                ll23.x = __float2bfloat16(x2 - __bfloat162float(h2));
                ll23.y = __float2bfloat16(x3 - __bfloat162float(h3));
                *reinterpret_cast<__nv_bfloat162*>(Ch + cOff + r0 * ldc + col) = hh01;
                *reinterpret_cast<__nv_bfloat162*>(Ch + cOff + r1 * ldc + col) = hh23;
                *reinterpret_cast<__nv_bfloat162*>(Cl + cOff + r0 * ldc + col) = ll01;
                *reinterpret_cast<__nv_bfloat162*>(Cl + cOff + r1 * ldc + col) = ll23;
            } else {
                __half2 hh01; hh01.x = __float2half(x0); hh01.y = __float2half(x1);
                __half2 hh23; hh23.x = __float2half(x2); hh23.y = __float2half(x3);
                *reinterpret_cast<__half2*>(Hh + cOff + r0 * ldc + col) = hh01;
                *reinterpret_cast<__half2*>(Hh + cOff + r1 * ldc + col) = hh23;
            }
        }
    }
}

// ---------------------------------------------------------------------------
// PV GEMM, single-phase fp16: M = P * Vt^T (P fp16, Vt fp16).
// Output: bf16 hi/lo split (feeds 3-phase O-proj).
// ---------------------------------------------------------------------------
__global__ void __launch_bounds__(256, 1)
gemm_pv(const __half* __restrict__ P, const __half* __restrict__ V,
        __nv_bfloat16* __restrict__ Ch, __nv_bfloat16* __restrict__ Cl,
        int K, int lda, int ldb, int ldc,
        long long aSB, long long aSH, long long bSB, long long bSH,
        long long cSB, long long cSH, int H)
{
    extern __shared__ char smem[];
    const uint32_t sbase = smem_u32(smem);
    const int tid = threadIdx.x;
    const int wid = tid >> 5;
    const int lid = tid & 31;

    const int zb = blockIdx.z / H;
    const int zh = blockIdx.z - zb * H;
    const int rowBase = blockIdx.y * BM;
    const int colBase = blockIdx.x * BN;

    const __half* A_ = P + zb * aSB + zh * aSH + (long long)rowBase * lda;
    const __half* B_ = V + zb * bSB + zh * bSH + (long long)colBase * ldb;
    const long long cOff = zb * cSB + zh * cSH;

    const int warpM = (wid >> 2) * 64;
    const int warpN = (wid & 3) * 32;

    float acc[4][4][4];
#pragma unroll
    for (int i = 0; i < 4; i++)
#pragma unroll
        for (int j = 0; j < 4; j++)
#pragma unroll
            for (int v = 0; v < 4; v++) acc[i][j][v] = 0.0f;

    const int nK = K >> 6;

    auto load_stage = [&](int t, int buf) {
        const int k0 = t << 6;
        const uint32_t sS = sbase + buf * STAGE2_B;
        const __half* src[2] = {A_, B_};
        const int lds[2] = {lda, ldb};
#pragma unroll
        for (int tl = 0; tl < 2; tl++) {
            const __half* Q = src[tl];
            const int ld = lds[tl];
            const uint32_t tb = sS + tl * TILE_B;
#pragma unroll
            for (int j = 0; j < 4; j++) {
                int idx = tid + j * 256;
                int row = idx >> 3;
                int c = idx & 7;
                int sw = c ^ (row & 7);
                cp16(tb + row * 128 + sw * 16,
                     Q + (long long)row * ld + k0 + c * 8);
            }
        }
    };

#pragma unroll
    for (int s = 0; s < STAGES; s++) {
        if (s < nK) load_stage(s, s);
        CP_COMMIT();
    }

    for (int t = 0; t < nK; t++) {
        const int buf = t % STAGES;
        CP_WAIT2();
        __syncthreads();

        const uint32_t sS = sbase + buf * STAGE2_B;
        const uint32_t sA = sS;
        const uint32_t sB = sS + TILE_B;

#pragma unroll
        for (int ks = 0; ks < 4; ks++) {
            uint32_t a[4][4], b[2][4];
#pragma unroll
            for (int i = 0; i < 4; i++)
                ldsm4(a[i], frag_addr(sA, warpM + i * 16, ks, lid));
#pragma unroll
            for (int j = 0; j < 2; j++)
                ldsm4(b[j], frag_addr(sB, warpN + j * 16, ks, lid));

#pragma unroll
            for (int i = 0; i < 4; i++) {
#pragma unroll
                for (int j = 0; j < 4; j++) {
                    uint32_t b0 = b[j >> 1][j & 1], b1 = b[j >> 1][(j & 1) + 2];
                    mma_f16(acc[i][j], a[i], b0, b1);
                }
            }
        }
        __syncthreads();

        const int nt = t + STAGES;
        if (nt < nK) load_stage(nt, buf);
        CP_COMMIT();
    }

    const int g = lid >> 2;
    const int tq = lid & 3;
#pragma unroll
    for (int i = 0; i < 4; i++) {
        const long long r0 = rowBase + warpM + i * 16 + g;
        const long long r1 = r0 + 8;
#pragma unroll
        for (int j = 0; j < 4; j++) {
            const int col = colBase + warpN + j * 8 + tq * 2;
            float x0 = acc[i][j][0], x1 = acc[i][j][1];
            float x2 = acc[i][j][2], x3 = acc[i][j][3];
            __nv_bfloat16 h0 = __float2bfloat16(x0);
            __nv_bfloat16 h1 = __float2bfloat16(x1);
            __nv_bfloat16 h2 = __float2bfloat16(x2);
            __nv_bfloat16 h3 = __float2bfloat16(x3);
            __nv_bfloat162 hh01; hh01.x = h0; hh01.y = h1;
            __nv_bfloat162 hh23; hh23.x = h2; hh23.y = h3;
            __nv_bfloat162 ll01, ll23;
            ll01.x = __float2bfloat16(x0 - __bfloat162float(h0));
            ll01.y = __float2bfloat16(x1 - __bfloat162float(h1));
            ll23.x = __float2bfloat16(x2 - __bfloat162float(h2));
            ll23.y = __float2bfloat16(x3 - __bfloat162float(h3));
            *reinterpret_cast<__nv_bfloat162*>(Ch + cOff + r0 * ldc + col) = hh01;
            *reinterpret_cast<__nv_bfloat162*>(Ch + cOff + r1 * ldc + col) = hh23;
            *reinterpret_cast<__nv_bfloat162*>(Cl + cOff + r0 * ldc + col) = ll01;
            *reinterpret_cast<__nv_bfloat162*>(Cl + cOff + r1 * ldc + col) = ll23;
        }
    }
}

__global__ void __launch_bounds__(256)
split_f32(const float* __restrict__ x, __nv_bfloat16* __restrict__ h,
          __nv_bfloat16* __restrict__ l, long long n4)
{
    long long i = (long long)blockIdx.x * blockDim.x + threadIdx.x;
    if (i >= n4) return;
    float4 v = reinterpret_cast<const float4*>(x)[i];
    __nv_bfloat16 h0 = __float2bfloat16(v.x), h1 = __float2bfloat16(v.y);
    __nv_bfloat16 h2 = __float2bfloat16(v.z), h3 = __float2bfloat16(v.w);
    __nv_bfloat162 a, b;
    a.x = h0; a.y = h1; b.x = h2; b.y = h3;
    reinterpret_cast<__nv_bfloat162*>(h)[2 * i] = a;
    reinterpret_cast<__nv_bfloat162*>(h)[2 * i + 1] = b;
    a.x = __float2bfloat16(v.x - __bfloat162float(h0));
    a.y = __float2bfloat16(v.y - __bfloat162float(h1));
    b.x = __float2bfloat16(v.z - __bfloat162float(h2));
    b.y = __float2bfloat16(v.w - __bfloat162float(h3));
    reinterpret_cast<__nv_bfloat162*>(l)[2 * i] = a;
    reinterpret_cast<__nv_bfloat162*>(l)[2 * i + 1] = b;
}

__global__ void __launch_bounds__(256)
softmax_f16(const float* __restrict__ S, __half* __restrict__ P)
{
    const float* row = S + (long long)blockIdx.x * SEQ;
    __half* p = P + (long long)blockIdx.x * SEQ;
    const int tid = threadIdx.x;

    float v[16];
    float m = -INFINITY;
#pragma unroll
    for (int i = 0; i < 16; i++) {
        v[i] = row[tid + i * 256];
        m = fmaxf(m, v[i]);
    }
    __shared__ float red[256];
    red[tid] = m;
    __syncthreads();
#pragma unroll
    for (int s = 128; s > 0; s >>= 1) {
        if (tid < s) red[tid] = fmaxf(red[tid], red[tid + s]);
        __syncthreads();
    }
    m = red[0];
    __syncthreads();
    float sum = 0.0f;
#pragma unroll
    for (int i = 0; i < 16; i++) {
        v[i] = __expf(v[i] - m);
        sum += v[i];
    }
    red[tid] = sum;
    __syncthreads();
#pragma unroll
    for (int s = 128; s > 0; s >>= 1) {
        if (tid < s) red[tid] += red[tid + s];
        __syncthreads();
    }
    const float inv = 1.0f / red[0];
#pragma unroll
    for (int i = 0; i < 16; i++)
        p[tid + i * 256] = __float2half(v[i] * inv);
}

static void* sym_addr(const void* symbol)
{
    void* p = nullptr;
    cudaGetSymbolAddress(&p, symbol);
    return p;
}

extern "C" void kernel_launch(void* const* d_in, const int* in_sizes, int n_in,
                              void* d_out, int out_size)
{
    const float* X  = (const float*)d_in[0];
    const float* Wq = (const float*)d_in[1];
    const float* Wk = (const float*)d_in[2];
    const float* Wv = (const float*)d_in[3];
    const float* Wo = (const float*)d_in[4];
    float* out = (float*)d_out;

    __nv_bfloat16* Xh  = (__nv_bfloat16*)sym_addr(g_Xh);
    __nv_bfloat16* Xl  = (__nv_bfloat16*)sym_addr(g_Xl);
    __nv_bfloat16* Wqh = (__nv_bfloat16*)sym_addr(g_Wqh);
    __nv_bfloat16* Wql = (__nv_bfloat16*)sym_addr(g_Wql);
    __nv_bfloat16* Wkh = (__nv_bfloat16*)sym_addr(g_Wkh);
    __nv_bfloat16* Wkl = (__nv_bfloat16*)sym_addr(g_Wkl);
    __nv_bfloat16* Wvh = (__nv_bfloat16*)sym_addr(g_Wvh);
    __nv_bfloat16* Wvl = (__nv_bfloat16*)sym_addr(g_Wvl);
    __nv_bfloat16* Woh = (__nv_bfloat16*)sym_addr(g_Woh);
    __nv_bfloat16* Wol = (__nv_bfloat16*)sym_addr(g_Wol);
    __nv_bfloat16* Qh  = (__nv_bfloat16*)sym_addr(g_Qh);
    __nv_bfloat16* Ql  = (__nv_bfloat16*)sym_addr(g_Ql);
    __nv_bfloat16* Kh  = (__nv_bfloat16*)sym_addr(g_Kh);
    __nv_bfloat16* Kl  = (__nv_bfloat16*)sym_addr(g_Kl);
    __half*        Vt  = (__half*)sym_addr(g_Vt);
    float*         S   = (float*)sym_addr(g_S);
    __half*        P   = (__half*)sym_addr(g_P);
    __nv_bfloat16* Mh  = (__nv_bfloat16*)sym_addr(g_Mh);
    __nv_bfloat16* Ml  = (__nv_bfloat16*)sym_addr(g_Ml);

    cudaFuncSetAttribute(gemm_bf16x3, cudaFuncAttributeMaxDynamicSharedMemorySize,
                         GEMM_SMEM);
    cudaFuncSetAttribute(gemm_pv, cudaFuncAttributeMaxDynamicSharedMemorySize,
                         PV_SMEM);

    {
        long long n4;
        n4 = (long long)MS * DMODEL / 4;
        split_f32<<<(unsigned)((n4 + 255) / 256), 256>>>(X, Xh, Xl, n4);
        n4 = (long long)DMODEL * DMODEL / 4;
        split_f32<<<(unsigned)((n4 + 255) / 256), 256>>>(Wq, Wqh, Wql, n4);
        split_f32<<<(unsigned)((n4 + 255) / 256), 256>>>(Wo, Woh, Wol, n4);
        n4 = (long long)DK * DMODEL / 4;
        split_f32<<<(unsigned)((n4 + 255) / 256), 256>>>(Wk, Wkh, Wkl, n4);
        split_f32<<<(unsigned)((n4 + 255) / 256), 256>>>(Wv, Wvh, Wvl, n4);
    }

    // Q = X @ Wq^T -> bf16 split
    gemm_bf16x3<<<dim3(DMODEL / BN, MS / BM, 1), 256, GEMM_SMEM>>>(
        Xh, Xl, Wqh, Wql, nullptr, Qh, Ql, nullptr,
        DMODEL, DMODEL, DMODEL, DMODEL, 1.0f, 1,
        0, 0, 0, 0, 0, 0, 1);

    // Kc = X @ Wk^T -> bf16 split
    gemm_bf16x3<<<dim3(DK / BN, MS / BM, 1), 256, GEMM_SMEM>>>(
        Xh, Xl, Wkh, Wkl, nullptr, Kh, Kl, nullptr,
        DMODEL, DMODEL, DMODEL, DK, 1.0f, 1,
        0, 0, 0, 0, 0, 0, 1);

    // VcT[b] = Wv @ X[b]^T -> fp16 single [256 x 4096] per batch
    gemm_bf16x3<<<dim3(SEQ / BN, DK / BM, BATCH), 256, GEMM_SMEM>>>(
        Wvh, Wvl, Xh, Xl, nullptr, nullptr, nullptr, Vt,
        DMODEL, DMODEL, DMODEL, SEQ, 1.0f, 2,
        0, 0, (long long)SEQ * DMODEL, 0, (long long)DK * SEQ, 0, 1);

    // S[b,h] = SCALE * Q[b,h] @ Kc[b]^T -> fp32
    gemm_bf16x3<<<dim3(SEQ / BN, SEQ / BM, BATCH * NHEAD), 256, GEMM_SMEM>>>(
        Qh, Ql, Kh, Kl, S, nullptr, nullptr, nullptr,
        DK, DMODEL, DK, SEQ, SCALE_F, 0,
        (long long)SEQ * DMODEL, DK,
        (long long)SEQ * DK, 0,
        (long long)NHEAD * SEQ * SEQ, (long long)SEQ * SEQ, NHEAD);

    // softmax -> fp16 P
    softmax_f16<<<BATCH * NHEAD * SEQ, 256>>>(S, P);

    // merged = P @ VcT^T -> bf16 split (single-phase fp16)
    gemm_pv<<<dim3(DK / BN, SEQ / BM, BATCH * NHEAD), 256, PV_SMEM>>>(
        P, Vt, Mh, Ml,
        SEQ, SEQ, SEQ, DMODEL,
        (long long)NHEAD * SEQ * SEQ, (long long)SEQ * SEQ,
        (long long)DK * SEQ, 0,
        (long long)SEQ * DMODEL, DK, NHEAD);

    // out = merged @ Wo^T -> fp32
    gemm_bf16x3<<<dim3(DMODEL / BN, MS / BM, 1), 256, GEMM_SMEM>>>(
        Mh, Ml, Woh, Wol, out, nullptr, nullptr, nullptr,
        DMODEL, DMODEL, DMODEL, DMODEL, 1.0f, 0,
        0, 0, 0, 0, 0, 0, 1);
}

// round 6
// speedup vs baseline: 4.2537x; 1.3016x over previous
#include <cuda_runtime.h>
#include <cuda_bf16.h>
#include <cuda_fp16.h>
#include <cstdint>
#include <math.h>

#define BATCH 2
#define SEQ   4096
#define DMODEL 1024
#define NHEAD 4
#define DK    256
#define MS (BATCH * SEQ)
#define SCALE_F (1.0f / 16.0f)

#define BM 128
#define BN 128
#define STAGES 3
#define TILE_B 16384
#define STAGE4_B (4 * TILE_B)
#define GEMM_SMEM (STAGES * STAGE4_B)
#define STAGE2_B (2 * TILE_B)
#define F16_SMEM (STAGES * STAGE2_B)

__device__ __align__(256) __nv_bfloat16 g_Xh[(size_t)MS * DMODEL];
__device__ __align__(256) __nv_bfloat16 g_Xl[(size_t)MS * DMODEL];
__device__ __align__(256) __nv_bfloat16 g_Wqh[(size_t)DMODEL * DMODEL];
__device__ __align__(256) __nv_bfloat16 g_Wql[(size_t)DMODEL * DMODEL];
__device__ __align__(256) __nv_bfloat16 g_Wkh[(size_t)DK * DMODEL];
__device__ __align__(256) __nv_bfloat16 g_Wkl[(size_t)DK * DMODEL];
__device__ __align__(256) __nv_bfloat16 g_Wvh[(size_t)DK * DMODEL];
__device__ __align__(256) __nv_bfloat16 g_Wvl[(size_t)DK * DMODEL];
__device__ __align__(256) __nv_bfloat16 g_Woh[(size_t)DMODEL * DMODEL];
__device__ __align__(256) __nv_bfloat16 g_Wol[(size_t)DMODEL * DMODEL];
__device__ __align__(256) __half        g_Qf[(size_t)MS * DMODEL];
__device__ __align__(256) __half        g_Kf[(size_t)MS * DK];
__device__ __align__(256) __half        g_Vt[(size_t)BATCH * DK * SEQ];
__device__ __align__(256) float         g_S[(size_t)BATCH * NHEAD * SEQ * SEQ];
__device__ __align__(256) __half        g_P[(size_t)BATCH * NHEAD * SEQ * SEQ];
__device__ __align__(256) __nv_bfloat16 g_Mh[(size_t)MS * DMODEL];
__device__ __align__(256) __nv_bfloat16 g_Ml[(size_t)MS * DMODEL];

__device__ __forceinline__ uint32_t smem_u32(const void* p) {
    uint32_t a;
    asm("{ .reg .u64 t; cvta.to.shared.u64 t, %1; cvt.u32.u64 %0, t; }"
        : "=r"(a) : "l"(p));
    return a;
}
__device__ __forceinline__ void cp16(uint32_t s, const void* g) {
    asm volatile("cp.async.cg.shared.global [%0], [%1], 16;" :: "r"(s), "l"(g));
}
#define CP_COMMIT() asm volatile("cp.async.commit_group;" ::: "memory")
#define CP_WAIT2()  asm volatile("cp.async.wait_group 2;" ::: "memory")

__device__ __forceinline__ void ldsm4(uint32_t* r, uint32_t addr) {
    asm volatile("ldmatrix.sync.aligned.m8n8.x4.shared.b16 {%0,%1,%2,%3}, [%4];"
                 : "=r"(r[0]), "=r"(r[1]), "=r"(r[2]), "=r"(r[3]) : "r"(addr));
}
__device__ __forceinline__ void mma_bf16(float* c, const uint32_t* a,
                                         uint32_t b0, uint32_t b1) {
    asm volatile(
        "mma.sync.aligned.m16n8k16.row.col.f32.bf16.bf16.f32 "
        "{%0,%1,%2,%3}, {%4,%5,%6,%7}, {%8,%9}, {%0,%1,%2,%3};\n"
        : "+f"(c[0]), "+f"(c[1]), "+f"(c[2]), "+f"(c[3])
        : "r"(a[0]), "r"(a[1]), "r"(a[2]), "r"(a[3]), "r"(b0), "r"(b1));
}
__device__ __forceinline__ void mma_f16(float* c, const uint32_t* a,
                                        uint32_t b0, uint32_t b1) {
    asm volatile(
        "mma.sync.aligned.m16n8k16.row.col.f32.f16.f16.f32 "
        "{%0,%1,%2,%3}, {%4,%5,%6,%7}, {%8,%9}, {%0,%1,%2,%3};\n"
        : "+f"(c[0]), "+f"(c[1]), "+f"(c[2]), "+f"(c[3])
        : "r"(a[0]), "r"(a[1]), "r"(a[2]), "r"(a[3]), "r"(b0), "r"(b1));
}
__device__ __forceinline__ uint32_t frag_addr(uint32_t tbase, int rowBase,
                                              int ks, int lane) {
    int row = rowBase + (lane & 15);
    int chunk = ks * 2 + (lane >> 4);
    int sw = chunk ^ (row & 7);
    return tbase + row * 128 + sw * 16;
}

// ---------------------------------------------------------------------------
// bf16 3-phase split GEMM: C = alpha*(A*B^T), A=Ah+Al, B=Bh+Bl.
// mode 0: fp32 out. mode 1: bf16 hi/lo out. mode 2: fp16 single out (Hh).
// ---------------------------------------------------------------------------
__global__ void __launch_bounds__(256, 1)
gemm_bf16x3(const __nv_bfloat16* __restrict__ Ah, const __nv_bfloat16* __restrict__ Al,
            const __nv_bfloat16* __restrict__ Bh, const __nv_bfloat16* __restrict__ Bl,
            float* __restrict__ Cf, __nv_bfloat16* __restrict__ Ch,
            __nv_bfloat16* __restrict__ Cl, __half* __restrict__ Hh,
            int K, int lda, int ldb, int ldc, float alpha, int mode,
            long long aSB, long long aSH, long long bSB, long long bSH,
            long long cSB, long long cSH, int H)
{
    extern __shared__ char smem[];
    const uint32_t sbase = smem_u32(smem);
    const int tid = threadIdx.x;
    const int wid = tid >> 5;
    const int lid = tid & 31;

    const int zb = blockIdx.z / H;
    const int zh = blockIdx.z - zb * H;
    const int rowBase = blockIdx.y * BM;
    const int colBase = blockIdx.x * BN;

    const __nv_bfloat16* Ah_ = Ah + zb * aSB + zh * aSH + (long long)rowBase * lda;
    const __nv_bfloat16* Al_ = Al + zb * aSB + zh * aSH + (long long)rowBase * lda;
    const __nv_bfloat16* Bh_ = Bh + zb * bSB + zh * bSH + (long long)colBase * ldb;
    const __nv_bfloat16* Bl_ = Bl + zb * bSB + zh * bSH + (long long)colBase * ldb;
    const long long cOff = zb * cSB + zh * cSH;

    const int warpM = (wid >> 2) * 64;
    const int warpN = (wid & 3) * 32;

    float acc[4][4][4];
#pragma unroll
    for (int i = 0; i < 4; i++)
#pragma unroll
        for (int j = 0; j < 4; j++)
#pragma unroll
            for (int v = 0; v < 4; v++) acc[i][j][v] = 0.0f;

    const int nK = K >> 6;

    auto load_stage = [&](int t, int buf) {
        const int k0 = t << 6;
        const uint32_t sS = sbase + buf * STAGE4_B;
        const __nv_bfloat16* src[4] = {Ah_, Al_, Bh_, Bl_};
        const int lds[4] = {lda, lda, ldb, ldb};
#pragma unroll
        for (int tl = 0; tl < 4; tl++) {
            const __nv_bfloat16* P = src[tl];
            const int ld = lds[tl];
            const uint32_t tb = sS + tl * TILE_B;
#pragma unroll
            for (int j = 0; j < 4; j++) {
                int idx = tid + j * 256;
                int row = idx >> 3;
                int c = idx & 7;
                int sw = c ^ (row & 7);
                cp16(tb + row * 128 + sw * 16,
                     P + (long long)row * ld + k0 + c * 8);
            }
        }
    };

#pragma unroll
    for (int s = 0; s < STAGES; s++) {
        if (s < nK) load_stage(s, s);
        CP_COMMIT();
    }

    for (int t = 0; t < nK; t++) {
        const int buf = t % STAGES;
        CP_WAIT2();
        __syncthreads();

        const uint32_t sS = sbase + buf * STAGE4_B;
        const uint32_t sAh = sS;
        const uint32_t sAl = sS + TILE_B;
        const uint32_t sBh = sS + 2 * TILE_B;
        const uint32_t sBl = sS + 3 * TILE_B;

#pragma unroll
        for (int ks = 0; ks < 4; ks++) {
            uint32_t ah[4][4], al[4][4], bh[2][4], bl[2][4];
#pragma unroll
            for (int i = 0; i < 4; i++)
                ldsm4(ah[i], frag_addr(sAh, warpM + i * 16, ks, lid));
#pragma unroll
            for (int j = 0; j < 2; j++)
                ldsm4(bh[j], frag_addr(sBh, warpN + j * 16, ks, lid));
#pragma unroll
            for (int j = 0; j < 2; j++)
                ldsm4(bl[j], frag_addr(sBl, warpN + j * 16, ks, lid));
#pragma unroll
            for (int i = 0; i < 4; i++)
                ldsm4(al[i], frag_addr(sAl, warpM + i * 16, ks, lid));

#pragma unroll
            for (int i = 0; i < 4; i++) {
#pragma unroll
                for (int j = 0; j < 4; j++) {
                    uint32_t bh0 = bh[j >> 1][j & 1], bh1 = bh[j >> 1][(j & 1) + 2];
                    uint32_t bl0 = bl[j >> 1][j & 1], bl1 = bl[j >> 1][(j & 1) + 2];
                    mma_bf16(acc[i][j], ah[i], bh0, bh1);
                    mma_bf16(acc[i][j], ah[i], bl0, bl1);
                    mma_bf16(acc[i][j], al[i], bh0, bh1);
                }
            }
        }
        __syncthreads();

        const int nt = t + STAGES;
        if (nt < nK) load_stage(nt, buf);
        CP_COMMIT();
    }

    const int g = lid >> 2;
    const int tq = lid & 3;
#pragma unroll
    for (int i = 0; i < 4; i++) {
        const long long r0 = rowBase + warpM + i * 16 + g;
        const long long r1 = r0 + 8;
#pragma unroll
        for (int j = 0; j < 4; j++) {
            const int col = colBase + warpN + j * 8 + tq * 2;
            float x0 = acc[i][j][0], x1 = acc[i][j][1];
            float x2 = acc[i][j][2], x3 = acc[i][j][3];
            if (mode == 0) {
                *reinterpret_cast<float2*>(Cf + cOff + r0 * ldc + col) =
                    make_float2(x0 * alpha, x1 * alpha);
                *reinterpret_cast<float2*>(Cf + cOff + r1 * ldc + col) =
                    make_float2(x2 * alpha, x3 * alpha);
            } else if (mode == 1) {
                __nv_bfloat16 h0 = __float2bfloat16(x0);
                __nv_bfloat16 h1 = __float2bfloat16(x1);
                __nv_bfloat16 h2 = __float2bfloat16(x2);
                __nv_bfloat16 h3 = __float2bfloat16(x3);
                __nv_bfloat162 hh01; hh01.x = h0; hh01.y = h1;
                __nv_bfloat162 hh23; hh23.x = h2; hh23.y = h3;
                __nv_bfloat162 ll01, ll23;
                ll01.x = __float2bfloat16(x0 - __bfloat162float(h0));
                ll01.y = __float2bfloat16(x1 - __bfloat162float(h1));
                ll23.x = __float2bfloat16(x2 - __bfloat162float(h2));
                ll23.y = __float2bfloat16(x3 - __bfloat162float(h3));
                *reinterpret_cast<__nv_bfloat162*>(Ch + cOff + r0 * ldc + col) = hh01;
                *reinterpret_cast<__nv_bfloat162*>(Ch + cOff + r1 * ldc + col) = hh23;
                *reinterpret_cast<__nv_bfloat162*>(Cl + cOff + r0 * ldc + col) = ll01;
                *reinterpret_cast<__nv_bfloat162*>(Cl + cOff + r1 * ldc + col) = ll23;
            } else {
                __half2 hh01; hh01.x = __float2half(x0); hh01.y = __float2half(x1);
                __half2 hh23; hh23.x = __float2half(x2); hh23.y = __float2half(x3);
                *reinterpret_cast<__half2*>(Hh + cOff + r0 * ldc + col) = hh01;
                *reinterpret_cast<__half2*>(Hh + cOff + r1 * ldc + col) = hh23;
            }
        }
    }
}

// ---------------------------------------------------------------------------
// Single-phase fp16 GEMM: C = alpha*(A*B^T), A and B plain fp16.
// mode 0: fp32 out (scaled by alpha). mode 1: bf16 hi/lo split out.
// Serves QK^T (mode 0) and PV (mode 1).
// ---------------------------------------------------------------------------
__global__ void __launch_bounds__(256, 1)
gemm_f16(const __half* __restrict__ A, const __half* __restrict__ B,
         float* __restrict__ Cf,
         __nv_bfloat16* __restrict__ Ch, __nv_bfloat16* __restrict__ Cl,
         int K, int lda, int ldb, int ldc, float alpha, int mode,
         long long aSB, long long aSH, long long bSB, long long bSH,
         long long cSB, long long cSH, int H)
{
    extern __shared__ char smem[];
    const uint32_t sbase = smem_u32(smem);
    const int tid = threadIdx.x;
    const int wid = tid >> 5;
    const int lid = tid & 31;

    const int zb = blockIdx.z / H;
    const int zh = blockIdx.z - zb * H;
    const int rowBase = blockIdx.y * BM;
    const int colBase = blockIdx.x * BN;

    const __half* A_ = A + zb * aSB + zh * aSH + (long long)rowBase * lda;
    const __half* B_ = B + zb * bSB + zh * bSH + (long long)colBase * ldb;
    const long long cOff = zb * cSB + zh * cSH;

    const int warpM = (wid >> 2) * 64;
    const int warpN = (wid & 3) * 32;

    float acc[4][4][4];
#pragma unroll
    for (int i = 0; i < 4; i++)
#pragma unroll
        for (int j = 0; j < 4; j++)
#pragma unroll
            for (int v = 0; v < 4; v++) acc[i][j][v] = 0.0f;

    const int nK = K >> 6;

    auto load_stage = [&](int t, int buf) {
        const int k0 = t << 6;
        const uint32_t sS = sbase + buf * STAGE2_B;
        const __half* src[2] = {A_, B_};
        const int lds[2] = {lda, ldb};
#pragma unroll
        for (int tl = 0; tl < 2; tl++) {
            const __half* Q = src[tl];
            const int ld = lds[tl];
            const uint32_t tb = sS + tl * TILE_B;
#pragma unroll
            for (int j = 0; j < 4; j++) {
                int idx = tid + j * 256;
                int row = idx >> 3;
                int c = idx & 7;
                int sw = c ^ (row & 7);
                cp16(tb + row * 128 + sw * 16,
                     Q + (long long)row * ld + k0 + c * 8);
            }
        }
    };

#pragma unroll
    for (int s = 0; s < STAGES; s++) {
        if (s < nK) load_stage(s, s);
        CP_COMMIT();
    }

    for (int t = 0; t < nK; t++) {
        const int buf = t % STAGES;
        CP_WAIT2();
        __syncthreads();

        const uint32_t sS = sbase + buf * STAGE2_B;
        const uint32_t sA = sS;
        const uint32_t sB = sS + TILE_B;

#pragma unroll
        for (int ks = 0; ks < 4; ks++) {
            uint32_t a[4][4], b[2][4];
#pragma unroll
            for (int i = 0; i < 4; i++)
                ldsm4(a[i], frag_addr(sA, warpM + i * 16, ks, lid));
#pragma unroll
            for (int j = 0; j < 2; j++)
                ldsm4(b[j], frag_addr(sB, warpN + j * 16, ks, lid));

#pragma unroll
            for (int i = 0; i < 4; i++) {
#pragma unroll
                for (int j = 0; j < 4; j++) {
                    uint32_t b0 = b[j >> 1][j & 1], b1 = b[j >> 1][(j & 1) + 2];
                    mma_f16(acc[i][j], a[i], b0, b1);
                }
            }
        }
        __syncthreads();

        const int nt = t + STAGES;
        if (nt < nK) load_stage(nt, buf);
        CP_COMMIT();
    }

    const int g = lid >> 2;
    const int tq = lid & 3;
#pragma unroll
    for (int i = 0; i < 4; i++) {
        const long long r0 = rowBase + warpM + i * 16 + g;
        const long long r1 = r0 + 8;
#pragma unroll
        for (int j = 0; j < 4; j++) {
            const int col = colBase + warpN + j * 8 + tq * 2;
            float x0 = acc[i][j][0], x1 = acc[i][j][1];
            float x2 = acc[i][j][2], x3 = acc[i][j][3];
            if (mode == 0) {
                *reinterpret_cast<float2*>(Cf + cOff + r0 * ldc + col) =
                    make_float2(x0 * alpha, x1 * alpha);
                *reinterpret_cast<float2*>(Cf + cOff + r1 * ldc + col) =
                    make_float2(x2 * alpha, x3 * alpha);
            } else {
                __nv_bfloat16 h0 = __float2bfloat16(x0);
                __nv_bfloat16 h1 = __float2bfloat16(x1);
                __nv_bfloat16 h2 = __float2bfloat16(x2);
                __nv_bfloat16 h3 = __float2bfloat16(x3);
                __nv_bfloat162 hh01; hh01.x = h0; hh01.y = h1;
                __nv_bfloat162 hh23; hh23.x = h2; hh23.y = h3;
                __nv_bfloat162 ll01, ll23;
                ll01.x = __float2bfloat16(x0 - __bfloat162float(h0));
                ll01.y = __float2bfloat16(x1 - __bfloat162float(h1));
                ll23.x = __float2bfloat16(x2 - __bfloat162float(h2));
                ll23.y = __float2bfloat16(x3 - __bfloat162float(h3));
                *reinterpret_cast<__nv_bfloat162*>(Ch + cOff + r0 * ldc + col) = hh01;
                *reinterpret_cast<__nv_bfloat162*>(Ch + cOff + r1 * ldc + col) = hh23;
                *reinterpret_cast<__nv_bfloat162*>(Cl + cOff + r0 * ldc + col) = ll01;
                *reinterpret_cast<__nv_bfloat162*>(Cl + cOff + r1 * ldc + col) = ll23;
            }
        }
    }
}

__global__ void __launch_bounds__(256)
split_f32(const float* __restrict__ x, __nv_bfloat16* __restrict__ h,
          __nv_bfloat16* __restrict__ l, long long n4)
{
    long long i = (long long)blockIdx.x * blockDim.x + threadIdx.x;
    if (i >= n4) return;
    float4 v = reinterpret_cast<const float4*>(x)[i];
    __nv_bfloat16 h0 = __float2bfloat16(v.x), h1 = __float2bfloat16(v.y);
    __nv_bfloat16 h2 = __float2bfloat16(v.z), h3 = __float2bfloat16(v.w);
    __nv_bfloat162 a, b;
    a.x = h0; a.y = h1; b.x = h2; b.y = h3;
    reinterpret_cast<__nv_bfloat162*>(h)[2 * i] = a;
    reinterpret_cast<__nv_bfloat162*>(h)[2 * i + 1] = b;
    a.x = __float2bfloat16(v.x - __bfloat162float(h0));
    a.y = __float2bfloat16(v.y - __bfloat162float(h1));
    b.x = __float2bfloat16(v.z - __bfloat162float(h2));
    b.y = __float2bfloat16(v.w - __bfloat162float(h3));
    reinterpret_cast<__nv_bfloat162*>(l)[2 * i] = a;
    reinterpret_cast<__nv_bfloat162*>(l)[2 * i + 1] = b;
}

__global__ void __launch_bounds__(256)
softmax_f16(const float* __restrict__ S, __half* __restrict__ P)
{
    const float* row = S + (long long)blockIdx.x * SEQ;
    __half* p = P + (long long)blockIdx.x * SEQ;
    const int tid = threadIdx.x;

    float v[16];
    float m = -INFINITY;
#pragma unroll
    for (int i = 0; i < 16; i++) {
        v[i] = row[tid + i * 256];
        m = fmaxf(m, v[i]);
    }
    __shared__ float red[256];
    red[tid] = m;
    __syncthreads();
#pragma unroll
    for (int s = 128; s > 0; s >>= 1) {
        if (tid < s) red[tid] = fmaxf(red[tid], red[tid + s]);
        __syncthreads();
    }
    m = red[0];
    __syncthreads();
    float sum = 0.0f;
#pragma unroll
    for (int i = 0; i < 16; i++) {
        v[i] = __expf(v[i] - m);
        sum += v[i];
    }
    red[tid] = sum;
    __syncthreads();
#pragma unroll
    for (int s = 128; s > 0; s >>= 1) {
        if (tid < s) red[tid] += red[tid + s];
        __syncthreads();
    }
    const float inv = 1.0f / red[0];
#pragma unroll
    for (int i = 0; i < 16; i++)
        p[tid + i * 256] = __float2half(v[i] * inv);
}

static void* sym_addr(const void* symbol)
{
    void* p = nullptr;
    cudaGetSymbolAddress(&p, symbol);
    return p;
}

extern "C" void kernel_launch(void* const* d_in, const int* in_sizes, int n_in,
                              void* d_out, int out_size)
{
    const float* X  = (const float*)d_in[0];
    const float* Wq = (const float*)d_in[1];
    const float* Wk = (const float*)d_in[2];
    const float* Wv = (const float*)d_in[3];
    const float* Wo = (const float*)d_in[4];
    float* out = (float*)d_out;

    __nv_bfloat16* Xh  = (__nv_bfloat16*)sym_addr(g_Xh);
    __nv_bfloat16* Xl  = (__nv_bfloat16*)sym_addr(g_Xl);
    __nv_bfloat16* Wqh = (__nv_bfloat16*)sym_addr(g_Wqh);
    __nv_bfloat16* Wql = (__nv_bfloat16*)sym_addr(g_Wql);
    __nv_bfloat16* Wkh = (__nv_bfloat16*)sym_addr(g_Wkh);
    __nv_bfloat16* Wkl = (__nv_bfloat16*)sym_addr(g_Wkl);
    __nv_bfloat16* Wvh = (__nv_bfloat16*)sym_addr(g_Wvh);
    __nv_bfloat16* Wvl = (__nv_bfloat16*)sym_addr(g_Wvl);
    __nv_bfloat16* Woh = (__nv_bfloat16*)sym_addr(g_Woh);
    __nv_bfloat16* Wol = (__nv_bfloat16*)sym_addr(g_Wol);
    __half*        Qf  = (__half*)sym_addr(g_Qf);
    __half*        Kf  = (__half*)sym_addr(g_Kf);
    __half*        Vt  = (__half*)sym_addr(g_Vt);
    float*         S   = (float*)sym_addr(g_S);
    __half*        P   = (__half*)sym_addr(g_P);
    __nv_bfloat16* Mh  = (__nv_bfloat16*)sym_addr(g_Mh);
    __nv_bfloat16* Ml  = (__nv_bfloat16*)sym_addr(g_Ml);

    cudaFuncSetAttribute(gemm_bf16x3, cudaFuncAttributeMaxDynamicSharedMemorySize,
                         GEMM_SMEM);
    cudaFuncSetAttribute(gemm_f16, cudaFuncAttributeMaxDynamicSharedMemorySize,
                         F16_SMEM);

    {
        long long n4;
        n4 = (long long)MS * DMODEL / 4;
        split_f32<<<(unsigned)((n4 + 255) / 256), 256>>>(X, Xh, Xl, n4);
        n4 = (long long)DMODEL * DMODEL / 4;
        split_f32<<<(unsigned)((n4 + 255) / 256), 256>>>(Wq, Wqh, Wql, n4);
        split_f32<<<(unsigned)((n4 + 255) / 256), 256>>>(Wo, Woh, Wol, n4);
        n4 = (long long)DK * DMODEL / 4;
        split_f32<<<(unsigned)((n4 + 255) / 256), 256>>>(Wk, Wkh, Wkl, n4);
        split_f32<<<(unsigned)((n4 + 255) / 256), 256>>>(Wv, Wvh, Wvl, n4);
    }

    // Q = X @ Wq^T -> fp16 single [8192 x 1024]
    gemm_bf16x3<<<dim3(DMODEL / BN, MS / BM, 1), 256, GEMM_SMEM>>>(
        Xh, Xl, Wqh, Wql, nullptr, nullptr, nullptr, Qf,
        DMODEL, DMODEL, DMODEL, DMODEL, 1.0f, 2,
        0, 0, 0, 0, 0, 0, 1);

    // Kc = X @ Wk^T -> fp16 single [8192 x 256]
    gemm_bf16x3<<<dim3(DK / BN, MS / BM, 1), 256, GEMM_SMEM>>>(
        Xh, Xl, Wkh, Wkl, nullptr, nullptr, nullptr, Kf,
        DMODEL, DMODEL, DMODEL, DK, 1.0f, 2,
        0, 0, 0, 0, 0, 0, 1);

    // VcT[b] = Wv @ X[b]^T -> fp16 single [256 x 4096] per batch
    gemm_bf16x3<<<dim3(SEQ / BN, DK / BM, BATCH), 256, GEMM_SMEM>>>(
        Wvh, Wvl, Xh, Xl, nullptr, nullptr, nullptr, Vt,
        DMODEL, DMODEL, DMODEL, SEQ, 1.0f, 2,
        0, 0, (long long)SEQ * DMODEL, 0, (long long)DK * SEQ, 0, 1);

    // S[b,h] = SCALE * Q[b,h] @ Kc[b]^T -> fp32 (1-phase fp16)
    gemm_f16<<<dim3(SEQ / BN, SEQ / BM, BATCH * NHEAD), 256, F16_SMEM>>>(
        Qf, Kf, S, nullptr, nullptr,
        DK, DMODEL, DK, SEQ, SCALE_F, 0,
        (long long)SEQ * DMODEL, DK,
        (long long)SEQ * DK, 0,
        (long long)NHEAD * SEQ * SEQ, (long long)SEQ * SEQ, NHEAD);

    // softmax -> fp16 P
    softmax_f16<<<BATCH * NHEAD * SEQ, 256>>>(S, P);

    // merged = P @ VcT^T -> bf16 split (1-phase fp16)
    gemm_f16<<<dim3(DK / BN, SEQ / BM, BATCH * NHEAD), 256, F16_SMEM>>>(
        P, Vt, nullptr, Mh, Ml,
        SEQ, SEQ, SEQ, DMODEL, 1.0f, 1,
        (long long)NHEAD * SEQ * SEQ, (long long)SEQ * SEQ,
        (long long)DK * SEQ, 0,
        (long long)SEQ * DMODEL, DK, NHEAD);

    // out = merged @ Wo^T -> fp32 (3-phase bf16)
    gemm_bf16x3<<<dim3(DMODEL / BN, MS / BM, 1), 256, GEMM_SMEM>>>(
        Mh, Ml, Woh, Wol, out, nullptr, nullptr, nullptr,
        DMODEL, DMODEL, DMODEL, DMODEL, 1.0f, 0,
        0, 0, 0, 0, 0, 0, 1);
}

// round 7
// speedup vs baseline: 5.1751x; 1.2166x over previous
#include <cuda_runtime.h>
#include <cuda_fp16.h>
#include <cstdint>
#include <math.h>

#define BATCH 2
#define SEQ   4096
#define DMODEL 1024
#define NHEAD 4
#define DK    256
#define MS (BATCH * SEQ)
#define SCALE_F (1.0f / 16.0f)

#define BM 128
#define BN 128
#define STAGES 3
#define TILE_B 16384
#define STAGE4_B (4 * TILE_B)
#define G2_SMEM (STAGES * STAGE4_B)
#define STAGE2_B (2 * TILE_B)
#define G1_SMEM (STAGES * STAGE2_B)

// ---------------------------------------------------------------------------
// Device scratch (all fp16)
// ---------------------------------------------------------------------------
__device__ __align__(256) __half g_Xh[(size_t)MS * DMODEL];
__device__ __align__(256) __half g_Xl[(size_t)MS * DMODEL];
__device__ __align__(256) __half g_Wq[(size_t)DMODEL * DMODEL];
__device__ __align__(256) __half g_Wk[(size_t)DK * DMODEL];
__device__ __align__(256) __half g_Wv[(size_t)DK * DMODEL];
__device__ __align__(256) __half g_Woh[(size_t)DMODEL * DMODEL];
__device__ __align__(256) __half g_Wol[(size_t)DMODEL * DMODEL];
__device__ __align__(256) __half g_Qf[(size_t)MS * DMODEL];
__device__ __align__(256) __half g_Kf[(size_t)MS * DK];
__device__ __align__(256) __half g_Vt[(size_t)BATCH * DK * SEQ];
__device__ __align__(256) __half g_S[(size_t)BATCH * NHEAD * SEQ * SEQ];
__device__ __align__(256) __half g_M[(size_t)MS * DMODEL];

// ---------------------------------------------------------------------------
// PTX helpers
// ---------------------------------------------------------------------------
__device__ __forceinline__ uint32_t smem_u32(const void* p) {
    uint32_t a;
    asm("{ .reg .u64 t; cvta.to.shared.u64 t, %1; cvt.u32.u64 %0, t; }"
        : "=r"(a) : "l"(p));
    return a;
}
__device__ __forceinline__ void cp16(uint32_t s, const void* g) {
    asm volatile("cp.async.cg.shared.global [%0], [%1], 16;" :: "r"(s), "l"(g));
}
#define CP_COMMIT() asm volatile("cp.async.commit_group;" ::: "memory")
#define CP_WAIT2()  asm volatile("cp.async.wait_group 2;" ::: "memory")

__device__ __forceinline__ void ldsm4(uint32_t* r, uint32_t addr) {
    asm volatile("ldmatrix.sync.aligned.m8n8.x4.shared.b16 {%0,%1,%2,%3}, [%4];"
                 : "=r"(r[0]), "=r"(r[1]), "=r"(r[2]), "=r"(r[3]) : "r"(addr));
}
__device__ __forceinline__ void mma_f16(float* c, const uint32_t* a,
                                        uint32_t b0, uint32_t b1) {
    asm volatile(
        "mma.sync.aligned.m16n8k16.row.col.f32.f16.f16.f32 "
        "{%0,%1,%2,%3}, {%4,%5,%6,%7}, {%8,%9}, {%0,%1,%2,%3};\n"
        : "+f"(c[0]), "+f"(c[1]), "+f"(c[2]), "+f"(c[3])
        : "r"(a[0]), "r"(a[1]), "r"(a[2]), "r"(a[3]), "r"(b0), "r"(b1));
}
__device__ __forceinline__ uint32_t frag_addr(uint32_t tbase, int rowBase,
                                              int ks, int lane) {
    int row = rowBase + (lane & 15);
    int chunk = ks * 2 + (lane >> 4);
    int sw = chunk ^ (row & 7);
    return tbase + row * 128 + sw * 16;
}

// ---------------------------------------------------------------------------
// 2-phase fp16 GEMM: C = alpha * (A0*B0^T + A1*B1^T).
// dupA: A1 aliases A0 (loaded once); dupB: B1 aliases B0.
// mode 0: fp32 out. mode 2: fp16 out. Batched over blockIdx.z = b*H + h.
// ---------------------------------------------------------------------------
__global__ void __launch_bounds__(256, 1)
gemm_2ph(const __half* __restrict__ A0, const __half* __restrict__ A1,
         const __half* __restrict__ B0, const __half* __restrict__ B1,
         float* __restrict__ Cf, __half* __restrict__ Hf,
         int K, int lda, int ldb, int ldc, float alpha, int mode,
         int dupA, int dupB,
         long long aSB, long long bSB, long long cSB, int H)
{
    extern __shared__ char smem[];
    const uint32_t sbase = smem_u32(smem);
    const int tid = threadIdx.x;
    const int wid = tid >> 5;
    const int lid = tid & 31;

    const int zb = blockIdx.z / H;
    const int rowBase = blockIdx.y * BM;
    const int colBase = blockIdx.x * BN;

    const __half* A0_ = A0 + zb * aSB + (long long)rowBase * lda;
    const __half* A1_ = A1 + zb * aSB + (long long)rowBase * lda;
    const __half* B0_ = B0 + zb * bSB + (long long)colBase * ldb;
    const __half* B1_ = B1 + zb * bSB + (long long)colBase * ldb;
    const long long cOff = zb * cSB;

    const int warpM = (wid >> 2) * 64;
    const int warpN = (wid & 3) * 32;

    float acc[4][4][4];
#pragma unroll
    for (int i = 0; i < 4; i++)
#pragma unroll
        for (int j = 0; j < 4; j++)
#pragma unroll
            for (int v = 0; v < 4; v++) acc[i][j][v] = 0.0f;

    const int nK = K >> 6;

    auto load_tile = [&](const __half* P, int ld, uint32_t tb, int k0) {
#pragma unroll
        for (int j = 0; j < 4; j++) {
            int idx = tid + j * 256;
            int row = idx >> 3;
            int c = idx & 7;
            int sw = c ^ (row & 7);
            cp16(tb + row * 128 + sw * 16, P + (long long)row * ld + k0 + c * 8);
        }
    };
    auto load_stage = [&](int t, int buf) {
        const int k0 = t << 6;
        const uint32_t sS = sbase + buf * STAGE4_B;
        load_tile(A0_, lda, sS, k0);
        if (!dupA) load_tile(A1_, lda, sS + TILE_B, k0);
        load_tile(B0_, ldb, sS + 2 * TILE_B, k0);
        if (!dupB) load_tile(B1_, ldb, sS + 3 * TILE_B, k0);
    };

#pragma unroll
    for (int s = 0; s < STAGES; s++) {
        if (s < nK) load_stage(s, s);
        CP_COMMIT();
    }

    for (int t = 0; t < nK; t++) {
        const int buf = t % STAGES;
        CP_WAIT2();
        __syncthreads();

        const uint32_t sS = sbase + buf * STAGE4_B;
        const uint32_t sA0 = sS;
        const uint32_t sA1 = dupA ? sS : sS + TILE_B;
        const uint32_t sB0 = sS + 2 * TILE_B;
        const uint32_t sB1 = dupB ? sB0 : sS + 3 * TILE_B;

#pragma unroll
        for (int ks = 0; ks < 4; ks++) {
            uint32_t a0[4][4], a1[4][4], b0[2][4], b1[2][4];
#pragma unroll
            for (int i = 0; i < 4; i++)
                ldsm4(a0[i], frag_addr(sA0, warpM + i * 16, ks, lid));
#pragma unroll
            for (int j = 0; j < 2; j++)
                ldsm4(b0[j], frag_addr(sB0, warpN + j * 16, ks, lid));
#pragma unroll
            for (int i = 0; i < 4; i++)
                ldsm4(a1[i], frag_addr(sA1, warpM + i * 16, ks, lid));
#pragma unroll
            for (int j = 0; j < 2; j++)
                ldsm4(b1[j], frag_addr(sB1, warpN + j * 16, ks, lid));

#pragma unroll
            for (int i = 0; i < 4; i++) {
#pragma unroll
                for (int j = 0; j < 4; j++) {
                    mma_f16(acc[i][j], a0[i],
                            b0[j >> 1][j & 1], b0[j >> 1][(j & 1) + 2]);
                    mma_f16(acc[i][j], a1[i],
                            b1[j >> 1][j & 1], b1[j >> 1][(j & 1) + 2]);
                }
            }
        }
        __syncthreads();

        const int nt = t + STAGES;
        if (nt < nK) load_stage(nt, buf);
        CP_COMMIT();
    }

    const int g = lid >> 2;
    const int tq = lid & 3;
#pragma unroll
    for (int i = 0; i < 4; i++) {
        const long long r0 = rowBase + warpM + i * 16 + g;
        const long long r1 = r0 + 8;
#pragma unroll
        for (int j = 0; j < 4; j++) {
            const int col = colBase + warpN + j * 8 + tq * 2;
            float x0 = acc[i][j][0] * alpha, x1 = acc[i][j][1] * alpha;
            float x2 = acc[i][j][2] * alpha, x3 = acc[i][j][3] * alpha;
            if (mode == 0) {
                *reinterpret_cast<float2*>(Cf + cOff + r0 * ldc + col) =
                    make_float2(x0, x1);
                *reinterpret_cast<float2*>(Cf + cOff + r1 * ldc + col) =
                    make_float2(x2, x3);
            } else {
                *reinterpret_cast<__half2*>(Hf + cOff + r0 * ldc + col) =
                    __floats2half2_rn(x0, x1);
                *reinterpret_cast<__half2*>(Hf + cOff + r1 * ldc + col) =
                    __floats2half2_rn(x2, x3);
            }
        }
    }
}

// ---------------------------------------------------------------------------
// 1-phase fp16 GEMM: C = alpha*(A*B^T). mode 2: fp16 out.
// 96KB smem -> 2 CTAs/SM for latency hiding (QK has only K=256).
// ---------------------------------------------------------------------------
__global__ void __launch_bounds__(256, 2)
gemm_f16(const __half* __restrict__ A, const __half* __restrict__ B,
         __half* __restrict__ Hf,
         int K, int lda, int ldb, int ldc, float alpha,
         long long aSB, long long aSH, long long bSB, long long bSH,
         long long cSB, long long cSH, int H)
{
    extern __shared__ char smem[];
    const uint32_t sbase = smem_u32(smem);
    const int tid = threadIdx.x;
    const int wid = tid >> 5;
    const int lid = tid & 31;

    const int zb = blockIdx.z / H;
    const int zh = blockIdx.z - zb * H;
    const int rowBase = blockIdx.y * BM;
    const int colBase = blockIdx.x * BN;

    const __half* A_ = A + zb * aSB + zh * aSH + (long long)rowBase * lda;
    const __half* B_ = B + zb * bSB + zh * bSH + (long long)colBase * ldb;
    const long long cOff = zb * cSB + zh * cSH;

    const int warpM = (wid >> 2) * 64;
    const int warpN = (wid & 3) * 32;

    float acc[4][4][4];
#pragma unroll
    for (int i = 0; i < 4; i++)
#pragma unroll
        for (int j = 0; j < 4; j++)
#pragma unroll
            for (int v = 0; v < 4; v++) acc[i][j][v] = 0.0f;

    const int nK = K >> 6;

    auto load_stage = [&](int t, int buf) {
        const int k0 = t << 6;
        const uint32_t sS = sbase + buf * STAGE2_B;
        const __half* src[2] = {A_, B_};
        const int lds[2] = {lda, ldb};
#pragma unroll
        for (int tl = 0; tl < 2; tl++) {
            const __half* Q = src[tl];
            const int ld = lds[tl];
            const uint32_t tb = sS + tl * TILE_B;
#pragma unroll
            for (int j = 0; j < 4; j++) {
                int idx = tid + j * 256;
                int row = idx >> 3;
                int c = idx & 7;
                int sw = c ^ (row & 7);
                cp16(tb + row * 128 + sw * 16,
                     Q + (long long)row * ld + k0 + c * 8);
            }
        }
    };

#pragma unroll
    for (int s = 0; s < STAGES; s++) {
        if (s < nK) load_stage(s, s);
        CP_COMMIT();
    }

    for (int t = 0; t < nK; t++) {
        const int buf = t % STAGES;
        CP_WAIT2();
        __syncthreads();

        const uint32_t sS = sbase + buf * STAGE2_B;
        const uint32_t sA = sS;
        const uint32_t sB = sS + TILE_B;

#pragma unroll
        for (int ks = 0; ks < 4; ks++) {
            uint32_t a[4][4], b[2][4];
#pragma unroll
            for (int i = 0; i < 4; i++)
                ldsm4(a[i], frag_addr(sA, warpM + i * 16, ks, lid));
#pragma unroll
            for (int j = 0; j < 2; j++)
                ldsm4(b[j], frag_addr(sB, warpN + j * 16, ks, lid));

#pragma unroll
            for (int i = 0; i < 4; i++) {
#pragma unroll
                for (int j = 0; j < 4; j++) {
                    mma_f16(acc[i][j], a[i],
                            b[j >> 1][j & 1], b[j >> 1][(j & 1) + 2]);
                }
            }
        }
        __syncthreads();

        const int nt = t + STAGES;
        if (nt < nK) load_stage(nt, buf);
        CP_COMMIT();
    }

    const int g = lid >> 2;
    const int tq = lid & 3;
#pragma unroll
    for (int i = 0; i < 4; i++) {
        const long long r0 = rowBase + warpM + i * 16 + g;
        const long long r1 = r0 + 8;
#pragma unroll
        for (int j = 0; j < 4; j++) {
            const int col = colBase + warpN + j * 8 + tq * 2;
            *reinterpret_cast<__half2*>(Hf + cOff + r0 * ldc + col) =
                __floats2half2_rn(acc[i][j][0] * alpha, acc[i][j][1] * alpha);
            *reinterpret_cast<__half2*>(Hf + cOff + r1 * ldc + col) =
                __floats2half2_rn(acc[i][j][2] * alpha, acc[i][j][3] * alpha);
        }
    }
}

// ---------------------------------------------------------------------------
// fp32 -> fp16 hi/lo split (X, Wo)
// ---------------------------------------------------------------------------
__global__ void __launch_bounds__(256)
split2_f16(const float* __restrict__ x, __half* __restrict__ h,
           __half* __restrict__ l, long long n4)
{
    long long i = (long long)blockIdx.x * blockDim.x + threadIdx.x;
    if (i >= n4) return;
    float4 v = reinterpret_cast<const float4*>(x)[i];
    __half h0 = __float2half(v.x), h1 = __float2half(v.y);
    __half h2 = __float2half(v.z), h3 = __float2half(v.w);
    __half2 a, b;
    a.x = h0; a.y = h1; b.x = h2; b.y = h3;
    reinterpret_cast<__half2*>(h)[2 * i] = a;
    reinterpret_cast<__half2*>(h)[2 * i + 1] = b;
    a.x = __float2half(v.x - __half2float(h0));
    a.y = __float2half(v.y - __half2float(h1));
    b.x = __float2half(v.z - __half2float(h2));
    b.y = __float2half(v.w - __half2float(h3));
    reinterpret_cast<__half2*>(l)[2 * i] = a;
    reinterpret_cast<__half2*>(l)[2 * i + 1] = b;
}

// fp32 -> fp16 single (Wq, Wk, Wv)
__global__ void __launch_bounds__(256)
split1_f16(const float* __restrict__ x, __half* __restrict__ h, long long n4)
{
    long long i = (long long)blockIdx.x * blockDim.x + threadIdx.x;
    if (i >= n4) return;
    float4 v = reinterpret_cast<const float4*>(x)[i];
    __half2 a, b;
    a.x = __float2half(v.x); a.y = __float2half(v.y);
    b.x = __float2half(v.z); b.y = __float2half(v.w);
    reinterpret_cast<__half2*>(h)[2 * i] = a;
    reinterpret_cast<__half2*>(h)[2 * i + 1] = b;
}

// ---------------------------------------------------------------------------
// In-place row softmax on fp16 S (rows of 4096)
// ---------------------------------------------------------------------------
__global__ void __launch_bounds__(256)
softmax_inplace(__half* __restrict__ S)
{
    __half* row = S + (long long)blockIdx.x * SEQ;
    const int tid = threadIdx.x;

    float v[16];
    float m = -INFINITY;
#pragma unroll
    for (int i = 0; i < 16; i++) {
        v[i] = __half2float(row[tid + i * 256]);
        m = fmaxf(m, v[i]);
    }
    __shared__ float red[256];
    red[tid] = m;
    __syncthreads();
#pragma unroll
    for (int s = 128; s > 0; s >>= 1) {
        if (tid < s) red[tid] = fmaxf(red[tid], red[tid + s]);
        __syncthreads();
    }
    m = red[0];
    __syncthreads();
    float sum = 0.0f;
#pragma unroll
    for (int i = 0; i < 16; i++) {
        v[i] = __expf(v[i] - m);
        sum += v[i];
    }
    red[tid] = sum;
    __syncthreads();
#pragma unroll
    for (int s = 128; s > 0; s >>= 1) {
        if (tid < s) red[tid] += red[tid + s];
        __syncthreads();
    }
    const float inv = 1.0f / red[0];
#pragma unroll
    for (int i = 0; i < 16; i++)
        row[tid + i * 256] = __float2half(v[i] * inv);
}

static void* sym_addr(const void* symbol)
{
    void* p = nullptr;
    cudaGetSymbolAddress(&p, symbol);
    return p;
}

extern "C" void kernel_launch(void* const* d_in, const int* in_sizes, int n_in,
                              void* d_out, int out_size)
{
    const float* X  = (const float*)d_in[0];
    const float* Wq = (const float*)d_in[1];
    const float* Wk = (const float*)d_in[2];
    const float* Wv = (const float*)d_in[3];
    const float* Wo = (const float*)d_in[4];
    float* out = (float*)d_out;

    __half* Xh  = (__half*)sym_addr(g_Xh);
    __half* Xl  = (__half*)sym_addr(g_Xl);
    __half* Wqf = (__half*)sym_addr(g_Wq);
    __half* Wkf = (__half*)sym_addr(g_Wk);
    __half* Wvf = (__half*)sym_addr(g_Wv);
    __half* Woh = (__half*)sym_addr(g_Woh);
    __half* Wol = (__half*)sym_addr(g_Wol);
    __half* Qf  = (__half*)sym_addr(g_Qf);
    __half* Kf  = (__half*)sym_addr(g_Kf);
    __half* Vt  = (__half*)sym_addr(g_Vt);
    __half* S   = (__half*)sym_addr(g_S);
    __half* M   = (__half*)sym_addr(g_M);

    cudaFuncSetAttribute(gemm_2ph, cudaFuncAttributeMaxDynamicSharedMemorySize,
                         G2_SMEM);
    cudaFuncSetAttribute(gemm_f16, cudaFuncAttributeMaxDynamicSharedMemorySize,
                         G1_SMEM);

    {
        long long n4;
        n4 = (long long)MS * DMODEL / 4;
        split2_f16<<<(unsigned)((n4 + 255) / 256), 256>>>(X, Xh, Xl, n4);
        n4 = (long long)DMODEL * DMODEL / 4;
        split1_f16<<<(unsigned)((n4 + 255) / 256), 256>>>(Wq, Wqf, n4);
        split2_f16<<<(unsigned)((n4 + 255) / 256), 256>>>(Wo, Woh, Wol, n4);
        n4 = (long long)DK * DMODEL / 4;
        split1_f16<<<(unsigned)((n4 + 255) / 256), 256>>>(Wk, Wkf, n4);
        split1_f16<<<(unsigned)((n4 + 255) / 256), 256>>>(Wv, Wvf, n4);
    }

    // Q = (Xh + Xl) @ Wq^T -> fp16  [8192 x 1024]
    gemm_2ph<<<dim3(DMODEL / BN, MS / BM, 1), 256, G2_SMEM>>>(
        Xh, Xl, Wqf, Wqf, nullptr, Qf,
        DMODEL, DMODEL, DMODEL, DMODEL, 1.0f, 2, 0, 1,
        0, 0, 0, 1);

    // Kc = (Xh + Xl) @ Wk^T -> fp16  [8192 x 256]
    gemm_2ph<<<dim3(DK / BN, MS / BM, 1), 256, G2_SMEM>>>(
        Xh, Xl, Wkf, Wkf, nullptr, Kf,
        DMODEL, DMODEL, DMODEL, DK, 1.0f, 2, 0, 1,
        0, 0, 0, 1);

    // VcT[b] = Wv @ (Xh + Xl)[b]^T -> fp16  [256 x 4096] per batch
    gemm_2ph<<<dim3(SEQ / BN, DK / BM, BATCH), 256, G2_SMEM>>>(
        Wvf, Wvf, Xh, Xl, nullptr, Vt,
        DMODEL, DMODEL, DMODEL, SEQ, 1.0f, 2, 1, 0,
        0, (long long)SEQ * DMODEL, (long long)DK * SEQ, 1);

    // S[b,h] = SCALE * Q[b,h] @ Kc[b]^T -> fp16
    gemm_f16<<<dim3(SEQ / BN, SEQ / BM, BATCH * NHEAD), 256, G1_SMEM>>>(
        Qf, Kf, S,
        DK, DMODEL, DK, SEQ, SCALE_F,
        (long long)SEQ * DMODEL, DK,
        (long long)SEQ * DK, 0,
        (long long)NHEAD * SEQ * SEQ, (long long)SEQ * SEQ, NHEAD);

    // softmax in place on S
    softmax_inplace<<<BATCH * NHEAD * SEQ, 256>>>(S);

    // M = P @ VcT^T -> fp16 merged [8192 x 1024]
    gemm_f16<<<dim3(DK / BN, SEQ / BM, BATCH * NHEAD), 256, G1_SMEM>>>(
        S, Vt, M,
        SEQ, SEQ, SEQ, DMODEL, 1.0f,
        (long long)NHEAD * SEQ * SEQ, (long long)SEQ * SEQ,
        (long long)DK * SEQ, 0,
        (long long)SEQ * DMODEL, DK, NHEAD);

    // out = M @ (Woh + Wol)^T -> fp32
    gemm_2ph<<<dim3(DMODEL / BN, MS / BM, 1), 256, G2_SMEM>>>(
        M, M, Woh, Wol, out, nullptr,
        DMODEL, DMODEL, DMODEL, DMODEL, 1.0f, 0, 1, 0,
        0, 0, 0, 1);
}

// round 8
// speedup vs baseline: 5.8493x; 1.1303x over previous
#include <cuda_runtime.h>
#include <cuda_fp16.h>
#include <cstdint>
#include <math.h>

#define BATCH 2
#define SEQ   4096
#define DMODEL 1024
#define NHEAD 4
#define DK    256
#define MS (BATCH * SEQ)
#define SCALE_F (1.0f / 16.0f)

#define BM 128
#define BN 128
#define STAGES 3
#define TILE_B 16384
#define STAGE4_B (4 * TILE_B)
#define G2_SMEM (STAGES * STAGE4_B)
#define STAGE2_B (2 * TILE_B)
#define G1_SMEM (STAGES * STAGE2_B)

// ---------------------------------------------------------------------------
// Device scratch (all fp16) + fp32 row sums
// ---------------------------------------------------------------------------
__device__ __align__(256) __half g_Xh[(size_t)MS * DMODEL];
__device__ __align__(256) __half g_Xl[(size_t)MS * DMODEL];
__device__ __align__(256) __half g_Wq[(size_t)DMODEL * DMODEL];
__device__ __align__(256) __half g_Wk[(size_t)DK * DMODEL];
__device__ __align__(256) __half g_Wv[(size_t)DK * DMODEL];
__device__ __align__(256) __half g_Woh[(size_t)DMODEL * DMODEL];
__device__ __align__(256) __half g_Wol[(size_t)DMODEL * DMODEL];
__device__ __align__(256) __half g_Qf[(size_t)MS * DMODEL];
__device__ __align__(256) __half g_Kf[(size_t)MS * DK];
__device__ __align__(256) __half g_Vt[(size_t)BATCH * DK * SEQ];
__device__ __align__(256) __half g_S[(size_t)BATCH * NHEAD * SEQ * SEQ];
__device__ __align__(256) __half g_M[(size_t)MS * DMODEL];
__device__ __align__(256) float  g_rowsum[(size_t)BATCH * NHEAD * SEQ];

// ---------------------------------------------------------------------------
// PTX helpers
// ---------------------------------------------------------------------------
__device__ __forceinline__ uint32_t smem_u32(const void* p) {
    uint32_t a;
    asm("{ .reg .u64 t; cvta.to.shared.u64 t, %1; cvt.u32.u64 %0, t; }"
        : "=r"(a) : "l"(p));
    return a;
}
__device__ __forceinline__ void cp16(uint32_t s, const void* g) {
    asm volatile("cp.async.cg.shared.global [%0], [%1], 16;" :: "r"(s), "l"(g));
}
#define CP_COMMIT() asm volatile("cp.async.commit_group;" ::: "memory")
#define CP_WAIT2()  asm volatile("cp.async.wait_group 2;" ::: "memory")

__device__ __forceinline__ void ldsm4(uint32_t* r, uint32_t addr) {
    asm volatile("ldmatrix.sync.aligned.m8n8.x4.shared.b16 {%0,%1,%2,%3}, [%4];"
                 : "=r"(r[0]), "=r"(r[1]), "=r"(r[2]), "=r"(r[3]) : "r"(addr));
}
__device__ __forceinline__ void mma_f16(float* c, const uint32_t* a,
                                        uint32_t b0, uint32_t b1) {
    asm volatile(
        "mma.sync.aligned.m16n8k16.row.col.f32.f16.f16.f32 "
        "{%0,%1,%2,%3}, {%4,%5,%6,%7}, {%8,%9}, {%0,%1,%2,%3};\n"
        : "+f"(c[0]), "+f"(c[1]), "+f"(c[2]), "+f"(c[3])
        : "r"(a[0]), "r"(a[1]), "r"(a[2]), "r"(a[3]), "r"(b0), "r"(b1));
}
__device__ __forceinline__ uint32_t frag_addr(uint32_t tbase, int rowBase,
                                              int ks, int lane) {
    int row = rowBase + (lane & 15);
    int chunk = ks * 2 + (lane >> 4);
    int sw = chunk ^ (row & 7);
    return tbase + row * 128 + sw * 16;
}

// ---------------------------------------------------------------------------
// 2-phase fp16 GEMM: C = alpha * (A0*B0^T + A1*B1^T). (projections / O-proj)
// dupA: A1 aliases A0; dupB: B1 aliases B0.
// mode 0: fp32 out. mode 2: fp16 out.
// ---------------------------------------------------------------------------
__global__ void __launch_bounds__(256, 1)
gemm_2ph(const __half* __restrict__ A0, const __half* __restrict__ A1,
         const __half* __restrict__ B0, const __half* __restrict__ B1,
         float* __restrict__ Cf, __half* __restrict__ Hf,
         int K, int lda, int ldb, int ldc, float alpha, int mode,
         int dupA, int dupB,
         long long aSB, long long bSB, long long cSB, int H)
{
    extern __shared__ char smem[];
    const uint32_t sbase = smem_u32(smem);
    const int tid = threadIdx.x;
    const int wid = tid >> 5;
    const int lid = tid & 31;

    const int zb = blockIdx.z / H;
    const int rowBase = blockIdx.y * BM;
    const int colBase = blockIdx.x * BN;

    const __half* A0_ = A0 + zb * aSB + (long long)rowBase * lda;
    const __half* A1_ = A1 + zb * aSB + (long long)rowBase * lda;
    const __half* B0_ = B0 + zb * bSB + (long long)colBase * ldb;
    const __half* B1_ = B1 + zb * bSB + (long long)colBase * ldb;
    const long long cOff = zb * cSB;

    const int warpM = (wid >> 2) * 64;
    const int warpN = (wid & 3) * 32;

    float acc[4][4][4];
#pragma unroll
    for (int i = 0; i < 4; i++)
#pragma unroll
        for (int j = 0; j < 4; j++)
#pragma unroll
            for (int v = 0; v < 4; v++) acc[i][j][v] = 0.0f;

    const int nK = K >> 6;

    auto load_tile = [&](const __half* P, int ld, uint32_t tb, int k0) {
#pragma unroll
        for (int j = 0; j < 4; j++) {
            int idx = tid + j * 256;
            int row = idx >> 3;
            int c = idx & 7;
            int sw = c ^ (row & 7);
            cp16(tb + row * 128 + sw * 16, P + (long long)row * ld + k0 + c * 8);
        }
    };
    auto load_stage = [&](int t, int buf) {
        const int k0 = t << 6;
        const uint32_t sS = sbase + buf * STAGE4_B;
        load_tile(A0_, lda, sS, k0);
        if (!dupA) load_tile(A1_, lda, sS + TILE_B, k0);
        load_tile(B0_, ldb, sS + 2 * TILE_B, k0);
        if (!dupB) load_tile(B1_, ldb, sS + 3 * TILE_B, k0);
    };

#pragma unroll
    for (int s = 0; s < STAGES; s++) {
        if (s < nK) load_stage(s, s);
        CP_COMMIT();
    }

    for (int t = 0; t < nK; t++) {
        const int buf = t % STAGES;
        CP_WAIT2();
        __syncthreads();

        const uint32_t sS = sbase + buf * STAGE4_B;
        const uint32_t sA0 = sS;
        const uint32_t sA1 = dupA ? sS : sS + TILE_B;
        const uint32_t sB0 = sS + 2 * TILE_B;
        const uint32_t sB1 = dupB ? sB0 : sS + 3 * TILE_B;

#pragma unroll
        for (int ks = 0; ks < 4; ks++) {
            uint32_t a0[4][4], a1[4][4], b0[2][4], b1[2][4];
#pragma unroll
            for (int i = 0; i < 4; i++)
                ldsm4(a0[i], frag_addr(sA0, warpM + i * 16, ks, lid));
#pragma unroll
            for (int j = 0; j < 2; j++)
                ldsm4(b0[j], frag_addr(sB0, warpN + j * 16, ks, lid));
#pragma unroll
            for (int i = 0; i < 4; i++)
                ldsm4(a1[i], frag_addr(sA1, warpM + i * 16, ks, lid));
#pragma unroll
            for (int j = 0; j < 2; j++)
                ldsm4(b1[j], frag_addr(sB1, warpN + j * 16, ks, lid));

#pragma unroll
            for (int i = 0; i < 4; i++) {
#pragma unroll
                for (int j = 0; j < 4; j++) {
                    mma_f16(acc[i][j], a0[i],
                            b0[j >> 1][j & 1], b0[j >> 1][(j & 1) + 2]);
                    mma_f16(acc[i][j], a1[i],
                            b1[j >> 1][j & 1], b1[j >> 1][(j & 1) + 2]);
                }
            }
        }
        __syncthreads();

        const int nt = t + STAGES;
        if (nt < nK) load_stage(nt, buf);
        CP_COMMIT();
    }

    const int g = lid >> 2;
    const int tq = lid & 3;
#pragma unroll
    for (int i = 0; i < 4; i++) {
        const long long r0 = rowBase + warpM + i * 16 + g;
        const long long r1 = r0 + 8;
#pragma unroll
        for (int j = 0; j < 4; j++) {
            const int col = colBase + warpN + j * 8 + tq * 2;
            float x0 = acc[i][j][0] * alpha, x1 = acc[i][j][1] * alpha;
            float x2 = acc[i][j][2] * alpha, x3 = acc[i][j][3] * alpha;
            if (mode == 0) {
                *reinterpret_cast<float2*>(Cf + cOff + r0 * ldc + col) =
                    make_float2(x0, x1);
                *reinterpret_cast<float2*>(Cf + cOff + r1 * ldc + col) =
                    make_float2(x2, x3);
            } else {
                *reinterpret_cast<__half2*>(Hf + cOff + r0 * ldc + col) =
                    __floats2half2_rn(x0, x1);
                *reinterpret_cast<__half2*>(Hf + cOff + r1 * ldc + col) =
                    __floats2half2_rn(x2, x3);
            }
        }
    }
}

// ---------------------------------------------------------------------------
// 1-phase fp16 GEMM with fused softmax pieces.
// fuse 0: fp16 out = alpha*acc.
// fuse 1 (QK): out = exp(alpha*acc) fp16, atomicAdd per-row sums to rowsum.
// fuse 2 (PV): out = acc / rowsum[row] fp16.
// ---------------------------------------------------------------------------
__global__ void __launch_bounds__(256, 2)
gemm_f16(const __half* __restrict__ A, const __half* __restrict__ B,
         __half* __restrict__ Hf, float* __restrict__ rowsum, int fuse,
         int K, int lda, int ldb, int ldc, float alpha,
         long long aSB, long long aSH, long long bSB, long long bSH,
         long long cSB, long long cSH, int H)
{
    extern __shared__ char smem[];
    const uint32_t sbase = smem_u32(smem);
    const int tid = threadIdx.x;
    const int wid = tid >> 5;
    const int lid = tid & 31;

    const int zb = blockIdx.z / H;
    const int zh = blockIdx.z - zb * H;
    const int rowBase = blockIdx.y * BM;
    const int colBase = blockIdx.x * BN;

    const __half* A_ = A + zb * aSB + zh * aSH + (long long)rowBase * lda;
    const __half* B_ = B + zb * bSB + zh * bSH + (long long)colBase * ldb;
    const long long cOff = zb * cSB + zh * cSH;

    const int warpM = (wid >> 2) * 64;
    const int warpN = (wid & 3) * 32;

    float acc[4][4][4];
#pragma unroll
    for (int i = 0; i < 4; i++)
#pragma unroll
        for (int j = 0; j < 4; j++)
#pragma unroll
            for (int v = 0; v < 4; v++) acc[i][j][v] = 0.0f;

    const int nK = K >> 6;

    auto load_stage = [&](int t, int buf) {
        const int k0 = t << 6;
        const uint32_t sS = sbase + buf * STAGE2_B;
        const __half* src[2] = {A_, B_};
        const int lds[2] = {lda, ldb};
#pragma unroll
        for (int tl = 0; tl < 2; tl++) {
            const __half* Q = src[tl];
            const int ld = lds[tl];
            const uint32_t tb = sS + tl * TILE_B;
#pragma unroll
            for (int j = 0; j < 4; j++) {
                int idx = tid + j * 256;
                int row = idx >> 3;
                int c = idx & 7;
                int sw = c ^ (row & 7);
                cp16(tb + row * 128 + sw * 16,
                     Q + (long long)row * ld + k0 + c * 8);
            }
        }
    };

#pragma unroll
    for (int s = 0; s < STAGES; s++) {
        if (s < nK) load_stage(s, s);
        CP_COMMIT();
    }

    for (int t = 0; t < nK; t++) {
        const int buf = t % STAGES;
        CP_WAIT2();
        __syncthreads();

        const uint32_t sS = sbase + buf * STAGE2_B;
        const uint32_t sA = sS;
        const uint32_t sB = sS + TILE_B;

#pragma unroll
        for (int ks = 0; ks < 4; ks++) {
            uint32_t a[4][4], b[2][4];
#pragma unroll
            for (int i = 0; i < 4; i++)
                ldsm4(a[i], frag_addr(sA, warpM + i * 16, ks, lid));
#pragma unroll
            for (int j = 0; j < 2; j++)
                ldsm4(b[j], frag_addr(sB, warpN + j * 16, ks, lid));

#pragma unroll
            for (int i = 0; i < 4; i++) {
#pragma unroll
                for (int j = 0; j < 4; j++) {
                    mma_f16(acc[i][j], a[i],
                            b[j >> 1][j & 1], b[j >> 1][(j & 1) + 2]);
                }
            }
        }
        __syncthreads();

        const int nt = t + STAGES;
        if (nt < nK) load_stage(nt, buf);
        CP_COMMIT();
    }

    const int g = lid >> 2;
    const int tq = lid & 3;
    const long long sumBase = (long long)blockIdx.z * SEQ;

#pragma unroll
    for (int i = 0; i < 4; i++) {
        const int lr0 = rowBase + warpM + i * 16 + g;   // local row
        const int lr1 = lr0 + 8;
        const long long r0 = lr0, r1 = lr1;

        float inv0 = 1.0f, inv1 = 1.0f;
        if (fuse == 2) {
            inv0 = __frcp_rn(rowsum[sumBase + lr0]);
            inv1 = __frcp_rn(rowsum[sumBase + lr1]);
        }
        float se0 = 0.0f, se1 = 0.0f;

#pragma unroll
        for (int j = 0; j < 4; j++) {
            const int col = colBase + warpN + j * 8 + tq * 2;
            float x0 = acc[i][j][0] * alpha, x1 = acc[i][j][1] * alpha;
            float x2 = acc[i][j][2] * alpha, x3 = acc[i][j][3] * alpha;
            if (fuse == 1) {
                x0 = __expf(x0); x1 = __expf(x1);
                x2 = __expf(x2); x3 = __expf(x3);
                se0 += x0 + x1;
                se1 += x2 + x3;
            } else if (fuse == 2) {
                x0 *= inv0; x1 *= inv0;
                x2 *= inv1; x3 *= inv1;
            }
            *reinterpret_cast<__half2*>(Hf + cOff + r0 * ldc + col) =
                __floats2half2_rn(x0, x1);
            *reinterpret_cast<__half2*>(Hf + cOff + r1 * ldc + col) =
                __floats2half2_rn(x2, x3);
        }

        if (fuse == 1) {
            // reduce over the 4 quad lanes (tq) that share this row
            se0 += __shfl_xor_sync(0xffffffffu, se0, 1);
            se0 += __shfl_xor_sync(0xffffffffu, se0, 2);
            se1 += __shfl_xor_sync(0xffffffffu, se1, 1);
            se1 += __shfl_xor_sync(0xffffffffu, se1, 2);
            if (tq == 0) {
                atomicAdd(&rowsum[sumBase + lr0], se0);
                atomicAdd(&rowsum[sumBase + lr1], se1);
            }
        }
    }
}

// ---------------------------------------------------------------------------
// fp32 -> fp16 hi/lo split (X, Wo)
// ---------------------------------------------------------------------------
__global__ void __launch_bounds__(256)
split2_f16(const float* __restrict__ x, __half* __restrict__ h,
           __half* __restrict__ l, long long n4)
{
    long long i = (long long)blockIdx.x * blockDim.x + threadIdx.x;
    if (i >= n4) return;
    float4 v = reinterpret_cast<const float4*>(x)[i];
    __half h0 = __float2half(v.x), h1 = __float2half(v.y);
    __half h2 = __float2half(v.z), h3 = __float2half(v.w);
    __half2 a, b;
    a.x = h0; a.y = h1; b.x = h2; b.y = h3;
    reinterpret_cast<__half2*>(h)[2 * i] = a;
    reinterpret_cast<__half2*>(h)[2 * i + 1] = b;
    a.x = __float2half(v.x - __half2float(h0));
    a.y = __float2half(v.y - __half2float(h1));
    b.x = __float2half(v.z - __half2float(h2));
    b.y = __float2half(v.w - __half2float(h3));
    reinterpret_cast<__half2*>(l)[2 * i] = a;
    reinterpret_cast<__half2*>(l)[2 * i + 1] = b;
}

// fp32 -> fp16 single (Wq, Wk, Wv)
__global__ void __launch_bounds__(256)
split1_f16(const float* __restrict__ x, __half* __restrict__ h, long long n4)
{
    long long i = (long long)blockIdx.x * blockDim.x + threadIdx.x;
    if (i >= n4) return;
    float4 v = reinterpret_cast<const float4*>(x)[i];
    __half2 a, b;
    a.x = __float2half(v.x); a.y = __float2half(v.y);
    b.x = __float2half(v.z); b.y = __float2half(v.w);
    reinterpret_cast<__half2*>(h)[2 * i] = a;
    reinterpret_cast<__half2*>(h)[2 * i + 1] = b;
}

static void* sym_addr(const void* symbol)
{
    void* p = nullptr;
    cudaGetSymbolAddress(&p, symbol);
    return p;
}

extern "C" void kernel_launch(void* const* d_in, const int* in_sizes, int n_in,
                              void* d_out, int out_size)
{
    const float* X  = (const float*)d_in[0];
    const float* Wq = (const float*)d_in[1];
    const float* Wk = (const float*)d_in[2];
    const float* Wv = (const float*)d_in[3];
    const float* Wo = (const float*)d_in[4];
    float* out = (float*)d_out;

    __half* Xh  = (__half*)sym_addr(g_Xh);
    __half* Xl  = (__half*)sym_addr(g_Xl);
    __half* Wqf = (__half*)sym_addr(g_Wq);
    __half* Wkf = (__half*)sym_addr(g_Wk);
    __half* Wvf = (__half*)sym_addr(g_Wv);
    __half* Woh = (__half*)sym_addr(g_Woh);
    __half* Wol = (__half*)sym_addr(g_Wol);
    __half* Qf  = (__half*)sym_addr(g_Qf);
    __half* Kf  = (__half*)sym_addr(g_Kf);
    __half* Vt  = (__half*)sym_addr(g_Vt);
    __half* S   = (__half*)sym_addr(g_S);
    __half* M   = (__half*)sym_addr(g_M);
    float*  rs  = (float*)sym_addr(g_rowsum);

    cudaFuncSetAttribute(gemm_2ph, cudaFuncAttributeMaxDynamicSharedMemorySize,
                         G2_SMEM);
    cudaFuncSetAttribute(gemm_f16, cudaFuncAttributeMaxDynamicSharedMemorySize,
                         G1_SMEM);

    // zero row sums (graph-capturable async memset)
    cudaMemsetAsync(rs, 0, (size_t)BATCH * NHEAD * SEQ * sizeof(float));

    {
        long long n4;
        n4 = (long long)MS * DMODEL / 4;
        split2_f16<<<(unsigned)((n4 + 255) / 256), 256>>>(X, Xh, Xl, n4);
        n4 = (long long)DMODEL * DMODEL / 4;
        split1_f16<<<(unsigned)((n4 + 255) / 256), 256>>>(Wq, Wqf, n4);
        split2_f16<<<(unsigned)((n4 + 255) / 256), 256>>>(Wo, Woh, Wol, n4);
        n4 = (long long)DK * DMODEL / 4;
        split1_f16<<<(unsigned)((n4 + 255) / 256), 256>>>(Wk, Wkf, n4);
        split1_f16<<<(unsigned)((n4 + 255) / 256), 256>>>(Wv, Wvf, n4);
    }

    // Q = (Xh + Xl) @ Wq^T -> fp16
    gemm_2ph<<<dim3(DMODEL / BN, MS / BM, 1), 256, G2_SMEM>>>(
        Xh, Xl, Wqf, Wqf, nullptr, Qf,
        DMODEL, DMODEL, DMODEL, DMODEL, 1.0f, 2, 0, 1,
        0, 0, 0, 1);

    // Kc = (Xh + Xl) @ Wk^T -> fp16
    gemm_2ph<<<dim3(DK / BN, MS / BM, 1), 256, G2_SMEM>>>(
        Xh, Xl, Wkf, Wkf, nullptr, Kf,
        DMODEL, DMODEL, DMODEL, DK, 1.0f, 2, 0, 1,
        0, 0, 0, 1);

    // VcT[b] = Wv @ (Xh + Xl)[b]^T -> fp16
    gemm_2ph<<<dim3(SEQ / BN, DK / BM, BATCH), 256, G2_SMEM>>>(
        Wvf, Wvf, Xh, Xl, nullptr, Vt,
        DMODEL, DMODEL, DMODEL, SEQ, 1.0f, 2, 1, 0,
        0, (long long)SEQ * DMODEL, (long long)DK * SEQ, 1);

    // S[b,h] = exp(SCALE * Q @ K^T) -> fp16, rowsum accumulated
    gemm_f16<<<dim3(SEQ / BN, SEQ / BM, BATCH * NHEAD), 256, G1_SMEM>>>(
        Qf, Kf, S, rs, 1,
        DK, DMODEL, DK, SEQ, SCALE_F,
        (long long)SEQ * DMODEL, DK,
        (long long)SEQ * DK, 0,
        (long long)NHEAD * SEQ * SEQ, (long long)SEQ * SEQ, NHEAD);

    // M = (S @ VcT^T) / rowsum -> fp16 merged
    gemm_f16<<<dim3(DK / BN, SEQ / BM, BATCH * NHEAD), 256, G1_SMEM>>>(
        S, Vt, M, rs, 2,
        SEQ, SEQ, SEQ, DMODEL, 1.0f,
        (long long)NHEAD * SEQ * SEQ, (long long)SEQ * SEQ,
        (long long)DK * SEQ, 0,
        (long long)SEQ * DMODEL, DK, NHEAD);

    // out = M @ (Woh + Wol)^T -> fp32
    gemm_2ph<<<dim3(DMODEL / BN, MS / BM, 1), 256, G2_SMEM>>>(
        M, M, Woh, Wol, out, nullptr,
        DMODEL, DMODEL, DMODEL, DMODEL, 1.0f, 0, 1, 0,
        0, 0, 0, 1);
}

// round 9
// speedup vs baseline: 5.9908x; 1.0242x over previous
#include <cuda_runtime.h>
#include <cuda_fp16.h>
#include <cstdint>
#include <math.h>

#define BATCH 2
#define SEQ   4096
#define DMODEL 1024
#define NHEAD 4
#define DK    256
#define MS (BATCH * SEQ)
#define SCALE_F (1.0f / 16.0f)

#define BM 128
#define BN 128
#define TILE_B 16384

// projections: 3 tiles/stage, 2 stages -> 96KB, 2 CTA/SM
#define P_STAGES 2
#define STAGE3_B (3 * TILE_B)
#define G2_SMEM (P_STAGES * STAGE3_B)

// attention: 2 tiles/stage, 3 stages -> 96KB, 2 CTA/SM
#define STAGES 3
#define STAGE2_B (2 * TILE_B)
#define G1_SMEM (STAGES * STAGE2_B)

// ---------------------------------------------------------------------------
// Device scratch (all fp16) + fp32 row sums
// ---------------------------------------------------------------------------
__device__ __align__(256) __half g_Xh[(size_t)MS * DMODEL];
__device__ __align__(256) __half g_Xl[(size_t)MS * DMODEL];
__device__ __align__(256) __half g_Wq[(size_t)DMODEL * DMODEL];
__device__ __align__(256) __half g_Wk[(size_t)DK * DMODEL];
__device__ __align__(256) __half g_Wv[(size_t)DK * DMODEL];
__device__ __align__(256) __half g_Woh[(size_t)DMODEL * DMODEL];
__device__ __align__(256) __half g_Wol[(size_t)DMODEL * DMODEL];
__device__ __align__(256) __half g_Qf[(size_t)MS * DMODEL];
__device__ __align__(256) __half g_Kf[(size_t)MS * DK];
__device__ __align__(256) __half g_Vt[(size_t)BATCH * DK * SEQ];
__device__ __align__(256) __half g_S[(size_t)BATCH * NHEAD * SEQ * SEQ];
__device__ __align__(256) __half g_M[(size_t)MS * DMODEL];
__device__ __align__(256) float  g_rowsum[(size_t)BATCH * NHEAD * SEQ];

// ---------------------------------------------------------------------------
// PTX helpers
// ---------------------------------------------------------------------------
__device__ __forceinline__ uint32_t smem_u32(const void* p) {
    uint32_t a;
    asm("{ .reg .u64 t; cvta.to.shared.u64 t, %1; cvt.u32.u64 %0, t; }"
        : "=r"(a) : "l"(p));
    return a;
}
__device__ __forceinline__ void cp16(uint32_t s, const void* g) {
    asm volatile("cp.async.cg.shared.global [%0], [%1], 16;" :: "r"(s), "l"(g));
}
#define CP_COMMIT() asm volatile("cp.async.commit_group;" ::: "memory")
#define CP_WAIT1()  asm volatile("cp.async.wait_group 1;" ::: "memory")
#define CP_WAIT2()  asm volatile("cp.async.wait_group 2;" ::: "memory")

__device__ __forceinline__ void ldsm4(uint32_t* r, uint32_t addr) {
    asm volatile("ldmatrix.sync.aligned.m8n8.x4.shared.b16 {%0,%1,%2,%3}, [%4];"
                 : "=r"(r[0]), "=r"(r[1]), "=r"(r[2]), "=r"(r[3]) : "r"(addr));
}
__device__ __forceinline__ void mma_f16(float* c, const uint32_t* a,
                                        uint32_t b0, uint32_t b1) {
    asm volatile(
        "mma.sync.aligned.m16n8k16.row.col.f32.f16.f16.f32 "
        "{%0,%1,%2,%3}, {%4,%5,%6,%7}, {%8,%9}, {%0,%1,%2,%3};\n"
        : "+f"(c[0]), "+f"(c[1]), "+f"(c[2]), "+f"(c[3])
        : "r"(a[0]), "r"(a[1]), "r"(a[2]), "r"(a[3]), "r"(b0), "r"(b1));
}
__device__ __forceinline__ uint32_t frag_addr(uint32_t tbase, int rowBase,
                                              int ks, int lane) {
    int row = rowBase + (lane & 15);
    int chunk = ks * 2 + (lane >> 4);
    int sw = chunk ^ (row & 7);
    return tbase + row * 128 + sw * 16;
}

// ---------------------------------------------------------------------------
// 2-phase fp16 GEMM (projections): C = alpha * (A0*B0^T + A1*B1^T).
// Exactly one operand is duplicated -> 3 distinct tiles per stage (48KB),
// 2 stages = 96KB -> 2 CTAs/SM. Fragments are reused across the two phases
// to stay within the 2-CTA register budget.
// mode 0: fp32 out. mode 2: fp16 out.
// ---------------------------------------------------------------------------
__global__ void __launch_bounds__(256, 2)
gemm_2ph(const __half* __restrict__ A0, const __half* __restrict__ A1,
         const __half* __restrict__ B0, const __half* __restrict__ B1,
         float* __restrict__ Cf, __half* __restrict__ Hf,
         int K, int lda, int ldb, int ldc, float alpha, int mode,
         int dupA, int dupB,
         long long aSB, long long bSB, long long cSB, int H)
{
    extern __shared__ char smem[];
    const uint32_t sbase = smem_u32(smem);
    const int tid = threadIdx.x;
    const int wid = tid >> 5;
    const int lid = tid & 31;

    const int zb = blockIdx.z / H;
    const int rowBase = blockIdx.y * BM;
    const int colBase = blockIdx.x * BN;

    const __half* A0_ = A0 + zb * aSB + (long long)rowBase * lda;
    const __half* A1_ = A1 + zb * aSB + (long long)rowBase * lda;
    const __half* B0_ = B0 + zb * bSB + (long long)colBase * ldb;
    const __half* B1_ = B1 + zb * bSB + (long long)colBase * ldb;
    const long long cOff = zb * cSB;

    const int warpM = (wid >> 2) * 64;
    const int warpN = (wid & 3) * 32;

    float acc[4][4][4];
#pragma unroll
    for (int i = 0; i < 4; i++)
#pragma unroll
        for (int j = 0; j < 4; j++)
#pragma unroll
            for (int v = 0; v < 4; v++) acc[i][j][v] = 0.0f;

    const int nK = K >> 6;

    // slot offsets within a stage (3 tiles). If dupA: {A0, B0, B1};
    // if dupB: {A0, A1, B0}.
    const uint32_t offA0 = 0;
    const uint32_t offA1 = dupA ? 0u : (uint32_t)TILE_B;
    const uint32_t offB0 = dupA ? (uint32_t)TILE_B : 2u * TILE_B;
    const uint32_t offB1 = dupA ? 2u * TILE_B
                                : (dupB ? 2u * TILE_B : 2u * TILE_B);
    // (dupB: B1 aliases B0 at slot 2)
    const uint32_t offB1e = dupB ? offB0 : offB1;

    auto load_tile = [&](const __half* P, int ld, uint32_t tb, int k0) {
#pragma unroll
        for (int j = 0; j < 4; j++) {
            int idx = tid + j * 256;
            int row = idx >> 3;
            int c = idx & 7;
            int sw = c ^ (row & 7);
            cp16(tb + row * 128 + sw * 16, P + (long long)row * ld + k0 + c * 8);
        }
    };
    auto load_stage = [&](int t, int buf) {
        const int k0 = t << 6;
        const uint32_t sS = sbase + buf * STAGE3_B;
        load_tile(A0_, lda, sS + offA0, k0);
        if (!dupA) load_tile(A1_, lda, sS + offA1, k0);
        load_tile(B0_, ldb, sS + offB0, k0);
        if (!dupB) load_tile(B1_, ldb, sS + offB1, k0);
    };

#pragma unroll
    for (int s = 0; s < P_STAGES; s++) {
        if (s < nK) load_stage(s, s);
        CP_COMMIT();
    }

    for (int t = 0; t < nK; t++) {
        const int buf = t & (P_STAGES - 1);
        CP_WAIT1();
        __syncthreads();

        const uint32_t sS = sbase + buf * STAGE3_B;
        const uint32_t sA0 = sS + offA0;
        const uint32_t sA1 = sS + offA1;
        const uint32_t sB0 = sS + offB0;
        const uint32_t sB1 = sS + offB1e;

#pragma unroll
        for (int ks = 0; ks < 4; ks++) {
            uint32_t af[4][4], bf[2][4];
            // phase 0
#pragma unroll
            for (int i = 0; i < 4; i++)
                ldsm4(af[i], frag_addr(sA0, warpM + i * 16, ks, lid));
#pragma unroll
            for (int j = 0; j < 2; j++)
                ldsm4(bf[j], frag_addr(sB0, warpN + j * 16, ks, lid));
#pragma unroll
            for (int i = 0; i < 4; i++)
#pragma unroll
                for (int j = 0; j < 4; j++)
                    mma_f16(acc[i][j], af[i],
                            bf[j >> 1][j & 1], bf[j >> 1][(j & 1) + 2]);
            // phase 1 (reuse fragment registers)
#pragma unroll
            for (int i = 0; i < 4; i++)
                ldsm4(af[i], frag_addr(sA1, warpM + i * 16, ks, lid));
#pragma unroll
            for (int j = 0; j < 2; j++)
                ldsm4(bf[j], frag_addr(sB1, warpN + j * 16, ks, lid));
#pragma unroll
            for (int i = 0; i < 4; i++)
#pragma unroll
                for (int j = 0; j < 4; j++)
                    mma_f16(acc[i][j], af[i],
                            bf[j >> 1][j & 1], bf[j >> 1][(j & 1) + 2]);
        }
        __syncthreads();

        const int nt = t + P_STAGES;
        if (nt < nK) load_stage(nt, buf);
        CP_COMMIT();
    }

    const int g = lid >> 2;
    const int tq = lid & 3;
#pragma unroll
    for (int i = 0; i < 4; i++) {
        const long long r0 = rowBase + warpM + i * 16 + g;
        const long long r1 = r0 + 8;
#pragma unroll
        for (int j = 0; j < 4; j++) {
            const int col = colBase + warpN + j * 8 + tq * 2;
            float x0 = acc[i][j][0] * alpha, x1 = acc[i][j][1] * alpha;
            float x2 = acc[i][j][2] * alpha, x3 = acc[i][j][3] * alpha;
            if (mode == 0) {
                *reinterpret_cast<float2*>(Cf + cOff + r0 * ldc + col) =
                    make_float2(x0, x1);
                *reinterpret_cast<float2*>(Cf + cOff + r1 * ldc + col) =
                    make_float2(x2, x3);
            } else {
                *reinterpret_cast<__half2*>(Hf + cOff + r0 * ldc + col) =
                    __floats2half2_rn(x0, x1);
                *reinterpret_cast<__half2*>(Hf + cOff + r1 * ldc + col) =
                    __floats2half2_rn(x2, x3);
            }
        }
    }
}

// ---------------------------------------------------------------------------
// 1-phase fp16 GEMM with fused softmax pieces.
// fuse 0: fp16 out. fuse 1 (QK): out = exp(alpha*acc), rowsum atomics.
// fuse 2 (PV): out = acc / rowsum[row].
// ---------------------------------------------------------------------------
__global__ void __launch_bounds__(256, 2)
gemm_f16(const __half* __restrict__ A, const __half* __restrict__ B,
         __half* __restrict__ Hf, float* __restrict__ rowsum, int fuse,
         int K, int lda, int ldb, int ldc, float alpha,
         long long aSB, long long aSH, long long bSB, long long bSH,
         long long cSB, long long cSH, int H)
{
    extern __shared__ char smem[];
    const uint32_t sbase = smem_u32(smem);
    const int tid = threadIdx.x;
    const int wid = tid >> 5;
    const int lid = tid & 31;

    const int zb = blockIdx.z / H;
    const int zh = blockIdx.z - zb * H;
    const int rowBase = blockIdx.y * BM;
    const int colBase = blockIdx.x * BN;

    const __half* A_ = A + zb * aSB + zh * aSH + (long long)rowBase * lda;
    const __half* B_ = B + zb * bSB + zh * bSH + (long long)colBase * ldb;
    const long long cOff = zb * cSB + zh * cSH;

    const int warpM = (wid >> 2) * 64;
    const int warpN = (wid & 3) * 32;

    float acc[4][4][4];
#pragma unroll
    for (int i = 0; i < 4; i++)
#pragma unroll
        for (int j = 0; j < 4; j++)
#pragma unroll
            for (int v = 0; v < 4; v++) acc[i][j][v] = 0.0f;

    const int nK = K >> 6;

    auto load_stage = [&](int t, int buf) {
        const int k0 = t << 6;
        const uint32_t sS = sbase + buf * STAGE2_B;
        const __half* src[2] = {A_, B_};
        const int lds[2] = {lda, ldb};
#pragma unroll
        for (int tl = 0; tl < 2; tl++) {
            const __half* Q = src[tl];
            const int ld = lds[tl];
            const uint32_t tb = sS + tl * TILE_B;
#pragma unroll
            for (int j = 0; j < 4; j++) {
                int idx = tid + j * 256;
                int row = idx >> 3;
                int c = idx & 7;
                int sw = c ^ (row & 7);
                cp16(tb + row * 128 + sw * 16,
                     Q + (long long)row * ld + k0 + c * 8);
            }
        }
    };

#pragma unroll
    for (int s = 0; s < STAGES; s++) {
        if (s < nK) load_stage(s, s);
        CP_COMMIT();
    }

    for (int t = 0; t < nK; t++) {
        const int buf = t % STAGES;
        CP_WAIT2();
        __syncthreads();

        const uint32_t sS = sbase + buf * STAGE2_B;
        const uint32_t sA = sS;
        const uint32_t sB = sS + TILE_B;

#pragma unroll
        for (int ks = 0; ks < 4; ks++) {
            uint32_t a[4][4], b[2][4];
#pragma unroll
            for (int i = 0; i < 4; i++)
                ldsm4(a[i], frag_addr(sA, warpM + i * 16, ks, lid));
#pragma unroll
            for (int j = 0; j < 2; j++)
                ldsm4(b[j], frag_addr(sB, warpN + j * 16, ks, lid));

#pragma unroll
            for (int i = 0; i < 4; i++) {
#pragma unroll
                for (int j = 0; j < 4; j++) {
                    mma_f16(acc[i][j], a[i],
                            b[j >> 1][j & 1], b[j >> 1][(j & 1) + 2]);
                }
            }
        }
        __syncthreads();

        const int nt = t + STAGES;
        if (nt < nK) load_stage(nt, buf);
        CP_COMMIT();
    }

    const int g = lid >> 2;
    const int tq = lid & 3;
    const long long sumBase = (long long)blockIdx.z * SEQ;

#pragma unroll
    for (int i = 0; i < 4; i++) {
        const int lr0 = rowBase + warpM + i * 16 + g;
        const int lr1 = lr0 + 8;
        const long long r0 = lr0, r1 = lr1;

        float inv0 = 1.0f, inv1 = 1.0f;
        if (fuse == 2) {
            inv0 = __frcp_rn(rowsum[sumBase + lr0]);
            inv1 = __frcp_rn(rowsum[sumBase + lr1]);
        }
        float se0 = 0.0f, se1 = 0.0f;

#pragma unroll
        for (int j = 0; j < 4; j++) {
            const int col = colBase + warpN + j * 8 + tq * 2;
            float x0 = acc[i][j][0] * alpha, x1 = acc[i][j][1] * alpha;
            float x2 = acc[i][j][2] * alpha, x3 = acc[i][j][3] * alpha;
            if (fuse == 1) {
                x0 = __expf(x0); x1 = __expf(x1);
                x2 = __expf(x2); x3 = __expf(x3);
                se0 += x0 + x1;
                se1 += x2 + x3;
            } else if (fuse == 2) {
                x0 *= inv0; x1 *= inv0;
                x2 *= inv1; x3 *= inv1;
            }
            *reinterpret_cast<__half2*>(Hf + cOff + r0 * ldc + col) =
                __floats2half2_rn(x0, x1);
            *reinterpret_cast<__half2*>(Hf + cOff + r1 * ldc + col) =
                __floats2half2_rn(x2, x3);
        }

        if (fuse == 1) {
            se0 += __shfl_xor_sync(0xffffffffu, se0, 1);
            se0 += __shfl_xor_sync(0xffffffffu, se0, 2);
            se1 += __shfl_xor_sync(0xffffffffu, se1, 1);
            se1 += __shfl_xor_sync(0xffffffffu, se1, 2);
            if (tq == 0) {
                atomicAdd(&rowsum[sumBase + lr0], se0);
                atomicAdd(&rowsum[sumBase + lr1], se1);
            }
        }
    }
}

// ---------------------------------------------------------------------------
// fp32 -> fp16 hi/lo split (X, Wo)
// ---------------------------------------------------------------------------
__global__ void __launch_bounds__(256)
split2_f16(const float* __restrict__ x, __half* __restrict__ h,
           __half* __restrict__ l, long long n4)
{
    long long i = (long long)blockIdx.x * blockDim.x + threadIdx.x;
    if (i >= n4) return;
    float4 v = reinterpret_cast<const float4*>(x)[i];
    __half h0 = __float2half(v.x), h1 = __float2half(v.y);
    __half h2 = __float2half(v.z), h3 = __float2half(v.w);
    __half2 a, b;
    a.x = h0; a.y = h1; b.x = h2; b.y = h3;
    reinterpret_cast<__half2*>(h)[2 * i] = a;
    reinterpret_cast<__half2*>(h)[2 * i + 1] = b;
    a.x = __float2half(v.x - __half2float(h0));
    a.y = __float2half(v.y - __half2float(h1));
    b.x = __float2half(v.z - __half2float(h2));
    b.y = __float2half(v.w - __half2float(h3));
    reinterpret_cast<__half2*>(l)[2 * i] = a;
    reinterpret_cast<__half2*>(l)[2 * i + 1] = b;
}

// fp32 -> fp16 single (Wq, Wk, Wv)
__global__ void __launch_bounds__(256)
split1_f16(const float* __restrict__ x, __half* __restrict__ h, long long n4)
{
    long long i = (long long)blockIdx.x * blockDim.x + threadIdx.x;
    if (i >= n4) return;
    float4 v = reinterpret_cast<const float4*>(x)[i];
    __half2 a, b;
    a.x = __float2half(v.x); a.y = __float2half(v.y);
    b.x = __float2half(v.z); b.y = __float2half(v.w);
    reinterpret_cast<__half2*>(h)[2 * i] = a;
    reinterpret_cast<__half2*>(h)[2 * i + 1] = b;
}

static void* sym_addr(const void* symbol)
{
    void* p = nullptr;
    cudaGetSymbolAddress(&p, symbol);
    return p;
}

extern "C" void kernel_launch(void* const* d_in, const int* in_sizes, int n_in,
                              void* d_out, int out_size)
{
    const float* X  = (const float*)d_in[0];
    const float* Wq = (const float*)d_in[1];
    const float* Wk = (const float*)d_in[2];
    const float* Wv = (const float*)d_in[3];
    const float* Wo = (const float*)d_in[4];
    float* out = (float*)d_out;

    __half* Xh  = (__half*)sym_addr(g_Xh);
    __half* Xl  = (__half*)sym_addr(g_Xl);
    __half* Wqf = (__half*)sym_addr(g_Wq);
    __half* Wkf = (__half*)sym_addr(g_Wk);
    __half* Wvf = (__half*)sym_addr(g_Wv);
    __half* Woh = (__half*)sym_addr(g_Woh);
    __half* Wol = (__half*)sym_addr(g_Wol);
    __half* Qf  = (__half*)sym_addr(g_Qf);
    __half* Kf  = (__half*)sym_addr(g_Kf);
    __half* Vt  = (__half*)sym_addr(g_Vt);
    __half* S   = (__half*)sym_addr(g_S);
    __half* M   = (__half*)sym_addr(g_M);
    float*  rs  = (float*)sym_addr(g_rowsum);

    cudaFuncSetAttribute(gemm_2ph, cudaFuncAttributeMaxDynamicSharedMemorySize,
                         G2_SMEM);
    cudaFuncSetAttribute(gemm_f16, cudaFuncAttributeMaxDynamicSharedMemorySize,
                         G1_SMEM);

    cudaMemsetAsync(rs, 0, (size_t)BATCH * NHEAD * SEQ * sizeof(float));

    {
        long long n4;
        n4 = (long long)MS * DMODEL / 4;
        split2_f16<<<(unsigned)((n4 + 255) / 256), 256>>>(X, Xh, Xl, n4);
        n4 = (long long)DMODEL * DMODEL / 4;
        split1_f16<<<(unsigned)((n4 + 255) / 256), 256>>>(Wq, Wqf, n4);
        split2_f16<<<(unsigned)((n4 + 255) / 256), 256>>>(Wo, Woh, Wol, n4);
        n4 = (long long)DK * DMODEL / 4;
        split1_f16<<<(unsigned)((n4 + 255) / 256), 256>>>(Wk, Wkf, n4);
        split1_f16<<<(unsigned)((n4 + 255) / 256), 256>>>(Wv, Wvf, n4);
    }

    // Q = (Xh + Xl) @ Wq^T -> fp16
    gemm_2ph<<<dim3(DMODEL / BN, MS / BM, 1), 256, G2_SMEM>>>(
        Xh, Xl, Wqf, Wqf, nullptr, Qf,
        DMODEL, DMODEL, DMODEL, DMODEL, 1.0f, 2, 0, 1,
        0, 0, 0, 1);

    // Kc = (Xh + Xl) @ Wk^T -> fp16
    gemm_2ph<<<dim3(DK / BN, MS / BM, 1), 256, G2_SMEM>>>(
        Xh, Xl, Wkf, Wkf, nullptr, Kf,
        DMODEL, DMODEL, DMODEL, DK, 1.0f, 2, 0, 1,
        0, 0, 0, 1);

    // VcT[b] = Wv @ (Xh + Xl)[b]^T -> fp16
    gemm_2ph<<<dim3(SEQ / BN, DK / BM, BATCH), 256, G2_SMEM>>>(
        Wvf, Wvf, Xh, Xl, nullptr, Vt,
        DMODEL, DMODEL, DMODEL, SEQ, 1.0f, 2, 1, 0,
        0, (long long)SEQ * DMODEL, (long long)DK * SEQ, 1);

    // S[b,h] = exp(SCALE * Q @ K^T) -> fp16, rowsum accumulated
    gemm_f16<<<dim3(SEQ / BN, SEQ / BM, BATCH * NHEAD), 256, G1_SMEM>>>(
        Qf, Kf, S, rs, 1,
        DK, DMODEL, DK, SEQ, SCALE_F,
        (long long)SEQ * DMODEL, DK,
        (long long)SEQ * DK, 0,
        (long long)NHEAD * SEQ * SEQ, (long long)SEQ * SEQ, NHEAD);

    // M = (S @ VcT^T) / rowsum -> fp16 merged
    gemm_f16<<<dim3(DK / BN, SEQ / BM, BATCH * NHEAD), 256, G1_SMEM>>>(
        S, Vt, M, rs, 2,
        SEQ, SEQ, SEQ, DMODEL, 1.0f,
        (long long)NHEAD * SEQ * SEQ, (long long)SEQ * SEQ,
        (long long)DK * SEQ, 0,
        (long long)SEQ * DMODEL, DK, NHEAD);

    // out = M @ (Woh + Wol)^T -> fp32
    gemm_2ph<<<dim3(DMODEL / BN, MS / BM, 1), 256, G2_SMEM>>>(
        M, M, Woh, Wol, out, nullptr,
        DMODEL, DMODEL, DMODEL, DMODEL, 1.0f, 0, 1, 0,
        0, 0, 0, 1);
}

// round 10
// speedup vs baseline: 6.6428x; 1.1088x over previous
#include <cuda_runtime.h>
#include <cuda_fp16.h>
#include <cstdint>
#include <math.h>

#define BATCH 2
#define SEQ   4096
#define DMODEL 1024
#define NHEAD 4
#define DK    256
#define MS (BATCH * SEQ)
#define SCALE_F (1.0f / 16.0f)
#define DQK (DMODEL + DK)          // 1280: merged Q|K projection width

#define BM 128
#define BN 128
#define TILE_B 16384

// O-proj (2-phase): 3 tiles/stage, 2 stages -> 96KB, 2 CTA/SM
#define P_STAGES 2
#define STAGE3_B (3 * TILE_B)
#define G2_SMEM (P_STAGES * STAGE3_B)

// 1-phase GEMMs: 2 tiles/stage, 3 stages -> 96KB, 2 CTA/SM
#define STAGES 3
#define STAGE2_B (2 * TILE_B)
#define G1_SMEM (STAGES * STAGE2_B)

// ---------------------------------------------------------------------------
// Device scratch
// ---------------------------------------------------------------------------
__device__ __align__(256) __half g_Xf[(size_t)MS * DMODEL];
__device__ __align__(256) __half g_Wqk[(size_t)DQK * DMODEL];   // Wq rows 0-1023, Wk rows 1024-1279
__device__ __align__(256) __half g_Wv[(size_t)DK * DMODEL];
__device__ __align__(256) __half g_Woh[(size_t)DMODEL * DMODEL];
__device__ __align__(256) __half g_Wol[(size_t)DMODEL * DMODEL];
__device__ __align__(256) __half g_QK[(size_t)MS * DQK];        // Q cols 0-1023, K cols 1024-1279
__device__ __align__(256) __half g_Vt[(size_t)BATCH * DK * SEQ];
__device__ __align__(256) __half g_S[(size_t)BATCH * NHEAD * SEQ * SEQ];
__device__ __align__(256) __half g_M[(size_t)MS * DMODEL];
__device__ __align__(256) float  g_rowsum[(size_t)BATCH * NHEAD * SEQ];

// ---------------------------------------------------------------------------
// PTX helpers
// ---------------------------------------------------------------------------
__device__ __forceinline__ uint32_t smem_u32(const void* p) {
    uint32_t a;
    asm("{ .reg .u64 t; cvta.to.shared.u64 t, %1; cvt.u32.u64 %0, t; }"
        : "=r"(a) : "l"(p));
    return a;
}
__device__ __forceinline__ void cp16(uint32_t s, const void* g) {
    asm volatile("cp.async.cg.shared.global [%0], [%1], 16;" :: "r"(s), "l"(g));
}
#define CP_COMMIT() asm volatile("cp.async.commit_group;" ::: "memory")
#define CP_WAIT1()  asm volatile("cp.async.wait_group 1;" ::: "memory")
#define CP_WAIT2()  asm volatile("cp.async.wait_group 2;" ::: "memory")

__device__ __forceinline__ void ldsm4(uint32_t* r, uint32_t addr) {
    asm volatile("ldmatrix.sync.aligned.m8n8.x4.shared.b16 {%0,%1,%2,%3}, [%4];"
                 : "=r"(r[0]), "=r"(r[1]), "=r"(r[2]), "=r"(r[3]) : "r"(addr));
}
__device__ __forceinline__ void mma_f16(float* c, const uint32_t* a,
                                        uint32_t b0, uint32_t b1) {
    asm volatile(
        "mma.sync.aligned.m16n8k16.row.col.f32.f16.f16.f32 "
        "{%0,%1,%2,%3}, {%4,%5,%6,%7}, {%8,%9}, {%0,%1,%2,%3};\n"
        : "+f"(c[0]), "+f"(c[1]), "+f"(c[2]), "+f"(c[3])
        : "r"(a[0]), "r"(a[1]), "r"(a[2]), "r"(a[3]), "r"(b0), "r"(b1));
}
__device__ __forceinline__ uint32_t frag_addr(uint32_t tbase, int rowBase,
                                              int ks, int lane) {
    int row = rowBase + (lane & 15);
    int chunk = ks * 2 + (lane >> 4);
    int sw = chunk ^ (row & 7);
    return tbase + row * 128 + sw * 16;
}

// ---------------------------------------------------------------------------
// 2-phase fp16 GEMM (O-proj only): C = A*B0^T + A*B1^T (dupA layout).
// 3 tiles/stage {A, B0, B1}, 2 stages, 2 CTA/SM. mode 0: fp32 out.
// ---------------------------------------------------------------------------
__global__ void __launch_bounds__(256, 2)
gemm_2ph(const __half* __restrict__ A0,
         const __half* __restrict__ B0, const __half* __restrict__ B1,
         float* __restrict__ Cf,
         int K, int lda, int ldb, int ldc)
{
    extern __shared__ char smem[];
    const uint32_t sbase = smem_u32(smem);
    const int tid = threadIdx.x;
    const int wid = tid >> 5;
    const int lid = tid & 31;

    const int rowBase = blockIdx.y * BM;
    const int colBase = blockIdx.x * BN;

    const __half* A0_ = A0 + (long long)rowBase * lda;
    const __half* B0_ = B0 + (long long)colBase * ldb;
    const __half* B1_ = B1 + (long long)colBase * ldb;

    const int warpM = (wid >> 2) * 64;
    const int warpN = (wid & 3) * 32;

    float acc[4][4][4];
#pragma unroll
    for (int i = 0; i < 4; i++)
#pragma unroll
        for (int j = 0; j < 4; j++)
#pragma unroll
            for (int v = 0; v < 4; v++) acc[i][j][v] = 0.0f;

    const int nK = K >> 6;

    auto load_tile = [&](const __half* P, int ld, uint32_t tb, int k0) {
#pragma unroll
        for (int j = 0; j < 4; j++) {
            int idx = tid + j * 256;
            int row = idx >> 3;
            int c = idx & 7;
            int sw = c ^ (row & 7);
            cp16(tb + row * 128 + sw * 16, P + (long long)row * ld + k0 + c * 8);
        }
    };
    auto load_stage = [&](int t, int buf) {
        const int k0 = t << 6;
        const uint32_t sS = sbase + buf * STAGE3_B;
        load_tile(A0_, lda, sS, k0);
        load_tile(B0_, ldb, sS + TILE_B, k0);
        load_tile(B1_, ldb, sS + 2 * TILE_B, k0);
    };

#pragma unroll
    for (int s = 0; s < P_STAGES; s++) {
        if (s < nK) load_stage(s, s);
        CP_COMMIT();
    }

    for (int t = 0; t < nK; t++) {
        const int buf = t & (P_STAGES - 1);
        CP_WAIT1();
        __syncthreads();

        const uint32_t sS = sbase + buf * STAGE3_B;
        const uint32_t sA = sS;
        const uint32_t sB0 = sS + TILE_B;
        const uint32_t sB1 = sS + 2 * TILE_B;

#pragma unroll
        for (int ks = 0; ks < 4; ks++) {
            uint32_t af[4][4], bf[2][4];
#pragma unroll
            for (int i = 0; i < 4; i++)
                ldsm4(af[i], frag_addr(sA, warpM + i * 16, ks, lid));
            // phase 0
#pragma unroll
            for (int j = 0; j < 2; j++)
                ldsm4(bf[j], frag_addr(sB0, warpN + j * 16, ks, lid));
#pragma unroll
            for (int i = 0; i < 4; i++)
#pragma unroll
                for (int j = 0; j < 4; j++)
                    mma_f16(acc[i][j], af[i],
                            bf[j >> 1][j & 1], bf[j >> 1][(j & 1) + 2]);
            // phase 1 (reuse B fragment registers)
#pragma unroll
            for (int j = 0; j < 2; j++)
                ldsm4(bf[j], frag_addr(sB1, warpN + j * 16, ks, lid));
#pragma unroll
            for (int i = 0; i < 4; i++)
#pragma unroll
                for (int j = 0; j < 4; j++)
                    mma_f16(acc[i][j], af[i],
                            bf[j >> 1][j & 1], bf[j >> 1][(j & 1) + 2]);
        }
        __syncthreads();

        const int nt = t + P_STAGES;
        if (nt < nK) load_stage(nt, buf);
        CP_COMMIT();
    }

    const int g = lid >> 2;
    const int tq = lid & 3;
#pragma unroll
    for (int i = 0; i < 4; i++) {
        const long long r0 = rowBase + warpM + i * 16 + g;
        const long long r1 = r0 + 8;
#pragma unroll
        for (int j = 0; j < 4; j++) {
            const int col = colBase + warpN + j * 8 + tq * 2;
            *reinterpret_cast<float2*>(Cf + r0 * ldc + col) =
                make_float2(acc[i][j][0], acc[i][j][1]);
            *reinterpret_cast<float2*>(Cf + r1 * ldc + col) =
                make_float2(acc[i][j][2], acc[i][j][3]);
        }
    }
}

// ---------------------------------------------------------------------------
// 1-phase fp16 GEMM with fused softmax pieces.
// fuse 0: fp16 out. fuse 1 (QK): out = exp(alpha*acc), rowsum atomics.
// fuse 2 (PV): out = acc / rowsum[row].
// ---------------------------------------------------------------------------
__global__ void __launch_bounds__(256, 2)
gemm_f16(const __half* __restrict__ A, const __half* __restrict__ B,
         __half* __restrict__ Hf, float* __restrict__ rowsum, int fuse,
         int K, int lda, int ldb, int ldc, float alpha,
         long long aSB, long long aSH, long long bSB, long long bSH,
         long long cSB, long long cSH, int H)
{
    extern __shared__ char smem[];
    const uint32_t sbase = smem_u32(smem);
    const int tid = threadIdx.x;
    const int wid = tid >> 5;
    const int lid = tid & 31;

    const int zb = blockIdx.z / H;
    const int zh = blockIdx.z - zb * H;
    const int rowBase = blockIdx.y * BM;
    const int colBase = blockIdx.x * BN;

    const __half* A_ = A + zb * aSB + zh * aSH + (long long)rowBase * lda;
    const __half* B_ = B + zb * bSB + zh * bSH + (long long)colBase * ldb;
    const long long cOff = zb * cSB + zh * cSH;

    const int warpM = (wid >> 2) * 64;
    const int warpN = (wid & 3) * 32;

    float acc[4][4][4];
#pragma unroll
    for (int i = 0; i < 4; i++)
#pragma unroll
        for (int j = 0; j < 4; j++)
#pragma unroll
            for (int v = 0; v < 4; v++) acc[i][j][v] = 0.0f;

    const int nK = K >> 6;

    auto load_stage = [&](int t, int buf) {
        const int k0 = t << 6;
        const uint32_t sS = sbase + buf * STAGE2_B;
        const __half* src[2] = {A_, B_};
        const int lds[2] = {lda, ldb};
#pragma unroll
        for (int tl = 0; tl < 2; tl++) {
            const __half* Q = src[tl];
            const int ld = lds[tl];
            const uint32_t tb = sS + tl * TILE_B;
#pragma unroll
            for (int j = 0; j < 4; j++) {
                int idx = tid + j * 256;
                int row = idx >> 3;
                int c = idx & 7;
                int sw = c ^ (row & 7);
                cp16(tb + row * 128 + sw * 16,
                     Q + (long long)row * ld + k0 + c * 8);
            }
        }
    };

#pragma unroll
    for (int s = 0; s < STAGES; s++) {
        if (s < nK) load_stage(s, s);
        CP_COMMIT();
    }

    for (int t = 0; t < nK; t++) {
        const int buf = t % STAGES;
        CP_WAIT2();
        __syncthreads();

        const uint32_t sS = sbase + buf * STAGE2_B;
        const uint32_t sA = sS;
        const uint32_t sB = sS + TILE_B;

#pragma unroll
        for (int ks = 0; ks < 4; ks++) {
            uint32_t a[4][4], b[2][4];
#pragma unroll
            for (int i = 0; i < 4; i++)
                ldsm4(a[i], frag_addr(sA, warpM + i * 16, ks, lid));
#pragma unroll
            for (int j = 0; j < 2; j++)
                ldsm4(b[j], frag_addr(sB, warpN + j * 16, ks, lid));

#pragma unroll
            for (int i = 0; i < 4; i++) {
#pragma unroll
                for (int j = 0; j < 4; j++) {
                    mma_f16(acc[i][j], a[i],
                            b[j >> 1][j & 1], b[j >> 1][(j & 1) + 2]);
                }
            }
        }
        __syncthreads();

        const int nt = t + STAGES;
        if (nt < nK) load_stage(nt, buf);
        CP_COMMIT();
    }

    const int g = lid >> 2;
    const int tq = lid & 3;
    const long long sumBase = (long long)blockIdx.z * SEQ;

#pragma unroll
    for (int i = 0; i < 4; i++) {
        const int lr0 = rowBase + warpM + i * 16 + g;
        const int lr1 = lr0 + 8;
        const long long r0 = lr0, r1 = lr1;

        float inv0 = 1.0f, inv1 = 1.0f;
        if (fuse == 2) {
            inv0 = __frcp_rn(rowsum[sumBase + lr0]);
            inv1 = __frcp_rn(rowsum[sumBase + lr1]);
        }
        float se0 = 0.0f, se1 = 0.0f;

#pragma unroll
        for (int j = 0; j < 4; j++) {
            const int col = colBase + warpN + j * 8 + tq * 2;
            float x0 = acc[i][j][0] * alpha, x1 = acc[i][j][1] * alpha;
            float x2 = acc[i][j][2] * alpha, x3 = acc[i][j][3] * alpha;
            if (fuse == 1) {
                x0 = __expf(x0); x1 = __expf(x1);
                x2 = __expf(x2); x3 = __expf(x3);
                se0 += x0 + x1;
                se1 += x2 + x3;
            } else if (fuse == 2) {
                x0 *= inv0; x1 *= inv0;
                x2 *= inv1; x3 *= inv1;
            }
            *reinterpret_cast<__half2*>(Hf + cOff + r0 * ldc + col) =
                __floats2half2_rn(x0, x1);
            *reinterpret_cast<__half2*>(Hf + cOff + r1 * ldc + col) =
                __floats2half2_rn(x2, x3);
        }

        if (fuse == 1) {
            se0 += __shfl_xor_sync(0xffffffffu, se0, 1);
            se0 += __shfl_xor_sync(0xffffffffu, se0, 2);
            se1 += __shfl_xor_sync(0xffffffffu, se1, 1);
            se1 += __shfl_xor_sync(0xffffffffu, se1, 2);
            if (tq == 0) {
                atomicAdd(&rowsum[sumBase + lr0], se0);
                atomicAdd(&rowsum[sumBase + lr1], se1);
            }
        }
    }
}

// ---------------------------------------------------------------------------
// fp32 -> fp16 hi/lo split (Wo)
// ---------------------------------------------------------------------------
__global__ void __launch_bounds__(256)
split2_f16(const float* __restrict__ x, __half* __restrict__ h,
           __half* __restrict__ l, long long n4)
{
    long long i = (long long)blockIdx.x * blockDim.x + threadIdx.x;
    if (i >= n4) return;
    float4 v = reinterpret_cast<const float4*>(x)[i];
    __half h0 = __float2half(v.x), h1 = __float2half(v.y);
    __half h2 = __float2half(v.z), h3 = __float2half(v.w);
    __half2 a, b;
    a.x = h0; a.y = h1; b.x = h2; b.y = h3;
    reinterpret_cast<__half2*>(h)[2 * i] = a;
    reinterpret_cast<__half2*>(h)[2 * i + 1] = b;
    a.x = __float2half(v.x - __half2float(h0));
    a.y = __float2half(v.y - __half2float(h1));
    b.x = __float2half(v.z - __half2float(h2));
    b.y = __float2half(v.w - __half2float(h3));
    reinterpret_cast<__half2*>(l)[2 * i] = a;
    reinterpret_cast<__half2*>(l)[2 * i + 1] = b;
}

// fp32 -> fp16 single (X, Wq, Wk, Wv)
__global__ void __launch_bounds__(256)
split1_f16(const float* __restrict__ x, __half* __restrict__ h, long long n4)
{
    long long i = (long long)blockIdx.x * blockDim.x + threadIdx.x;
    if (i >= n4) return;
    float4 v = reinterpret_cast<const float4*>(x)[i];
    __half2 a, b;
    a.x = __float2half(v.x); a.y = __float2half(v.y);
    b.x = __float2half(v.z); b.y = __float2half(v.w);
    reinterpret_cast<__half2*>(h)[2 * i] = a;
    reinterpret_cast<__half2*>(h)[2 * i + 1] = b;
}

static void* sym_addr(const void* symbol)
{
    void* p = nullptr;
    cudaGetSymbolAddress(&p, symbol);
    return p;
}

extern "C" void kernel_launch(void* const* d_in, const int* in_sizes, int n_in,
                              void* d_out, int out_size)
{
    const float* X  = (const float*)d_in[0];
    const float* Wq = (const float*)d_in[1];
    const float* Wk = (const float*)d_in[2];
    const float* Wv = (const float*)d_in[3];
    const float* Wo = (const float*)d_in[4];
    float* out = (float*)d_out;

    __half* Xf  = (__half*)sym_addr(g_Xf);
    __half* Wqk = (__half*)sym_addr(g_Wqk);
    __half* Wvf = (__half*)sym_addr(g_Wv);
    __half* Woh = (__half*)sym_addr(g_Woh);
    __half* Wol = (__half*)sym_addr(g_Wol);
    __half* QK  = (__half*)sym_addr(g_QK);
    __half* Vt  = (__half*)sym_addr(g_Vt);
    __half* S   = (__half*)sym_addr(g_S);
    __half* M   = (__half*)sym_addr(g_M);
    float*  rs  = (float*)sym_addr(g_rowsum);

    cudaFuncSetAttribute(gemm_2ph, cudaFuncAttributeMaxDynamicSharedMemorySize,
                         G2_SMEM);
    cudaFuncSetAttribute(gemm_f16, cudaFuncAttributeMaxDynamicSharedMemorySize,
                         G1_SMEM);

    cudaMemsetAsync(rs, 0, (size_t)BATCH * NHEAD * SEQ * sizeof(float));

    {
        long long n4;
        n4 = (long long)MS * DMODEL / 4;
        split1_f16<<<(unsigned)((n4 + 255) / 256), 256>>>(X, Xf, n4);
        n4 = (long long)DMODEL * DMODEL / 4;
        split1_f16<<<(unsigned)((n4 + 255) / 256), 256>>>(Wq, Wqk, n4);   // rows 0-1023
        split2_f16<<<(unsigned)((n4 + 255) / 256), 256>>>(Wo, Woh, Wol, n4);
        n4 = (long long)DK * DMODEL / 4;
        split1_f16<<<(unsigned)((n4 + 255) / 256), 256>>>(
            Wk, Wqk + (size_t)DMODEL * DMODEL, n4);                       // rows 1024-1279
        split1_f16<<<(unsigned)((n4 + 255) / 256), 256>>>(Wv, Wvf, n4);
    }

    // QK-proj (merged): QKbuf = Xf @ Wqk^T -> fp16 [8192 x 1280]
    gemm_f16<<<dim3(DQK / BN, MS / BM, 1), 256, G1_SMEM>>>(
        Xf, Wqk, QK, rs, 0,
        DMODEL, DMODEL, DMODEL, DQK, 1.0f,
        0, 0, 0, 0, 0, 0, 1);

    // VcT[b] = Wv @ Xf[b]^T -> fp16 [256 x 4096] per batch
    gemm_f16<<<dim3(SEQ / BN, DK / BM, BATCH), 256, G1_SMEM>>>(
        Wvf, Xf, Vt, rs, 0,
        DMODEL, DMODEL, DMODEL, SEQ, 1.0f,
        0, 0, (long long)SEQ * DMODEL, 0,
        (long long)DK * SEQ, 0, 1);

    // S[b,h] = exp(SCALE * Q[b,h] @ K[b]^T) -> fp16, rowsum accumulated.
    // Q = QKbuf cols 0-1023 (head offset 256), K = QKbuf cols 1024-1279.
    gemm_f16<<<dim3(SEQ / BN, SEQ / BM, BATCH * NHEAD), 256, G1_SMEM>>>(
        QK, QK + DMODEL, S, rs, 1,
        DK, DQK, DQK, SEQ, SCALE_F,
        (long long)SEQ * DQK, DK,
        (long long)SEQ * DQK, 0,
        (long long)NHEAD * SEQ * SEQ, (long long)SEQ * SEQ, NHEAD);

    // M = (S @ VcT^T) / rowsum -> fp16 merged [8192 x 1024]
    gemm_f16<<<dim3(DK / BN, SEQ / BM, BATCH * NHEAD), 256, G1_SMEM>>>(
        S, Vt, M, rs, 2,
        SEQ, SEQ, SEQ, DMODEL, 1.0f,
        (long long)NHEAD * SEQ * SEQ, (long long)SEQ * SEQ,
        (long long)DK * SEQ, 0,
        (long long)SEQ * DMODEL, DK, NHEAD);

    // out = M @ (Woh + Wol)^T -> fp32 (2-phase)
    gemm_2ph<<<dim3(DMODEL / BN, MS / BM, 1), 256, G2_SMEM>>>(
        M, Woh, Wol, out,
        DMODEL, DMODEL, DMODEL, DMODEL);
}